// round 8
// baseline (speedup 1.0000x reference)
#include <cuda_runtime.h>
#include <cuda_bf16.h>
#include <cstdint>
#include <math.h>

// Problem constants
#define BB 4
#define TT 2048
#define DD 1024
#define HH 16
#define DH 64
#define MTOT (BB*TT)        // 8192
#define N_QKV (3*DD)        // 3072

// Scratch (device globals: allocation-guard safe)
__device__ __nv_bfloat16 g_wqkv_h[(size_t)N_QKV * DD];  // W_qkv^T hi  [3072,1024]
__device__ __nv_bfloat16 g_wqkv_l[(size_t)N_QKV * DD];
__device__ __nv_bfloat16 g_wout_h[(size_t)DD * DD];     // W_out^T hi  [1024,1024]
__device__ __nv_bfloat16 g_wout_l[(size_t)DD * DD];
__device__ __nv_bfloat16 g_act_h[(size_t)MTOT * DD];    // activation hi [M,K]
__device__ __nv_bfloat16 g_act_l[(size_t)MTOT * DD];
// Q/K/V head-major [B*H][T][DH], hi/lo split (Q pre-scaled by 0.125)
#define QKV_ELEMS ((size_t)BB * HH * TT * DH)
__device__ __nv_bfloat16 g_q_h[QKV_ELEMS];
__device__ __nv_bfloat16 g_q_l[QKV_ELEMS];
__device__ __nv_bfloat16 g_k_h[QKV_ELEMS];
__device__ __nv_bfloat16 g_k_l[QKV_ELEMS];
__device__ __nv_bfloat16 g_v_h[QKV_ELEMS];
__device__ __nv_bfloat16 g_v_l[QKV_ELEMS];

// ---------------------------------------------------------------------------
// sm_80-portable PTX helpers
// ---------------------------------------------------------------------------
__device__ __forceinline__ uint32_t smem_u32(const void* p) {
    uint32_t a;
    asm("{ .reg .u64 t; cvta.to.shared.u64 t, %1; cvt.u32.u64 %0, t; }"
        : "=r"(a) : "l"(p));
    return a;
}
__device__ __forceinline__ void cpa16(uint32_t dst, const void* src) {
    asm volatile("cp.async.cg.shared.global [%0], [%1], 16;"
                 :: "r"(dst), "l"(src));
}
__device__ __forceinline__ void cpa4(uint32_t dst, const void* src) {
    asm volatile("cp.async.ca.shared.global [%0], [%1], 4;"
                 :: "r"(dst), "l"(src));
}
#define CP_COMMIT() asm volatile("cp.async.commit_group;" ::: "memory")
#define CP_WAIT(n)  asm volatile("cp.async.wait_group %0;" :: "n"(n) : "memory")

__device__ __forceinline__ void ldsm4(uint32_t* r, uint32_t addr) {
    asm volatile("ldmatrix.sync.aligned.m8n8.x4.shared.b16 {%0,%1,%2,%3}, [%4];"
                 : "=r"(r[0]), "=r"(r[1]), "=r"(r[2]), "=r"(r[3]) : "r"(addr));
}
__device__ __forceinline__ void ldsm4t(uint32_t* r, uint32_t addr) {
    asm volatile("ldmatrix.sync.aligned.m8n8.x4.trans.shared.b16 {%0,%1,%2,%3}, [%4];"
                 : "=r"(r[0]), "=r"(r[1]), "=r"(r[2]), "=r"(r[3]) : "r"(addr));
}
__device__ __forceinline__ void mma_bf16(float* d, const uint32_t* a,
                                         const uint32_t* b) {
    asm volatile("mma.sync.aligned.m16n8k16.row.col.f32.bf16.bf16.f32 "
                 "{%0,%1,%2,%3}, {%4,%5,%6,%7}, {%8,%9}, {%0,%1,%2,%3};"
                 : "+f"(d[0]), "+f"(d[1]), "+f"(d[2]), "+f"(d[3])
                 : "r"(a[0]), "r"(a[1]), "r"(a[2]), "r"(a[3]),
                   "r"(b[0]), "r"(b[1]));
}
// split pair of fp32 -> bf16x2 hi + bf16x2 lo
__device__ __forceinline__ void split2(float x, float y, uint32_t& hi, uint32_t& lo) {
    __nv_bfloat162 h, l;
    h.x = __float2bfloat16(x);
    h.y = __float2bfloat16(y);
    l.x = __float2bfloat16(x - __bfloat162float(h.x));
    l.y = __float2bfloat16(y - __bfloat162float(h.y));
    hi = *(uint32_t*)&h;
    lo = *(uint32_t*)&l;
}

// ---------------------------------------------------------------------------
// Fused conversion kernel: one launch does all three pre-split jobs.
//   blocks [0, 3072):        W_qkv transpose-split  (96 x 32 tile grid)
//   blocks [3072, 4096):     W_out transpose-split  (32 x 32 tile grid)
//   blocks [4096, 8192):     x activation split     (2 float4 per thread)
// ---------------------------------------------------------------------------
__device__ __forceinline__ void conv_w_body(
    const float* __restrict__ W, __nv_bfloat16* __restrict__ Wh,
    __nv_bfloat16* __restrict__ Wl, int K, int N, int bx, int by, int tid)
{
    __shared__ float t[32][33];
    const int n0 = bx * 32, k0 = by * 32;
    const int tx = tid & 31, ty = tid >> 5;
    #pragma unroll
    for (int i = 0; i < 32; i += 8)
        t[ty + i][tx] = W[(size_t)(k0 + ty + i) * N + n0 + tx];
    __syncthreads();
    #pragma unroll
    for (int i = 0; i < 32; i += 8) {
        int n = ty + i;
        float v = t[tx][n];
        __nv_bfloat16 h = __float2bfloat16(v);
        __nv_bfloat16 l = __float2bfloat16(v - __bfloat162float(h));
        size_t o = (size_t)(n0 + n) * K + k0 + tx;
        Wh[o] = h;
        Wl[o] = l;
    }
}

__global__ __launch_bounds__(256)
void conv_all_kernel(const float* __restrict__ W_qkv,
                     const float* __restrict__ W_out,
                     const float* __restrict__ x,
                     __nv_bfloat16* __restrict__ wqh, __nv_bfloat16* __restrict__ wql,
                     __nv_bfloat16* __restrict__ woh, __nv_bfloat16* __restrict__ wol,
                     __nv_bfloat16* __restrict__ xh,  __nv_bfloat16* __restrict__ xl)
{
    const int bid = blockIdx.x, tid = threadIdx.x;
    if (bid < 3072) {
        conv_w_body(W_qkv, wqh, wql, DD, N_QKV, bid % 96, bid / 96, tid);
    } else if (bid < 4096) {
        const int id = bid - 3072;
        conv_w_body(W_out, woh, wol, DD, DD, id % 32, id / 32, tid);
    } else {
        const int base = (bid - 4096) * 512 + tid;
        #pragma unroll
        for (int u = 0; u < 2; u++) {
            int idx = base + u * 256;     // < 2M always (4096 blocks * 512)
            float4 v = ((const float4*)x)[idx];
            uint32_t h0, h1, l0, l1;
            split2(v.x, v.y, h0, l0);
            split2(v.z, v.w, h1, l1);
            ((uint32_t*)xh)[idx * 2 + 0] = h0;
            ((uint32_t*)xh)[idx * 2 + 1] = h1;
            ((uint32_t*)xl)[idx * 2 + 0] = l0;
            ((uint32_t*)xl)[idx * 2 + 1] = l1;
        }
    }
}

// ---------------------------------------------------------------------------
// Tensor-core GEMM via mma.sync (bf16 3-term split, fp32 accumulate)
// BK=16, 3-stage cp.async pipeline; chunk c lives in stage c%3, prefetch
// distance 2, one __syncthreads per chunk.
// Smem rows padded to 48B (banks 3r mod 8 -> conflict-free ldmatrix).
// ---------------------------------------------------------------------------
#define GBK 16
#define GROWB 48                       // bytes per smem row
#define MATB (128 * GROWB)             // 6144
#define SA_H 0
#define SA_L (1 * MATB)
#define SB_H (2 * MATB)
#define SB_L (3 * MATB)
#define STAGEB (4 * MATB)              // 24576
#define GEMM_SMEM (3 * STAGEB)         // 73728

__device__ __forceinline__ void gemm_load_chunk(
    uint32_t stBase,
    const __nv_bfloat16* __restrict__ Ah, const __nv_bfloat16* __restrict__ Al,
    const __nv_bfloat16* __restrict__ Bh, const __nv_bfloat16* __restrict__ Bl,
    int bm0, int bn0, int k0, int K, int tid)
{
    const int row  = tid >> 1;            // 0..127
    const int half = tid & 1;             // which 16B half of the 32B row
    const size_t ga = (size_t)(bm0 + row) * K + k0 + half * 8;
    const size_t gb = (size_t)(bn0 + row) * K + k0 + half * 8;
    const uint32_t so = (uint32_t)(row * GROWB + half * 16);
    cpa16(stBase + SA_H + so, Ah + ga);
    cpa16(stBase + SA_L + so, Al + ga);
    cpa16(stBase + SB_H + so, Bh + gb);
    cpa16(stBase + SB_L + so, Bl + gb);
}

__global__ __launch_bounds__(256, 2)
void gemm_tc_kernel(const __nv_bfloat16* __restrict__ Ah,
                    const __nv_bfloat16* __restrict__ Al,
                    const __nv_bfloat16* __restrict__ Bh,
                    const __nv_bfloat16* __restrict__ Bl,
                    const float* __restrict__ bias, float* __restrict__ C,
                    int M, int N, int K,
                    __nv_bfloat16* qh, __nv_bfloat16* ql,
                    __nv_bfloat16* kh, __nv_bfloat16* kl,
                    __nv_bfloat16* vh, __nv_bfloat16* vl)
{
    extern __shared__ char smraw[];
    const uint32_t sb = smem_u32(smraw);
    const int tid = threadIdx.x, wid = tid >> 5, lane = tid & 31;
    const int bm0 = blockIdx.y * 128, bn0 = blockIdx.x * 128;
    const int wm = wid >> 2, wn = wid & 3;

    const int a_r = (lane & 7) + ((lane >> 3) & 1) * 8;
    const int a_k = (lane >> 4) * 8;
    const int b_r = (lane & 7) + (lane >> 4) * 8;
    const int b_k = ((lane >> 3) & 1) * 8;

    float acc[4][4][4];
    #pragma unroll
    for (int i = 0; i < 4; i++)
        #pragma unroll
        for (int j = 0; j < 4; j++)
            #pragma unroll
            for (int v = 0; v < 4; v++) acc[i][j][v] = 0.0f;

    const int NCH = K / GBK;   // 64

    // prologue: chunks 0 and 1 -> stages 0 and 1
    gemm_load_chunk(sb + 0 * STAGEB, Ah, Al, Bh, Bl, bm0, bn0, 0, K, tid);
    CP_COMMIT();
    gemm_load_chunk(sb + 1 * STAGEB, Ah, Al, Bh, Bl, bm0, bn0, GBK, K, tid);
    CP_COMMIT();

    int s_cur = 0;   // stage of chunk c == c % 3
    int s_pre = 2;   // stage of chunk c+2 == (c+2) % 3
    for (int c = 0; c < NCH; c++) {
        if (c + 1 < NCH) CP_WAIT(1); else CP_WAIT(0);   // chunk c arrived
        __syncthreads();   // all warps done computing chunk c-1 (stage s_pre)

        if (c + 2 < NCH) {
            gemm_load_chunk(sb + (uint32_t)s_pre * STAGEB,
                            Ah, Al, Bh, Bl, bm0, bn0, (c + 2) * GBK, K, tid);
            CP_COMMIT();
        }

        const uint32_t st = sb + (uint32_t)s_cur * STAGEB;

        uint32_t bh2[4][2], bl2[4][2];
        #pragma unroll
        for (int half = 0; half < 2; half++) {
            uint32_t baddr = (uint32_t)((wn * 32 + half * 16 + b_r) * GROWB
                                        + b_k * 2);
            uint32_t r[4];
            ldsm4(r, st + SB_H + baddr);
            bh2[half * 2 + 0][0] = r[0]; bh2[half * 2 + 0][1] = r[1];
            bh2[half * 2 + 1][0] = r[2]; bh2[half * 2 + 1][1] = r[3];
            ldsm4(r, st + SB_L + baddr);
            bl2[half * 2 + 0][0] = r[0]; bl2[half * 2 + 0][1] = r[1];
            bl2[half * 2 + 1][0] = r[2]; bl2[half * 2 + 1][1] = r[3];
        }
        #pragma unroll
        for (int mi = 0; mi < 4; mi++) {
            uint32_t aaddr = (uint32_t)((wm * 64 + mi * 16 + a_r) * GROWB
                                        + a_k * 2);
            uint32_t ah[4], al[4];
            ldsm4(ah, st + SA_H + aaddr);
            ldsm4(al, st + SA_L + aaddr);
            #pragma unroll
            for (int nf = 0; nf < 4; nf++) {
                mma_bf16(acc[mi][nf], ah, bh2[nf]);
                mma_bf16(acc[mi][nf], ah, bl2[nf]);
                mma_bf16(acc[mi][nf], al, bh2[nf]);
            }
        }

        // rotate: stage of chunk (c+1) is (s_cur+1)%3; of (c+3) is s_cur... 
        // i.e. the stage just consumed (s_cur) becomes the prefetch target
        // after the NEXT sync. Standard modular walk:
        int nxt = (s_cur == 2) ? 0 : s_cur + 1;
        s_pre = (s_pre == 2) ? 0 : s_pre + 1;
        s_cur = nxt;
    }

    // Epilogue
    #pragma unroll
    for (int mi = 0; mi < 4; mi++) {
        const int row = bm0 + wm * 64 + mi * 16 + (lane >> 2);
        #pragma unroll
        for (int nf = 0; nf < 4; nf++) {
            const int col = bn0 + wn * 32 + nf * 8 + (lane & 3) * 2;
            const float b0 = bias[col], b1 = bias[col + 1];
            float v0 = acc[mi][nf][0] + b0, v1 = acc[mi][nf][1] + b1;
            float v2 = acc[mi][nf][2] + b0, v3 = acc[mi][nf][3] + b1;
            if (qh == nullptr) {
                float2 p0, p1;
                p0.x = v0; p0.y = v1; p1.x = v2; p1.y = v3;
                *(float2*)&C[(size_t)row * N + col]       = p0;
                *(float2*)&C[(size_t)(row + 8) * N + col] = p1;
            } else {
                const int sec = col >> 10;
                const int hh  = (col >> 6) & 15;
                const int d   = col & 63;
                const int bb  = row >> 11;
                const int trow = row & 2047;
                const float sc = (sec == 0) ? 0.125f : 1.0f;
                __nv_bfloat16 *H, *L;
                if (sec == 0)      { H = qh; L = ql; }
                else if (sec == 1) { H = kh; L = kl; }
                else               { H = vh; L = vl; }
                size_t dst = (((size_t)(bb * 16 + hh)) * TT + trow) * 64 + d;
                uint32_t hi, lo;
                split2(v0 * sc, v1 * sc, hi, lo);
                *(uint32_t*)(H + dst) = hi;
                *(uint32_t*)(L + dst) = lo;
                split2(v2 * sc, v3 * sc, hi, lo);
                *(uint32_t*)(H + dst + 8 * 64) = hi;
                *(uint32_t*)(L + dst + 8 * 64) = lo;
            }
        }
    }
}

// ---------------------------------------------------------------------------
// Tensor-core flash attention — unchanged from round 6 (passing, 2 CTAs/SM)
// ---------------------------------------------------------------------------
#define AVROW 72                       // bf16 row stride (144 B)
#define KQH 0
#define KQL 18432
#define KKH 0
#define KKL 9216
#define KVH 18432
#define KVL 27648
#define ASTAGE 36864
#define AMSK (2 * ASTAGE)              // 73728
#define ATTN_SMEM (AMSK + 512)         // 74240

__device__ __forceinline__ void attn_kvload(
    uint32_t sb, int region, int bh, int n0,
    const __nv_bfloat16* __restrict__ Kh_g, const __nv_bfloat16* __restrict__ Kl_g,
    const __nv_bfloat16* __restrict__ Vh_g, const __nv_bfloat16* __restrict__ Vl_g,
    const int* __restrict__ mask, int b, int tid)
{
    const uint32_t st = sb + (uint32_t)region * ASTAGE;
    const size_t gb = ((size_t)bh * TT + n0) * 64;
    #pragma unroll
    for (int u = 0; u < 2; u++) {
        int idx = tid * 2 + u;
        int row = idx >> 3, ch = idx & 7;
        uint32_t so = (uint32_t)(row * 144 + ch * 16);
        size_t go = gb + row * 64 + ch * 8;
        cpa16(st + KKH + so, Kh_g + go);
        cpa16(st + KKL + so, Kl_g + go);
        cpa16(st + KVH + so, Vh_g + go);
        cpa16(st + KVL + so, Vl_g + go);
    }
    if (tid < 64)
        cpa4(sb + AMSK + (uint32_t)region * 256 + tid * 4,
             mask + (size_t)b * TT + n0 + tid);
}

__global__ __launch_bounds__(256, 2)
void attn_tc_kernel(const __nv_bfloat16* __restrict__ Qh_g,
                    const __nv_bfloat16* __restrict__ Ql_g,
                    const __nv_bfloat16* __restrict__ Kh_g,
                    const __nv_bfloat16* __restrict__ Kl_g,
                    const __nv_bfloat16* __restrict__ Vh_g,
                    const __nv_bfloat16* __restrict__ Vl_g,
                    const int* __restrict__ mask,
                    __nv_bfloat16* __restrict__ Oh_g,
                    __nv_bfloat16* __restrict__ Ol_g)
{
    extern __shared__ char smraw[];
    const uint32_t sb = smem_u32(smraw);
    const int tid = threadIdx.x, wid = tid >> 5, lane = tid & 31;
    const int bh = blockIdx.y;
    const int b = bh >> 4, h = bh & 15;
    const int t0 = blockIdx.x * 128;
    const int wm = wid;

    const int a_r = (lane & 7) + ((lane >> 3) & 1) * 8;
    const int a_k = (lane >> 4) * 8;
    const int b_r = (lane & 7) + (lane >> 4) * 8;
    const int b_k = ((lane >> 3) & 1) * 8;
    const int c0base = (lane & 3) * 2;

    const size_t qbase = ((size_t)bh * TT + t0) * 64;
    #pragma unroll
    for (int i = 0; i < 4; i++) {
        int f = tid + i * 256;
        int row = f >> 3, ch = f & 7;
        uint32_t so = (uint32_t)(row * 144 + ch * 16);
        size_t go = qbase + row * 64 + ch * 8;
        cpa16(sb + KQH + so, Qh_g + go);
        cpa16(sb + KQL + so, Ql_g + go);
    }
    attn_kvload(sb, 1, bh, 0, Kh_g, Kl_g, Vh_g, Vl_g, mask, b, tid);
    CP_COMMIT();
    CP_WAIT(0);
    __syncthreads();

    uint32_t qfh[4][4], qfl[4][4];
    #pragma unroll
    for (int kk = 0; kk < 4; kk++) {
        uint32_t addr = (uint32_t)(((wm * 16 + a_r) * AVROW + kk * 16 + a_k) * 2);
        ldsm4(qfh[kk], sb + KQH + addr);
        ldsm4(qfl[kk], sb + KQL + addr);
    }
    __syncthreads();

    float O[8][4];
    #pragma unroll
    for (int j = 0; j < 8; j++)
        #pragma unroll
        for (int v = 0; v < 4; v++) O[j][v] = 0.0f;
    float m0 = -3.0e38f, m1 = -3.0e38f, l0 = 0.0f, l1 = 0.0f;

    for (int t = 0; t < TT / 64; t++) {
        const int rt = (t + 1) & 1;
        if (t + 1 < TT / 64) {
            attn_kvload(sb, t & 1, bh, (t + 1) * 64,
                        Kh_g, Kl_g, Vh_g, Vl_g, mask, b, tid);
            CP_COMMIT();
        }
        const uint32_t st = sb + (uint32_t)rt * ASTAGE;
        const int* msk = (const int*)(smraw + AMSK + rt * 256);

        float acc[8][4];
        #pragma unroll
        for (int j = 0; j < 8; j++)
            #pragma unroll
            for (int v = 0; v < 4; v++) acc[j][v] = 0.0f;

        #pragma unroll
        for (int kk = 0; kk < 4; kk++) {
            #pragma unroll
            for (int nb = 0; nb < 4; nb++) {
                uint32_t addr = (uint32_t)(((nb * 16 + b_r) * AVROW
                                            + kk * 16 + b_k) * 2);
                uint32_t rh[4], rl[4];
                ldsm4(rh, st + KKH + addr);
                ldsm4(rl, st + KKL + addr);
                mma_bf16(acc[2 * nb],     qfh[kk], &rh[0]);
                mma_bf16(acc[2 * nb],     qfh[kk], &rl[0]);
                mma_bf16(acc[2 * nb],     qfl[kk], &rh[0]);
                mma_bf16(acc[2 * nb + 1], qfh[kk], &rh[2]);
                mma_bf16(acc[2 * nb + 1], qfh[kk], &rl[2]);
                mma_bf16(acc[2 * nb + 1], qfl[kk], &rh[2]);
            }
        }

        float rmax0 = -3.0e38f, rmax1 = -3.0e38f;
        #pragma unroll
        for (int j = 0; j < 8; j++) {
            int c = j * 8 + c0base;
            int mk0 = msk[c], mk1 = msk[c + 1];
            acc[j][0] = mk0 ? acc[j][0] : -1000.0f;
            acc[j][1] = mk1 ? acc[j][1] : -1000.0f;
            acc[j][2] = mk0 ? acc[j][2] : -1000.0f;
            acc[j][3] = mk1 ? acc[j][3] : -1000.0f;
            rmax0 = fmaxf(rmax0, fmaxf(acc[j][0], acc[j][1]));
            rmax1 = fmaxf(rmax1, fmaxf(acc[j][2], acc[j][3]));
        }
        rmax0 = fmaxf(rmax0, __shfl_xor_sync(0xffffffffu, rmax0, 1));
        rmax0 = fmaxf(rmax0, __shfl_xor_sync(0xffffffffu, rmax0, 2));
        rmax1 = fmaxf(rmax1, __shfl_xor_sync(0xffffffffu, rmax1, 1));
        rmax1 = fmaxf(rmax1, __shfl_xor_sync(0xffffffffu, rmax1, 2));

        float mn0 = fmaxf(m0, rmax0), mn1 = fmaxf(m1, rmax1);
        float al0 = __expf(m0 - mn0), al1 = __expf(m1 - mn1);
        m0 = mn0; m1 = mn1;

        float rs0 = 0.0f, rs1 = 0.0f;
        #pragma unroll
        for (int j = 0; j < 8; j++) {
            acc[j][0] = __expf(acc[j][0] - mn0); rs0 += acc[j][0];
            acc[j][1] = __expf(acc[j][1] - mn0); rs0 += acc[j][1];
            acc[j][2] = __expf(acc[j][2] - mn1); rs1 += acc[j][2];
            acc[j][3] = __expf(acc[j][3] - mn1); rs1 += acc[j][3];
        }
        rs0 += __shfl_xor_sync(0xffffffffu, rs0, 1);
        rs0 += __shfl_xor_sync(0xffffffffu, rs0, 2);
        rs1 += __shfl_xor_sync(0xffffffffu, rs1, 1);
        rs1 += __shfl_xor_sync(0xffffffffu, rs1, 2);
        l0 = l0 * al0 + rs0;
        l1 = l1 * al1 + rs1;
        #pragma unroll
        for (int j = 0; j < 8; j++) {
            O[j][0] *= al0; O[j][1] *= al0;
            O[j][2] *= al1; O[j][3] *= al1;
        }

        #pragma unroll
        for (int kk = 0; kk < 4; kk++) {
            uint32_t pah[4], pal[4];
            split2(acc[2 * kk][0],     acc[2 * kk][1],     pah[0], pal[0]);
            split2(acc[2 * kk][2],     acc[2 * kk][3],     pah[1], pal[1]);
            split2(acc[2 * kk + 1][0], acc[2 * kk + 1][1], pah[2], pal[2]);
            split2(acc[2 * kk + 1][2], acc[2 * kk + 1][3], pah[3], pal[3]);
            #pragma unroll
            for (int nb = 0; nb < 4; nb++) {
                uint32_t addr = (uint32_t)(((kk * 16 + ((lane >> 3) & 1) * 8
                                             + (lane & 7)) * AVROW
                                            + nb * 16 + (lane >> 4) * 8) * 2);
                uint32_t vh4[4], vl4[4];
                ldsm4t(vh4, st + KVH + addr);
                ldsm4t(vl4, st + KVL + addr);
                mma_bf16(O[2 * nb],     pah, &vh4[0]);
                mma_bf16(O[2 * nb],     pah, &vl4[0]);
                mma_bf16(O[2 * nb],     pal, &vh4[0]);
                mma_bf16(O[2 * nb + 1], pah, &vh4[2]);
                mma_bf16(O[2 * nb + 1], pah, &vl4[2]);
                mma_bf16(O[2 * nb + 1], pal, &vh4[2]);
            }
        }

        if (t + 1 < TT / 64) CP_WAIT(0);
        __syncthreads();
    }

    const float inv0 = 1.0f / l0, inv1 = 1.0f / l1;
    const int trow = t0 + wm * 16 + (lane >> 2);
    const size_t ob0 = ((size_t)(b * TT + trow)) * DD + h * 64;
    const size_t ob1 = ob0 + (size_t)8 * DD;
    #pragma unroll
    for (int jn = 0; jn < 8; jn++) {
        int c = jn * 8 + c0base;
        uint32_t hi, lo;
        split2(O[jn][0] * inv0, O[jn][1] * inv0, hi, lo);
        *(uint32_t*)(Oh_g + ob0 + c) = hi;
        *(uint32_t*)(Ol_g + ob0 + c) = lo;
        split2(O[jn][2] * inv1, O[jn][3] * inv1, hi, lo);
        *(uint32_t*)(Oh_g + ob1 + c) = hi;
        *(uint32_t*)(Ol_g + ob1 + c) = lo;
    }
}

// ---------------------------------------------------------------------------
extern "C" void kernel_launch(void* const* d_in, const int* in_sizes, int n_in,
                              void* d_out, int out_size)
{
    const float* x     = (const float*)d_in[0];
    const int*   mask  = (const int*)  d_in[1];
    const float* W_qkv = (const float*)d_in[2];
    const float* b_qkv = (const float*)d_in[3];
    const float* W_out = (const float*)d_in[4];
    const float* b_out = (const float*)d_in[5];
    float* out = (float*)d_out;

    __nv_bfloat16 *wqh, *wql, *woh, *wol, *xh, *xl;
    __nv_bfloat16 *qh, *ql, *kh, *kl, *vh, *vl;
    cudaGetSymbolAddress((void**)&wqh, g_wqkv_h);
    cudaGetSymbolAddress((void**)&wql, g_wqkv_l);
    cudaGetSymbolAddress((void**)&woh, g_wout_h);
    cudaGetSymbolAddress((void**)&wol, g_wout_l);
    cudaGetSymbolAddress((void**)&xh,  g_act_h);
    cudaGetSymbolAddress((void**)&xl,  g_act_l);
    cudaGetSymbolAddress((void**)&qh,  g_q_h);
    cudaGetSymbolAddress((void**)&ql,  g_q_l);
    cudaGetSymbolAddress((void**)&kh,  g_k_h);
    cudaGetSymbolAddress((void**)&kl,  g_k_l);
    cudaGetSymbolAddress((void**)&vh,  g_v_h);
    cudaGetSymbolAddress((void**)&vl,  g_v_l);

    cudaFuncSetAttribute(gemm_tc_kernel,
                         cudaFuncAttributeMaxDynamicSharedMemorySize, GEMM_SMEM);
    cudaFuncSetAttribute(attn_tc_kernel,
                         cudaFuncAttributeMaxDynamicSharedMemorySize, ATTN_SMEM);

    // 0) Fused pre-split (weights transposed [N,K] + input activations)
    conv_all_kernel<<<8192, 256>>>(W_qkv, W_out, x, wqh, wql, woh, wol, xh, xl);

    // 1) QKV projection; epilogue scatters split Q/K/V head-major (Q pre-scaled)
    gemm_tc_kernel<<<dim3(N_QKV / 128, MTOT / 128), 256, GEMM_SMEM>>>(
        xh, xl, wqh, wql, b_qkv, nullptr, MTOT, N_QKV, DD,
        qh, ql, kh, kl, vh, vl);

    // 2) Tensor-core flash attention; writes pre-split activations for GEMM2
    attn_tc_kernel<<<dim3(TT / 128, BB * HH), 256, ATTN_SMEM>>>(
        qh, ql, kh, kl, vh, vl, mask, xh, xl);

    // 3) Output projection
    gemm_tc_kernel<<<dim3(DD / 128, MTOT / 128), 256, GEMM_SMEM>>>(
        xh, xl, woh, wol, b_out, out, MTOT, DD, DD,
        nullptr, nullptr, nullptr, nullptr, nullptr, nullptr);
}

// round 9
// speedup vs baseline: 1.0095x; 1.0095x over previous
#include <cuda_runtime.h>
#include <cuda_bf16.h>
#include <cstdint>
#include <math.h>

// Problem constants
#define BB 4
#define TT 2048
#define DD 1024
#define HH 16
#define DH 64
#define MTOT (BB*TT)        // 8192
#define N_QKV (3*DD)        // 3072

// Scratch (device globals: allocation-guard safe)
__device__ __nv_bfloat16 g_wqkv_h[(size_t)N_QKV * DD];  // W_qkv^T hi  [3072,1024]
__device__ __nv_bfloat16 g_wqkv_l[(size_t)N_QKV * DD];
__device__ __nv_bfloat16 g_wout_h[(size_t)DD * DD];     // W_out^T hi  [1024,1024]
__device__ __nv_bfloat16 g_wout_l[(size_t)DD * DD];
__device__ __nv_bfloat16 g_act_h[(size_t)MTOT * DD];    // activation hi [M,K]
__device__ __nv_bfloat16 g_act_l[(size_t)MTOT * DD];
// Q/K/V head-major [B*H][T][DH], hi/lo split (Q pre-scaled by 0.125)
#define QKV_ELEMS ((size_t)BB * HH * TT * DH)
__device__ __nv_bfloat16 g_q_h[QKV_ELEMS];
__device__ __nv_bfloat16 g_q_l[QKV_ELEMS];
__device__ __nv_bfloat16 g_k_h[QKV_ELEMS];
__device__ __nv_bfloat16 g_k_l[QKV_ELEMS];
__device__ __nv_bfloat16 g_v_h[QKV_ELEMS];
__device__ __nv_bfloat16 g_v_l[QKV_ELEMS];

// ---------------------------------------------------------------------------
// sm_80-portable PTX helpers
// ---------------------------------------------------------------------------
__device__ __forceinline__ uint32_t smem_u32(const void* p) {
    uint32_t a;
    asm("{ .reg .u64 t; cvta.to.shared.u64 t, %1; cvt.u32.u64 %0, t; }"
        : "=r"(a) : "l"(p));
    return a;
}
__device__ __forceinline__ void cpa16(uint32_t dst, const void* src) {
    asm volatile("cp.async.cg.shared.global [%0], [%1], 16;"
                 :: "r"(dst), "l"(src));
}
__device__ __forceinline__ void cpa4(uint32_t dst, const void* src) {
    asm volatile("cp.async.ca.shared.global [%0], [%1], 4;"
                 :: "r"(dst), "l"(src));
}
#define CP_COMMIT() asm volatile("cp.async.commit_group;" ::: "memory")
#define CP_WAIT(n)  asm volatile("cp.async.wait_group %0;" :: "n"(n) : "memory")

__device__ __forceinline__ void ldsm4(uint32_t* r, uint32_t addr) {
    asm volatile("ldmatrix.sync.aligned.m8n8.x4.shared.b16 {%0,%1,%2,%3}, [%4];"
                 : "=r"(r[0]), "=r"(r[1]), "=r"(r[2]), "=r"(r[3]) : "r"(addr));
}
__device__ __forceinline__ void ldsm4t(uint32_t* r, uint32_t addr) {
    asm volatile("ldmatrix.sync.aligned.m8n8.x4.trans.shared.b16 {%0,%1,%2,%3}, [%4];"
                 : "=r"(r[0]), "=r"(r[1]), "=r"(r[2]), "=r"(r[3]) : "r"(addr));
}
__device__ __forceinline__ void mma_bf16(float* d, const uint32_t* a,
                                         const uint32_t* b) {
    asm volatile("mma.sync.aligned.m16n8k16.row.col.f32.bf16.bf16.f32 "
                 "{%0,%1,%2,%3}, {%4,%5,%6,%7}, {%8,%9}, {%0,%1,%2,%3};"
                 : "+f"(d[0]), "+f"(d[1]), "+f"(d[2]), "+f"(d[3])
                 : "r"(a[0]), "r"(a[1]), "r"(a[2]), "r"(a[3]),
                   "r"(b[0]), "r"(b[1]));
}
// split pair of fp32 -> bf16x2 hi + bf16x2 lo
__device__ __forceinline__ void split2(float x, float y, uint32_t& hi, uint32_t& lo) {
    __nv_bfloat162 h, l;
    h.x = __float2bfloat16(x);
    h.y = __float2bfloat16(y);
    l.x = __float2bfloat16(x - __bfloat162float(h.x));
    l.y = __float2bfloat16(y - __bfloat162float(h.y));
    hi = *(uint32_t*)&h;
    lo = *(uint32_t*)&l;
}

// ---------------------------------------------------------------------------
// Fused conversion kernel: one launch does all three pre-split jobs.
// ---------------------------------------------------------------------------
__device__ __forceinline__ void conv_w_body(
    const float* __restrict__ W, __nv_bfloat16* __restrict__ Wh,
    __nv_bfloat16* __restrict__ Wl, int K, int N, int bx, int by, int tid)
{
    __shared__ float t[32][33];
    const int n0 = bx * 32, k0 = by * 32;
    const int tx = tid & 31, ty = tid >> 5;
    #pragma unroll
    for (int i = 0; i < 32; i += 8)
        t[ty + i][tx] = W[(size_t)(k0 + ty + i) * N + n0 + tx];
    __syncthreads();
    #pragma unroll
    for (int i = 0; i < 32; i += 8) {
        int n = ty + i;
        float v = t[tx][n];
        __nv_bfloat16 h = __float2bfloat16(v);
        __nv_bfloat16 l = __float2bfloat16(v - __bfloat162float(h));
        size_t o = (size_t)(n0 + n) * K + k0 + tx;
        Wh[o] = h;
        Wl[o] = l;
    }
}

__global__ __launch_bounds__(256)
void conv_all_kernel(const float* __restrict__ W_qkv,
                     const float* __restrict__ W_out,
                     const float* __restrict__ x,
                     __nv_bfloat16* __restrict__ wqh, __nv_bfloat16* __restrict__ wql,
                     __nv_bfloat16* __restrict__ woh, __nv_bfloat16* __restrict__ wol,
                     __nv_bfloat16* __restrict__ xh,  __nv_bfloat16* __restrict__ xl)
{
    const int bid = blockIdx.x, tid = threadIdx.x;
    if (bid < 3072) {
        conv_w_body(W_qkv, wqh, wql, DD, N_QKV, bid % 96, bid / 96, tid);
    } else if (bid < 4096) {
        const int id = bid - 3072;
        conv_w_body(W_out, woh, wol, DD, DD, id % 32, id / 32, tid);
    } else {
        const int base = (bid - 4096) * 512 + tid;
        #pragma unroll
        for (int u = 0; u < 2; u++) {
            int idx = base + u * 256;
            float4 v = ((const float4*)x)[idx];
            uint32_t h0, h1, l0, l1;
            split2(v.x, v.y, h0, l0);
            split2(v.z, v.w, h1, l1);
            ((uint32_t*)xh)[idx * 2 + 0] = h0;
            ((uint32_t*)xh)[idx * 2 + 1] = h1;
            ((uint32_t*)xl)[idx * 2 + 0] = l0;
            ((uint32_t*)xl)[idx * 2 + 1] = l1;
        }
    }
}

// ---------------------------------------------------------------------------
// Tensor-core GEMM via mma.sync (bf16 3-term split, fp32 accumulate)
// R6-proven shape: BK=32, 2-stage cp.async, 80B smem rows, 2 CTAs/SM.
// MMA terms reordered: same-acc reuse distance = 4 MMAs (hides HMMA latency).
// ---------------------------------------------------------------------------
#define GBK 32
#define AROW 40
#define MAT_BYTES (128 * AROW * 2)
#define ST_A_H 0
#define ST_A_L (1 * MAT_BYTES)
#define ST_B_H (2 * MAT_BYTES)
#define ST_B_L (3 * MAT_BYTES)
#define STAGE_B (4 * MAT_BYTES)
#define GEMM_SMEM (2 * STAGE_B)

__device__ __forceinline__ void gemm_load_chunk(
    uint32_t stBase,
    const __nv_bfloat16* __restrict__ Ah, const __nv_bfloat16* __restrict__ Al,
    const __nv_bfloat16* __restrict__ Bh, const __nv_bfloat16* __restrict__ Bl,
    int bm0, int bn0, int k0, int K, int tid)
{
    const int row = tid >> 1;
    const int kc  = (tid & 1) * 16;
    const size_t ga = (size_t)(bm0 + row) * K + k0 + kc;
    const size_t gb = (size_t)(bn0 + row) * K + k0 + kc;
    const uint32_t so = (uint32_t)(row * 80 + kc * 2);
    cpa16(stBase + ST_A_H + so,      Ah + ga);
    cpa16(stBase + ST_A_H + so + 16, Ah + ga + 8);
    cpa16(stBase + ST_A_L + so,      Al + ga);
    cpa16(stBase + ST_A_L + so + 16, Al + ga + 8);
    cpa16(stBase + ST_B_H + so,      Bh + gb);
    cpa16(stBase + ST_B_H + so + 16, Bh + gb + 8);
    cpa16(stBase + ST_B_L + so,      Bl + gb);
    cpa16(stBase + ST_B_L + so + 16, Bl + gb + 8);
}

__global__ __launch_bounds__(256, 2)
void gemm_tc_kernel(const __nv_bfloat16* __restrict__ Ah,
                    const __nv_bfloat16* __restrict__ Al,
                    const __nv_bfloat16* __restrict__ Bh,
                    const __nv_bfloat16* __restrict__ Bl,
                    const float* __restrict__ bias, float* __restrict__ C,
                    int M, int N, int K,
                    __nv_bfloat16* qh, __nv_bfloat16* ql,
                    __nv_bfloat16* kh, __nv_bfloat16* kl,
                    __nv_bfloat16* vh, __nv_bfloat16* vl)
{
    extern __shared__ char smraw[];
    const uint32_t sb = smem_u32(smraw);
    const int tid = threadIdx.x, wid = tid >> 5, lane = tid & 31;
    const int bm0 = blockIdx.y * 128, bn0 = blockIdx.x * 128;
    const int wm = wid >> 2, wn = wid & 3;

    const int a_r = (lane & 7) + ((lane >> 3) & 1) * 8;
    const int a_k = (lane >> 4) * 8;
    const int b_r = (lane & 7) + (lane >> 4) * 8;
    const int b_k = ((lane >> 3) & 1) * 8;

    float acc[4][4][4];
    #pragma unroll
    for (int i = 0; i < 4; i++)
        #pragma unroll
        for (int j = 0; j < 4; j++)
            #pragma unroll
            for (int v = 0; v < 4; v++) acc[i][j][v] = 0.0f;

    const int NCH = K / GBK;

    gemm_load_chunk(sb, Ah, Al, Bh, Bl, bm0, bn0, 0, K, tid);
    CP_COMMIT();

    for (int c = 0; c < NCH; c++) {
        const uint32_t st = sb + (uint32_t)(c & 1) * STAGE_B;
        if (c + 1 < NCH) {
            gemm_load_chunk(sb + (uint32_t)((c + 1) & 1) * STAGE_B,
                            Ah, Al, Bh, Bl, bm0, bn0, (c + 1) * GBK, K, tid);
            CP_COMMIT();
            CP_WAIT(1);
        } else {
            CP_WAIT(0);
        }
        __syncthreads();

        #pragma unroll
        for (int ks = 0; ks < 2; ks++) {
            const int k0 = ks * 16;
            uint32_t bh2[4][2], bl2[4][2];
            #pragma unroll
            for (int half = 0; half < 2; half++) {
                uint32_t baddr = (uint32_t)((wn * 32 + half * 16 + b_r) * 80
                                            + (k0 + b_k) * 2);
                uint32_t r[4];
                ldsm4(r, st + ST_B_H + baddr);
                bh2[half * 2 + 0][0] = r[0]; bh2[half * 2 + 0][1] = r[1];
                bh2[half * 2 + 1][0] = r[2]; bh2[half * 2 + 1][1] = r[3];
                ldsm4(r, st + ST_B_L + baddr);
                bl2[half * 2 + 0][0] = r[0]; bl2[half * 2 + 0][1] = r[1];
                bl2[half * 2 + 1][0] = r[2]; bl2[half * 2 + 1][1] = r[3];
            }
            #pragma unroll
            for (int mi = 0; mi < 4; mi++) {
                uint32_t aaddr = (uint32_t)((wm * 64 + mi * 16 + a_r) * 80
                                            + (k0 + a_k) * 2);
                uint32_t ah[4], al[4];
                ldsm4(ah, st + ST_A_H + aaddr);
                ldsm4(al, st + ST_A_L + aaddr);
                // Reordered: per-acc term order preserved (hh, hl, lh), but
                // same-acc MMAs are now 4 apart instead of back-to-back.
                #pragma unroll
                for (int nf = 0; nf < 4; nf++) mma_bf16(acc[mi][nf], ah, bh2[nf]);
                #pragma unroll
                for (int nf = 0; nf < 4; nf++) mma_bf16(acc[mi][nf], ah, bl2[nf]);
                #pragma unroll
                for (int nf = 0; nf < 4; nf++) mma_bf16(acc[mi][nf], al, bh2[nf]);
            }
        }
        __syncthreads();
    }

    // Epilogue
    #pragma unroll
    for (int mi = 0; mi < 4; mi++) {
        const int row = bm0 + wm * 64 + mi * 16 + (lane >> 2);
        #pragma unroll
        for (int nf = 0; nf < 4; nf++) {
            const int col = bn0 + wn * 32 + nf * 8 + (lane & 3) * 2;
            const float b0 = bias[col], b1 = bias[col + 1];
            float v0 = acc[mi][nf][0] + b0, v1 = acc[mi][nf][1] + b1;
            float v2 = acc[mi][nf][2] + b0, v3 = acc[mi][nf][3] + b1;
            if (qh == nullptr) {
                float2 p0, p1;
                p0.x = v0; p0.y = v1; p1.x = v2; p1.y = v3;
                *(float2*)&C[(size_t)row * N + col]       = p0;
                *(float2*)&C[(size_t)(row + 8) * N + col] = p1;
            } else {
                const int sec = col >> 10;
                const int hh  = (col >> 6) & 15;
                const int d   = col & 63;
                const int bb  = row >> 11;
                const int trow = row & 2047;
                const float sc = (sec == 0) ? 0.125f : 1.0f;
                __nv_bfloat16 *H, *L;
                if (sec == 0)      { H = qh; L = ql; }
                else if (sec == 1) { H = kh; L = kl; }
                else               { H = vh; L = vl; }
                size_t dst = (((size_t)(bb * 16 + hh)) * TT + trow) * 64 + d;
                uint32_t hi, lo;
                split2(v0 * sc, v1 * sc, hi, lo);
                *(uint32_t*)(H + dst) = hi;
                *(uint32_t*)(L + dst) = lo;
                split2(v2 * sc, v3 * sc, hi, lo);
                *(uint32_t*)(H + dst + 8 * 64) = hi;
                *(uint32_t*)(L + dst + 8 * 64) = lo;
            }
        }
    }
}

// ---------------------------------------------------------------------------
// Tensor-core flash attention — R6 structure, MMA pairs interleaved.
// ---------------------------------------------------------------------------
#define AVROW 72                       // bf16 row stride (144 B)
#define KQH 0
#define KQL 18432
#define KKH 0
#define KKL 9216
#define KVH 18432
#define KVL 27648
#define ASTAGE 36864
#define AMSK (2 * ASTAGE)              // 73728
#define ATTN_SMEM (AMSK + 512)         // 74240

__device__ __forceinline__ void attn_kvload(
    uint32_t sb, int region, int bh, int n0,
    const __nv_bfloat16* __restrict__ Kh_g, const __nv_bfloat16* __restrict__ Kl_g,
    const __nv_bfloat16* __restrict__ Vh_g, const __nv_bfloat16* __restrict__ Vl_g,
    const int* __restrict__ mask, int b, int tid)
{
    const uint32_t st = sb + (uint32_t)region * ASTAGE;
    const size_t gb = ((size_t)bh * TT + n0) * 64;
    #pragma unroll
    for (int u = 0; u < 2; u++) {
        int idx = tid * 2 + u;
        int row = idx >> 3, ch = idx & 7;
        uint32_t so = (uint32_t)(row * 144 + ch * 16);
        size_t go = gb + row * 64 + ch * 8;
        cpa16(st + KKH + so, Kh_g + go);
        cpa16(st + KKL + so, Kl_g + go);
        cpa16(st + KVH + so, Vh_g + go);
        cpa16(st + KVL + so, Vl_g + go);
    }
    if (tid < 64)
        cpa4(sb + AMSK + (uint32_t)region * 256 + tid * 4,
             mask + (size_t)b * TT + n0 + tid);
}

__global__ __launch_bounds__(256, 2)
void attn_tc_kernel(const __nv_bfloat16* __restrict__ Qh_g,
                    const __nv_bfloat16* __restrict__ Ql_g,
                    const __nv_bfloat16* __restrict__ Kh_g,
                    const __nv_bfloat16* __restrict__ Kl_g,
                    const __nv_bfloat16* __restrict__ Vh_g,
                    const __nv_bfloat16* __restrict__ Vl_g,
                    const int* __restrict__ mask,
                    __nv_bfloat16* __restrict__ Oh_g,
                    __nv_bfloat16* __restrict__ Ol_g)
{
    extern __shared__ char smraw[];
    const uint32_t sb = smem_u32(smraw);
    const int tid = threadIdx.x, wid = tid >> 5, lane = tid & 31;
    const int bh = blockIdx.y;
    const int b = bh >> 4, h = bh & 15;
    const int t0 = blockIdx.x * 128;
    const int wm = wid;

    const int a_r = (lane & 7) + ((lane >> 3) & 1) * 8;
    const int a_k = (lane >> 4) * 8;
    const int b_r = (lane & 7) + (lane >> 4) * 8;
    const int b_k = ((lane >> 3) & 1) * 8;
    const int c0base = (lane & 3) * 2;

    const size_t qbase = ((size_t)bh * TT + t0) * 64;
    #pragma unroll
    for (int i = 0; i < 4; i++) {
        int f = tid + i * 256;
        int row = f >> 3, ch = f & 7;
        uint32_t so = (uint32_t)(row * 144 + ch * 16);
        size_t go = qbase + row * 64 + ch * 8;
        cpa16(sb + KQH + so, Qh_g + go);
        cpa16(sb + KQL + so, Ql_g + go);
    }
    attn_kvload(sb, 1, bh, 0, Kh_g, Kl_g, Vh_g, Vl_g, mask, b, tid);
    CP_COMMIT();
    CP_WAIT(0);
    __syncthreads();

    uint32_t qfh[4][4], qfl[4][4];
    #pragma unroll
    for (int kk = 0; kk < 4; kk++) {
        uint32_t addr = (uint32_t)(((wm * 16 + a_r) * AVROW + kk * 16 + a_k) * 2);
        ldsm4(qfh[kk], sb + KQH + addr);
        ldsm4(qfl[kk], sb + KQL + addr);
    }
    __syncthreads();

    float O[8][4];
    #pragma unroll
    for (int j = 0; j < 8; j++)
        #pragma unroll
        for (int v = 0; v < 4; v++) O[j][v] = 0.0f;
    float m0 = -3.0e38f, m1 = -3.0e38f, l0 = 0.0f, l1 = 0.0f;

    for (int t = 0; t < TT / 64; t++) {
        const int rt = (t + 1) & 1;
        if (t + 1 < TT / 64) {
            attn_kvload(sb, t & 1, bh, (t + 1) * 64,
                        Kh_g, Kl_g, Vh_g, Vl_g, mask, b, tid);
            CP_COMMIT();
        }
        const uint32_t st = sb + (uint32_t)rt * ASTAGE;
        const int* msk = (const int*)(smraw + AMSK + rt * 256);

        float acc[8][4];
        #pragma unroll
        for (int j = 0; j < 8; j++)
            #pragma unroll
            for (int v = 0; v < 4; v++) acc[j][v] = 0.0f;

        #pragma unroll
        for (int kk = 0; kk < 4; kk++) {
            #pragma unroll
            for (int nb = 0; nb < 4; nb++) {
                uint32_t addr = (uint32_t)(((nb * 16 + b_r) * AVROW
                                            + kk * 16 + b_k) * 2);
                uint32_t rh[4], rl[4];
                ldsm4(rh, st + KKH + addr);
                ldsm4(rl, st + KKL + addr);
                // interleaved: per-acc order hh, hl, lh preserved
                mma_bf16(acc[2 * nb],     qfh[kk], &rh[0]);
                mma_bf16(acc[2 * nb + 1], qfh[kk], &rh[2]);
                mma_bf16(acc[2 * nb],     qfh[kk], &rl[0]);
                mma_bf16(acc[2 * nb + 1], qfh[kk], &rl[2]);
                mma_bf16(acc[2 * nb],     qfl[kk], &rh[0]);
                mma_bf16(acc[2 * nb + 1], qfl[kk], &rh[2]);
            }
        }

        float rmax0 = -3.0e38f, rmax1 = -3.0e38f;
        #pragma unroll
        for (int j = 0; j < 8; j++) {
            int c = j * 8 + c0base;
            int mk0 = msk[c], mk1 = msk[c + 1];
            acc[j][0] = mk0 ? acc[j][0] : -1000.0f;
            acc[j][1] = mk1 ? acc[j][1] : -1000.0f;
            acc[j][2] = mk0 ? acc[j][2] : -1000.0f;
            acc[j][3] = mk1 ? acc[j][3] : -1000.0f;
            rmax0 = fmaxf(rmax0, fmaxf(acc[j][0], acc[j][1]));
            rmax1 = fmaxf(rmax1, fmaxf(acc[j][2], acc[j][3]));
        }
        rmax0 = fmaxf(rmax0, __shfl_xor_sync(0xffffffffu, rmax0, 1));
        rmax0 = fmaxf(rmax0, __shfl_xor_sync(0xffffffffu, rmax0, 2));
        rmax1 = fmaxf(rmax1, __shfl_xor_sync(0xffffffffu, rmax1, 1));
        rmax1 = fmaxf(rmax1, __shfl_xor_sync(0xffffffffu, rmax1, 2));

        float mn0 = fmaxf(m0, rmax0), mn1 = fmaxf(m1, rmax1);
        float al0 = __expf(m0 - mn0), al1 = __expf(m1 - mn1);
        m0 = mn0; m1 = mn1;

        float rs0 = 0.0f, rs1 = 0.0f;
        #pragma unroll
        for (int j = 0; j < 8; j++) {
            acc[j][0] = __expf(acc[j][0] - mn0); rs0 += acc[j][0];
            acc[j][1] = __expf(acc[j][1] - mn0); rs0 += acc[j][1];
            acc[j][2] = __expf(acc[j][2] - mn1); rs1 += acc[j][2];
            acc[j][3] = __expf(acc[j][3] - mn1); rs1 += acc[j][3];
        }
        rs0 += __shfl_xor_sync(0xffffffffu, rs0, 1);
        rs0 += __shfl_xor_sync(0xffffffffu, rs0, 2);
        rs1 += __shfl_xor_sync(0xffffffffu, rs1, 1);
        rs1 += __shfl_xor_sync(0xffffffffu, rs1, 2);
        l0 = l0 * al0 + rs0;
        l1 = l1 * al1 + rs1;
        #pragma unroll
        for (int j = 0; j < 8; j++) {
            O[j][0] *= al0; O[j][1] *= al0;
            O[j][2] *= al1; O[j][3] *= al1;
        }

        #pragma unroll
        for (int kk = 0; kk < 4; kk++) {
            uint32_t pah[4], pal[4];
            split2(acc[2 * kk][0],     acc[2 * kk][1],     pah[0], pal[0]);
            split2(acc[2 * kk][2],     acc[2 * kk][3],     pah[1], pal[1]);
            split2(acc[2 * kk + 1][0], acc[2 * kk + 1][1], pah[2], pal[2]);
            split2(acc[2 * kk + 1][2], acc[2 * kk + 1][3], pah[3], pal[3]);
            #pragma unroll
            for (int nb = 0; nb < 4; nb++) {
                uint32_t addr = (uint32_t)(((kk * 16 + ((lane >> 3) & 1) * 8
                                             + (lane & 7)) * AVROW
                                            + nb * 16 + (lane >> 4) * 8) * 2);
                uint32_t vh4[4], vl4[4];
                ldsm4t(vh4, st + KVH + addr);
                ldsm4t(vl4, st + KVL + addr);
                // interleaved: per-acc order hh, hl, lh preserved
                mma_bf16(O[2 * nb],     pah, &vh4[0]);
                mma_bf16(O[2 * nb + 1], pah, &vh4[2]);
                mma_bf16(O[2 * nb],     pah, &vl4[0]);
                mma_bf16(O[2 * nb + 1], pah, &vl4[2]);
                mma_bf16(O[2 * nb],     pal, &vh4[0]);
                mma_bf16(O[2 * nb + 1], pal, &vh4[2]);
            }
        }

        if (t + 1 < TT / 64) CP_WAIT(0);
        __syncthreads();
    }

    const float inv0 = 1.0f / l0, inv1 = 1.0f / l1;
    const int trow = t0 + wm * 16 + (lane >> 2);
    const size_t ob0 = ((size_t)(b * TT + trow)) * DD + h * 64;
    const size_t ob1 = ob0 + (size_t)8 * DD;
    #pragma unroll
    for (int jn = 0; jn < 8; jn++) {
        int c = jn * 8 + c0base;
        uint32_t hi, lo;
        split2(O[jn][0] * inv0, O[jn][1] * inv0, hi, lo);
        *(uint32_t*)(Oh_g + ob0 + c) = hi;
        *(uint32_t*)(Ol_g + ob0 + c) = lo;
        split2(O[jn][2] * inv1, O[jn][3] * inv1, hi, lo);
        *(uint32_t*)(Oh_g + ob1 + c) = hi;
        *(uint32_t*)(Ol_g + ob1 + c) = lo;
    }
}

// ---------------------------------------------------------------------------
extern "C" void kernel_launch(void* const* d_in, const int* in_sizes, int n_in,
                              void* d_out, int out_size)
{
    const float* x     = (const float*)d_in[0];
    const int*   mask  = (const int*)  d_in[1];
    const float* W_qkv = (const float*)d_in[2];
    const float* b_qkv = (const float*)d_in[3];
    const float* W_out = (const float*)d_in[4];
    const float* b_out = (const float*)d_in[5];
    float* out = (float*)d_out;

    __nv_bfloat16 *wqh, *wql, *woh, *wol, *xh, *xl;
    __nv_bfloat16 *qh, *ql, *kh, *kl, *vh, *vl;
    cudaGetSymbolAddress((void**)&wqh, g_wqkv_h);
    cudaGetSymbolAddress((void**)&wql, g_wqkv_l);
    cudaGetSymbolAddress((void**)&woh, g_wout_h);
    cudaGetSymbolAddress((void**)&wol, g_wout_l);
    cudaGetSymbolAddress((void**)&xh,  g_act_h);
    cudaGetSymbolAddress((void**)&xl,  g_act_l);
    cudaGetSymbolAddress((void**)&qh,  g_q_h);
    cudaGetSymbolAddress((void**)&ql,  g_q_l);
    cudaGetSymbolAddress((void**)&kh,  g_k_h);
    cudaGetSymbolAddress((void**)&kl,  g_k_l);
    cudaGetSymbolAddress((void**)&vh,  g_v_h);
    cudaGetSymbolAddress((void**)&vl,  g_v_l);

    cudaFuncSetAttribute(gemm_tc_kernel,
                         cudaFuncAttributeMaxDynamicSharedMemorySize, GEMM_SMEM);
    cudaFuncSetAttribute(attn_tc_kernel,
                         cudaFuncAttributeMaxDynamicSharedMemorySize, ATTN_SMEM);

    // 0) Fused pre-split (weights transposed [N,K] + input activations)
    conv_all_kernel<<<8192, 256>>>(W_qkv, W_out, x, wqh, wql, woh, wol, xh, xl);

    // 1) QKV projection; epilogue scatters split Q/K/V head-major (Q pre-scaled)
    gemm_tc_kernel<<<dim3(N_QKV / 128, MTOT / 128), 256, GEMM_SMEM>>>(
        xh, xl, wqh, wql, b_qkv, nullptr, MTOT, N_QKV, DD,
        qh, ql, kh, kl, vh, vl);

    // 2) Tensor-core flash attention; writes pre-split activations for GEMM2
    attn_tc_kernel<<<dim3(TT / 128, BB * HH), 256, ATTN_SMEM>>>(
        qh, ql, kh, kl, vh, vl, mask, xh, xl);

    // 3) Output projection
    gemm_tc_kernel<<<dim3(DD / 128, MTOT / 128), 256, GEMM_SMEM>>>(
        xh, xl, woh, wol, b_out, out, MTOT, DD, DD,
        nullptr, nullptr, nullptr, nullptr, nullptr, nullptr);
}

// round 10
// speedup vs baseline: 1.2829x; 1.2709x over previous
#include <cuda_runtime.h>
#include <cuda_bf16.h>
#include <cstdint>
#include <math.h>

// Problem constants
#define BB 4
#define TT 2048
#define DD 1024
#define HH 16
#define DH 64
#define MTOT (BB*TT)        // 8192
#define N_QKV (3*DD)        // 3072

// Scratch (device globals: allocation-guard safe)
__device__ __nv_bfloat16 g_wqkv_h[(size_t)N_QKV * DD];  // W_qkv^T hi  [3072,1024]
__device__ __nv_bfloat16 g_wqkv_l[(size_t)N_QKV * DD];
__device__ __nv_bfloat16 g_wout_h[(size_t)DD * DD];     // W_out^T hi  [1024,1024]
__device__ __nv_bfloat16 g_wout_l[(size_t)DD * DD];
__device__ __nv_bfloat16 g_act_h[(size_t)MTOT * DD];    // activation hi [M,K]
__device__ __nv_bfloat16 g_act_l[(size_t)MTOT * DD];
// Q/K/V head-major [B*H][T][DH], hi/lo split (Q pre-scaled by 0.125)
// K/V are COMPACTED: only unmasked keys, per batch (rows >= ncomp stay zero).
#define QKV_ELEMS ((size_t)BB * HH * TT * DH)
__device__ __nv_bfloat16 g_q_h[QKV_ELEMS];
__device__ __nv_bfloat16 g_q_l[QKV_ELEMS];
__device__ __nv_bfloat16 g_k_h[QKV_ELEMS];
__device__ __nv_bfloat16 g_k_l[QKV_ELEMS];
__device__ __nv_bfloat16 g_v_h[QKV_ELEMS];
__device__ __nv_bfloat16 g_v_l[QKV_ELEMS];
// mask compaction map: token -> compacted key index (or -1), and counts
__device__ int g_cmap[BB * TT];
__device__ int g_ncomp[BB];

// ---------------------------------------------------------------------------
// sm_80-portable PTX helpers
// ---------------------------------------------------------------------------
__device__ __forceinline__ uint32_t smem_u32(const void* p) {
    uint32_t a;
    asm("{ .reg .u64 t; cvta.to.shared.u64 t, %1; cvt.u32.u64 %0, t; }"
        : "=r"(a) : "l"(p));
    return a;
}
__device__ __forceinline__ void cpa16(uint32_t dst, const void* src) {
    asm volatile("cp.async.cg.shared.global [%0], [%1], 16;"
                 :: "r"(dst), "l"(src));
}
#define CP_COMMIT() asm volatile("cp.async.commit_group;" ::: "memory")
#define CP_WAIT(n)  asm volatile("cp.async.wait_group %0;" :: "n"(n) : "memory")

__device__ __forceinline__ void ldsm4(uint32_t* r, uint32_t addr) {
    asm volatile("ldmatrix.sync.aligned.m8n8.x4.shared.b16 {%0,%1,%2,%3}, [%4];"
                 : "=r"(r[0]), "=r"(r[1]), "=r"(r[2]), "=r"(r[3]) : "r"(addr));
}
__device__ __forceinline__ void ldsm4t(uint32_t* r, uint32_t addr) {
    asm volatile("ldmatrix.sync.aligned.m8n8.x4.trans.shared.b16 {%0,%1,%2,%3}, [%4];"
                 : "=r"(r[0]), "=r"(r[1]), "=r"(r[2]), "=r"(r[3]) : "r"(addr));
}
__device__ __forceinline__ void mma_bf16(float* d, const uint32_t* a,
                                         const uint32_t* b) {
    asm volatile("mma.sync.aligned.m16n8k16.row.col.f32.bf16.bf16.f32 "
                 "{%0,%1,%2,%3}, {%4,%5,%6,%7}, {%8,%9}, {%0,%1,%2,%3};"
                 : "+f"(d[0]), "+f"(d[1]), "+f"(d[2]), "+f"(d[3])
                 : "r"(a[0]), "r"(a[1]), "r"(a[2]), "r"(a[3]),
                   "r"(b[0]), "r"(b[1]));
}
// split pair of fp32 -> bf16x2 hi + bf16x2 lo
__device__ __forceinline__ void split2(float x, float y, uint32_t& hi, uint32_t& lo) {
    __nv_bfloat162 h, l;
    h.x = __float2bfloat16(x);
    h.y = __float2bfloat16(y);
    l.x = __float2bfloat16(x - __bfloat162float(h.x));
    l.y = __float2bfloat16(y - __bfloat162float(h.y));
    hi = *(uint32_t*)&h;
    lo = *(uint32_t*)&l;
}

// ---------------------------------------------------------------------------
// Fused conversion kernel: pre-split weights + activations, plus per-batch
// mask prefix-scan (blocks 8192..8195).
// ---------------------------------------------------------------------------
__device__ __forceinline__ void conv_w_body(
    const float* __restrict__ W, __nv_bfloat16* __restrict__ Wh,
    __nv_bfloat16* __restrict__ Wl, int K, int N, int bx, int by, int tid)
{
    __shared__ float t[32][33];
    const int n0 = bx * 32, k0 = by * 32;
    const int tx = tid & 31, ty = tid >> 5;
    #pragma unroll
    for (int i = 0; i < 32; i += 8)
        t[ty + i][tx] = W[(size_t)(k0 + ty + i) * N + n0 + tx];
    __syncthreads();
    #pragma unroll
    for (int i = 0; i < 32; i += 8) {
        int n = ty + i;
        float v = t[tx][n];
        __nv_bfloat16 h = __float2bfloat16(v);
        __nv_bfloat16 l = __float2bfloat16(v - __bfloat162float(h));
        size_t o = (size_t)(n0 + n) * K + k0 + tx;
        Wh[o] = h;
        Wl[o] = l;
    }
}

__global__ __launch_bounds__(256)
void conv_all_kernel(const float* __restrict__ W_qkv,
                     const float* __restrict__ W_out,
                     const float* __restrict__ x,
                     const int* __restrict__ mask,
                     __nv_bfloat16* __restrict__ wqh, __nv_bfloat16* __restrict__ wql,
                     __nv_bfloat16* __restrict__ woh, __nv_bfloat16* __restrict__ wol,
                     __nv_bfloat16* __restrict__ xh,  __nv_bfloat16* __restrict__ xl,
                     int* __restrict__ cmap, int* __restrict__ ncomp)
{
    const int bid = blockIdx.x, tid = threadIdx.x;
    if (bid < 3072) {
        conv_w_body(W_qkv, wqh, wql, DD, N_QKV, bid % 96, bid / 96, tid);
    } else if (bid < 4096) {
        const int id = bid - 3072;
        conv_w_body(W_out, woh, wol, DD, DD, id % 32, id / 32, tid);
    } else if (bid < 8192) {
        const int base = (bid - 4096) * 512 + tid;
        #pragma unroll
        for (int u = 0; u < 2; u++) {
            int idx = base + u * 256;
            float4 v = ((const float4*)x)[idx];
            uint32_t h0, h1, l0, l1;
            split2(v.x, v.y, h0, l0);
            split2(v.z, v.w, h1, l1);
            ((uint32_t*)xh)[idx * 2 + 0] = h0;
            ((uint32_t*)xh)[idx * 2 + 1] = h1;
            ((uint32_t*)xl)[idx * 2 + 0] = l0;
            ((uint32_t*)xl)[idx * 2 + 1] = l1;
        }
    } else {
        // mask prefix-scan for batch bb (2048 entries, 8 per thread)
        const int bb = bid - 8192;
        const int* mrow = mask + bb * TT;
        __shared__ int part[256];
        int loc[8];
        int s = 0;
        const int base = tid * 8;
        #pragma unroll
        for (int i = 0; i < 8; i++) {
            loc[i] = s;
            s += (mrow[base + i] != 0) ? 1 : 0;
        }
        part[tid] = s;
        __syncthreads();
        // Hillis-Steele inclusive scan
        for (int off = 1; off < 256; off <<= 1) {
            int v = (tid >= off) ? part[tid - off] : 0;
            __syncthreads();
            part[tid] += v;
            __syncthreads();
        }
        const int excl = (tid == 0) ? 0 : part[tid - 1];
        #pragma unroll
        for (int i = 0; i < 8; i++)
            cmap[bb * TT + base + i] =
                (mrow[base + i] != 0) ? (excl + loc[i]) : -1;
        if (tid == 255) ncomp[bb] = part[255];
    }
}

// ---------------------------------------------------------------------------
// Tensor-core GEMM via mma.sync (bf16 3-term split, fp32 accumulate)
// BK=32, 2-stage cp.async, 80B smem rows, 2 CTAs/SM.
// QKV epilogue scatters K/V through the compaction map.
// ---------------------------------------------------------------------------
#define GBK 32
#define AROW 40
#define MAT_BYTES (128 * AROW * 2)
#define ST_A_H 0
#define ST_A_L (1 * MAT_BYTES)
#define ST_B_H (2 * MAT_BYTES)
#define ST_B_L (3 * MAT_BYTES)
#define STAGE_B (4 * MAT_BYTES)
#define GEMM_SMEM (2 * STAGE_B)

__device__ __forceinline__ void gemm_load_chunk(
    uint32_t stBase,
    const __nv_bfloat16* __restrict__ Ah, const __nv_bfloat16* __restrict__ Al,
    const __nv_bfloat16* __restrict__ Bh, const __nv_bfloat16* __restrict__ Bl,
    int bm0, int bn0, int k0, int K, int tid)
{
    const int row = tid >> 1;
    const int kc  = (tid & 1) * 16;
    const size_t ga = (size_t)(bm0 + row) * K + k0 + kc;
    const size_t gb = (size_t)(bn0 + row) * K + k0 + kc;
    const uint32_t so = (uint32_t)(row * 80 + kc * 2);
    cpa16(stBase + ST_A_H + so,      Ah + ga);
    cpa16(stBase + ST_A_H + so + 16, Ah + ga + 8);
    cpa16(stBase + ST_A_L + so,      Al + ga);
    cpa16(stBase + ST_A_L + so + 16, Al + ga + 8);
    cpa16(stBase + ST_B_H + so,      Bh + gb);
    cpa16(stBase + ST_B_H + so + 16, Bh + gb + 8);
    cpa16(stBase + ST_B_L + so,      Bl + gb);
    cpa16(stBase + ST_B_L + so + 16, Bl + gb + 8);
}

__global__ __launch_bounds__(256, 2)
void gemm_tc_kernel(const __nv_bfloat16* __restrict__ Ah,
                    const __nv_bfloat16* __restrict__ Al,
                    const __nv_bfloat16* __restrict__ Bh,
                    const __nv_bfloat16* __restrict__ Bl,
                    const float* __restrict__ bias, float* __restrict__ C,
                    int M, int N, int K,
                    __nv_bfloat16* qh, __nv_bfloat16* ql,
                    __nv_bfloat16* kh, __nv_bfloat16* kl,
                    __nv_bfloat16* vh, __nv_bfloat16* vl,
                    const int* __restrict__ cmap)
{
    extern __shared__ char smraw[];
    const uint32_t sb = smem_u32(smraw);
    const int tid = threadIdx.x, wid = tid >> 5, lane = tid & 31;
    const int bm0 = blockIdx.y * 128, bn0 = blockIdx.x * 128;
    const int wm = wid >> 2, wn = wid & 3;

    const int a_r = (lane & 7) + ((lane >> 3) & 1) * 8;
    const int a_k = (lane >> 4) * 8;
    const int b_r = (lane & 7) + (lane >> 4) * 8;
    const int b_k = ((lane >> 3) & 1) * 8;

    float acc[4][4][4];
    #pragma unroll
    for (int i = 0; i < 4; i++)
        #pragma unroll
        for (int j = 0; j < 4; j++)
            #pragma unroll
            for (int v = 0; v < 4; v++) acc[i][j][v] = 0.0f;

    const int NCH = K / GBK;

    gemm_load_chunk(sb, Ah, Al, Bh, Bl, bm0, bn0, 0, K, tid);
    CP_COMMIT();

    for (int c = 0; c < NCH; c++) {
        const uint32_t st = sb + (uint32_t)(c & 1) * STAGE_B;
        if (c + 1 < NCH) {
            gemm_load_chunk(sb + (uint32_t)((c + 1) & 1) * STAGE_B,
                            Ah, Al, Bh, Bl, bm0, bn0, (c + 1) * GBK, K, tid);
            CP_COMMIT();
            CP_WAIT(1);
        } else {
            CP_WAIT(0);
        }
        __syncthreads();

        #pragma unroll
        for (int ks = 0; ks < 2; ks++) {
            const int k0 = ks * 16;
            uint32_t bh2[4][2], bl2[4][2];
            #pragma unroll
            for (int half = 0; half < 2; half++) {
                uint32_t baddr = (uint32_t)((wn * 32 + half * 16 + b_r) * 80
                                            + (k0 + b_k) * 2);
                uint32_t r[4];
                ldsm4(r, st + ST_B_H + baddr);
                bh2[half * 2 + 0][0] = r[0]; bh2[half * 2 + 0][1] = r[1];
                bh2[half * 2 + 1][0] = r[2]; bh2[half * 2 + 1][1] = r[3];
                ldsm4(r, st + ST_B_L + baddr);
                bl2[half * 2 + 0][0] = r[0]; bl2[half * 2 + 0][1] = r[1];
                bl2[half * 2 + 1][0] = r[2]; bl2[half * 2 + 1][1] = r[3];
            }
            #pragma unroll
            for (int mi = 0; mi < 4; mi++) {
                uint32_t aaddr = (uint32_t)((wm * 64 + mi * 16 + a_r) * 80
                                            + (k0 + a_k) * 2);
                uint32_t ah[4], al[4];
                ldsm4(ah, st + ST_A_H + aaddr);
                ldsm4(al, st + ST_A_L + aaddr);
                #pragma unroll
                for (int nf = 0; nf < 4; nf++) mma_bf16(acc[mi][nf], ah, bh2[nf]);
                #pragma unroll
                for (int nf = 0; nf < 4; nf++) mma_bf16(acc[mi][nf], ah, bl2[nf]);
                #pragma unroll
                for (int nf = 0; nf < 4; nf++) mma_bf16(acc[mi][nf], al, bh2[nf]);
            }
        }
        __syncthreads();
    }

    // Epilogue
    #pragma unroll
    for (int mi = 0; mi < 4; mi++) {
        const int row = bm0 + wm * 64 + mi * 16 + (lane >> 2);
        #pragma unroll
        for (int nf = 0; nf < 4; nf++) {
            const int col = bn0 + wn * 32 + nf * 8 + (lane & 3) * 2;
            const float b0 = bias[col], b1 = bias[col + 1];
            float v0 = acc[mi][nf][0] + b0, v1 = acc[mi][nf][1] + b1;
            float v2 = acc[mi][nf][2] + b0, v3 = acc[mi][nf][3] + b1;
            if (qh == nullptr) {
                float2 p0, p1;
                p0.x = v0; p0.y = v1; p1.x = v2; p1.y = v3;
                *(float2*)&C[(size_t)row * N + col]       = p0;
                *(float2*)&C[(size_t)(row + 8) * N + col] = p1;
            } else {
                const int sec = col >> 10;
                const int hh  = (col >> 6) & 15;
                const int d   = col & 63;
                const int bb  = row >> 11;
                const int trow = row & 2047;
                const size_t hb = ((size_t)(bb * 16 + hh)) * TT;
                if (sec == 0) {
                    // Q: dense, pre-scaled by 1/8
                    uint32_t hi, lo;
                    size_t dst = (hb + trow) * 64 + d;
                    split2(v0 * 0.125f, v1 * 0.125f, hi, lo);
                    *(uint32_t*)(qh + dst) = hi;
                    *(uint32_t*)(ql + dst) = lo;
                    split2(v2 * 0.125f, v3 * 0.125f, hi, lo);
                    *(uint32_t*)(qh + dst + 8 * 64) = hi;
                    *(uint32_t*)(ql + dst + 8 * 64) = lo;
                } else {
                    // K/V: compacted scatter via cmap (masked keys dropped)
                    __nv_bfloat16 *H = (sec == 1) ? kh : vh;
                    __nv_bfloat16 *L = (sec == 1) ? kl : vl;
                    const int cr0 = cmap[bb * TT + trow];
                    const int cr1 = cmap[bb * TT + trow + 8];
                    uint32_t hi, lo;
                    if (cr0 >= 0) {
                        size_t dst = (hb + cr0) * 64 + d;
                        split2(v0, v1, hi, lo);
                        *(uint32_t*)(H + dst) = hi;
                        *(uint32_t*)(L + dst) = lo;
                    }
                    if (cr1 >= 0) {
                        size_t dst = (hb + cr1) * 64 + d;
                        split2(v2, v3, hi, lo);
                        *(uint32_t*)(H + dst) = hi;
                        *(uint32_t*)(L + dst) = lo;
                    }
                }
            }
        }
    }
}

// ---------------------------------------------------------------------------
// Tensor-core flash attention over COMPACTED K/V (no in-loop mask loads;
// validity = key index < ncomp[b]).
// ---------------------------------------------------------------------------
#define AVROW 72                       // bf16 row stride (144 B)
#define KQH 0
#define KQL 18432
#define KKH 0
#define KKL 9216
#define KVH 18432
#define KVL 27648
#define ASTAGE 36864
#define ATTN_SMEM (2 * ASTAGE + 256)   // 73984

__device__ __forceinline__ void attn_kvload(
    uint32_t sb, int region, int bh, int n0,
    const __nv_bfloat16* __restrict__ Kh_g, const __nv_bfloat16* __restrict__ Kl_g,
    const __nv_bfloat16* __restrict__ Vh_g, const __nv_bfloat16* __restrict__ Vl_g,
    int tid)
{
    const uint32_t st = sb + (uint32_t)region * ASTAGE;
    const size_t gb = ((size_t)bh * TT + n0) * 64;
    #pragma unroll
    for (int u = 0; u < 2; u++) {
        int idx = tid * 2 + u;
        int row = idx >> 3, ch = idx & 7;
        uint32_t so = (uint32_t)(row * 144 + ch * 16);
        size_t go = gb + row * 64 + ch * 8;
        cpa16(st + KKH + so, Kh_g + go);
        cpa16(st + KKL + so, Kl_g + go);
        cpa16(st + KVH + so, Vh_g + go);
        cpa16(st + KVL + so, Vl_g + go);
    }
}

__global__ __launch_bounds__(256, 2)
void attn_tc_kernel(const __nv_bfloat16* __restrict__ Qh_g,
                    const __nv_bfloat16* __restrict__ Ql_g,
                    const __nv_bfloat16* __restrict__ Kh_g,
                    const __nv_bfloat16* __restrict__ Kl_g,
                    const __nv_bfloat16* __restrict__ Vh_g,
                    const __nv_bfloat16* __restrict__ Vl_g,
                    const int* __restrict__ ncomp,
                    __nv_bfloat16* __restrict__ Oh_g,
                    __nv_bfloat16* __restrict__ Ol_g)
{
    extern __shared__ char smraw[];
    const uint32_t sb = smem_u32(smraw);
    const int tid = threadIdx.x, wid = tid >> 5, lane = tid & 31;
    const int bh = blockIdx.y;
    const int b = bh >> 4, h = bh & 15;
    const int t0 = blockIdx.x * 128;
    const int wm = wid;

    const int a_r = (lane & 7) + ((lane >> 3) & 1) * 8;
    const int a_k = (lane >> 4) * 8;
    const int b_r = (lane & 7) + (lane >> 4) * 8;
    const int b_k = ((lane >> 3) & 1) * 8;
    const int c0base = (lane & 3) * 2;

    const int nc = ncomp[b];
    const int ntiles = (nc + 63) >> 6;   // >= 1 with overwhelming probability

    const size_t qbase = ((size_t)bh * TT + t0) * 64;
    #pragma unroll
    for (int i = 0; i < 4; i++) {
        int f = tid + i * 256;
        int row = f >> 3, ch = f & 7;
        uint32_t so = (uint32_t)(row * 144 + ch * 16);
        size_t go = qbase + row * 64 + ch * 8;
        cpa16(sb + KQH + so, Qh_g + go);
        cpa16(sb + KQL + so, Ql_g + go);
    }
    attn_kvload(sb, 1, bh, 0, Kh_g, Kl_g, Vh_g, Vl_g, tid);
    CP_COMMIT();
    CP_WAIT(0);
    __syncthreads();

    uint32_t qfh[4][4], qfl[4][4];
    #pragma unroll
    for (int kk = 0; kk < 4; kk++) {
        uint32_t addr = (uint32_t)(((wm * 16 + a_r) * AVROW + kk * 16 + a_k) * 2);
        ldsm4(qfh[kk], sb + KQH + addr);
        ldsm4(qfl[kk], sb + KQL + addr);
    }
    __syncthreads();

    float O[8][4];
    #pragma unroll
    for (int j = 0; j < 8; j++)
        #pragma unroll
        for (int v = 0; v < 4; v++) O[j][v] = 0.0f;
    float m0 = -3.0e38f, m1 = -3.0e38f, l0 = 0.0f, l1 = 0.0f;

    for (int t = 0; t < ntiles; t++) {
        const int rt = (t + 1) & 1;
        if (t + 1 < ntiles) {
            attn_kvload(sb, t & 1, bh, (t + 1) * 64,
                        Kh_g, Kl_g, Vh_g, Vl_g, tid);
            CP_COMMIT();
        }
        const uint32_t st = sb + (uint32_t)rt * ASTAGE;
        const int kbase = t * 64;

        float acc[8][4];
        #pragma unroll
        for (int j = 0; j < 8; j++)
            #pragma unroll
            for (int v = 0; v < 4; v++) acc[j][v] = 0.0f;

        #pragma unroll
        for (int kk = 0; kk < 4; kk++) {
            #pragma unroll
            for (int nb = 0; nb < 4; nb++) {
                uint32_t addr = (uint32_t)(((nb * 16 + b_r) * AVROW
                                            + kk * 16 + b_k) * 2);
                uint32_t rh[4], rl[4];
                ldsm4(rh, st + KKH + addr);
                ldsm4(rl, st + KKL + addr);
                mma_bf16(acc[2 * nb],     qfh[kk], &rh[0]);
                mma_bf16(acc[2 * nb + 1], qfh[kk], &rh[2]);
                mma_bf16(acc[2 * nb],     qfh[kk], &rl[0]);
                mma_bf16(acc[2 * nb + 1], qfh[kk], &rl[2]);
                mma_bf16(acc[2 * nb],     qfl[kk], &rh[0]);
                mma_bf16(acc[2 * nb + 1], qfl[kk], &rh[2]);
            }
        }

        // validity mask: key index < nc (tail-tile padding only)
        float rmax0 = -3.0e38f, rmax1 = -3.0e38f;
        #pragma unroll
        for (int j = 0; j < 8; j++) {
            int c = kbase + j * 8 + c0base;
            bool v0 = (c < nc), v1 = (c + 1 < nc);
            acc[j][0] = v0 ? acc[j][0] : -1000.0f;
            acc[j][1] = v1 ? acc[j][1] : -1000.0f;
            acc[j][2] = v0 ? acc[j][2] : -1000.0f;
            acc[j][3] = v1 ? acc[j][3] : -1000.0f;
            rmax0 = fmaxf(rmax0, fmaxf(acc[j][0], acc[j][1]));
            rmax1 = fmaxf(rmax1, fmaxf(acc[j][2], acc[j][3]));
        }
        rmax0 = fmaxf(rmax0, __shfl_xor_sync(0xffffffffu, rmax0, 1));
        rmax0 = fmaxf(rmax0, __shfl_xor_sync(0xffffffffu, rmax0, 2));
        rmax1 = fmaxf(rmax1, __shfl_xor_sync(0xffffffffu, rmax1, 1));
        rmax1 = fmaxf(rmax1, __shfl_xor_sync(0xffffffffu, rmax1, 2));

        float mn0 = fmaxf(m0, rmax0), mn1 = fmaxf(m1, rmax1);
        float al0 = __expf(m0 - mn0), al1 = __expf(m1 - mn1);
        m0 = mn0; m1 = mn1;

        float rs0 = 0.0f, rs1 = 0.0f;
        #pragma unroll
        for (int j = 0; j < 8; j++) {
            acc[j][0] = __expf(acc[j][0] - mn0); rs0 += acc[j][0];
            acc[j][1] = __expf(acc[j][1] - mn0); rs0 += acc[j][1];
            acc[j][2] = __expf(acc[j][2] - mn1); rs1 += acc[j][2];
            acc[j][3] = __expf(acc[j][3] - mn1); rs1 += acc[j][3];
        }
        rs0 += __shfl_xor_sync(0xffffffffu, rs0, 1);
        rs0 += __shfl_xor_sync(0xffffffffu, rs0, 2);
        rs1 += __shfl_xor_sync(0xffffffffu, rs1, 1);
        rs1 += __shfl_xor_sync(0xffffffffu, rs1, 2);
        l0 = l0 * al0 + rs0;
        l1 = l1 * al1 + rs1;
        #pragma unroll
        for (int j = 0; j < 8; j++) {
            O[j][0] *= al0; O[j][1] *= al0;
            O[j][2] *= al1; O[j][3] *= al1;
        }

        #pragma unroll
        for (int kk = 0; kk < 4; kk++) {
            uint32_t pah[4], pal[4];
            split2(acc[2 * kk][0],     acc[2 * kk][1],     pah[0], pal[0]);
            split2(acc[2 * kk][2],     acc[2 * kk][3],     pah[1], pal[1]);
            split2(acc[2 * kk + 1][0], acc[2 * kk + 1][1], pah[2], pal[2]);
            split2(acc[2 * kk + 1][2], acc[2 * kk + 1][3], pah[3], pal[3]);
            #pragma unroll
            for (int nb = 0; nb < 4; nb++) {
                uint32_t addr = (uint32_t)(((kk * 16 + ((lane >> 3) & 1) * 8
                                             + (lane & 7)) * AVROW
                                            + nb * 16 + (lane >> 4) * 8) * 2);
                uint32_t vh4[4], vl4[4];
                ldsm4t(vh4, st + KVH + addr);
                ldsm4t(vl4, st + KVL + addr);
                mma_bf16(O[2 * nb],     pah, &vh4[0]);
                mma_bf16(O[2 * nb + 1], pah, &vh4[2]);
                mma_bf16(O[2 * nb],     pah, &vl4[0]);
                mma_bf16(O[2 * nb + 1], pah, &vl4[2]);
                mma_bf16(O[2 * nb],     pal, &vh4[0]);
                mma_bf16(O[2 * nb + 1], pal, &vh4[2]);
            }
        }

        if (t + 1 < ntiles) CP_WAIT(0);
        __syncthreads();
    }

    const float inv0 = 1.0f / l0, inv1 = 1.0f / l1;
    const int trow = t0 + wm * 16 + (lane >> 2);
    const size_t ob0 = ((size_t)(b * TT + trow)) * DD + h * 64;
    const size_t ob1 = ob0 + (size_t)8 * DD;
    #pragma unroll
    for (int jn = 0; jn < 8; jn++) {
        int c = jn * 8 + c0base;
        uint32_t hi, lo;
        split2(O[jn][0] * inv0, O[jn][1] * inv0, hi, lo);
        *(uint32_t*)(Oh_g + ob0 + c) = hi;
        *(uint32_t*)(Ol_g + ob0 + c) = lo;
        split2(O[jn][2] * inv1, O[jn][3] * inv1, hi, lo);
        *(uint32_t*)(Oh_g + ob1 + c) = hi;
        *(uint32_t*)(Ol_g + ob1 + c) = lo;
    }
}

// ---------------------------------------------------------------------------
extern "C" void kernel_launch(void* const* d_in, const int* in_sizes, int n_in,
                              void* d_out, int out_size)
{
    const float* x     = (const float*)d_in[0];
    const int*   mask  = (const int*)  d_in[1];
    const float* W_qkv = (const float*)d_in[2];
    const float* b_qkv = (const float*)d_in[3];
    const float* W_out = (const float*)d_in[4];
    const float* b_out = (const float*)d_in[5];
    float* out = (float*)d_out;

    __nv_bfloat16 *wqh, *wql, *woh, *wol, *xh, *xl;
    __nv_bfloat16 *qh, *ql, *kh, *kl, *vh, *vl;
    int *cmap, *ncomp;
    cudaGetSymbolAddress((void**)&wqh, g_wqkv_h);
    cudaGetSymbolAddress((void**)&wql, g_wqkv_l);
    cudaGetSymbolAddress((void**)&woh, g_wout_h);
    cudaGetSymbolAddress((void**)&wol, g_wout_l);
    cudaGetSymbolAddress((void**)&xh,  g_act_h);
    cudaGetSymbolAddress((void**)&xl,  g_act_l);
    cudaGetSymbolAddress((void**)&qh,  g_q_h);
    cudaGetSymbolAddress((void**)&ql,  g_q_l);
    cudaGetSymbolAddress((void**)&kh,  g_k_h);
    cudaGetSymbolAddress((void**)&kl,  g_k_l);
    cudaGetSymbolAddress((void**)&vh,  g_v_h);
    cudaGetSymbolAddress((void**)&vl,  g_v_l);
    cudaGetSymbolAddress((void**)&cmap,  g_cmap);
    cudaGetSymbolAddress((void**)&ncomp, g_ncomp);

    cudaFuncSetAttribute(gemm_tc_kernel,
                         cudaFuncAttributeMaxDynamicSharedMemorySize, GEMM_SMEM);
    cudaFuncSetAttribute(attn_tc_kernel,
                         cudaFuncAttributeMaxDynamicSharedMemorySize, ATTN_SMEM);

    // 0) Fused pre-split + mask prefix-scan
    conv_all_kernel<<<8196, 256>>>(W_qkv, W_out, x, mask,
                                   wqh, wql, woh, wol, xh, xl, cmap, ncomp);

    // 1) QKV projection; K/V scattered compacted via cmap (Q pre-scaled)
    gemm_tc_kernel<<<dim3(N_QKV / 128, MTOT / 128), 256, GEMM_SMEM>>>(
        xh, xl, wqh, wql, b_qkv, nullptr, MTOT, N_QKV, DD,
        qh, ql, kh, kl, vh, vl, cmap);

    // 2) Flash attention over compacted K/V (~half the tiles)
    attn_tc_kernel<<<dim3(TT / 128, BB * HH), 256, ATTN_SMEM>>>(
        qh, ql, kh, kl, vh, vl, ncomp, xh, xl);

    // 3) Output projection
    gemm_tc_kernel<<<dim3(DD / 128, MTOT / 128), 256, GEMM_SMEM>>>(
        xh, xl, woh, wol, b_out, out, MTOT, DD, DD,
        nullptr, nullptr, nullptr, nullptr, nullptr, nullptr, nullptr);
}

// round 11
// speedup vs baseline: 1.4580x; 1.1364x over previous
#include <cuda_runtime.h>
#include <cuda_bf16.h>
#include <cstdint>
#include <math.h>

// Problem constants
#define BB 4
#define TT 2048
#define DD 1024
#define HH 16
#define DH 64
#define MTOT (BB*TT)        // 8192
#define N_QKV (3*DD)        // 3072
#define N_KV  (2*DD)        // 2048

// Scratch (device globals: allocation-guard safe)
__device__ __nv_bfloat16 g_wqkv_h[(size_t)N_QKV * DD];  // W_qkv^T hi  [3072,1024]
__device__ __nv_bfloat16 g_wqkv_l[(size_t)N_QKV * DD];
__device__ __nv_bfloat16 g_wout_h[(size_t)DD * DD];     // W_out^T hi  [1024,1024]
__device__ __nv_bfloat16 g_wout_l[(size_t)DD * DD];
__device__ __nv_bfloat16 g_act_h[(size_t)MTOT * DD];    // activation hi [M,K]
__device__ __nv_bfloat16 g_act_l[(size_t)MTOT * DD];
// Q/K/V head-major [B*H][T][DH], hi/lo split (Q pre-scaled by 0.125)
// K/V are COMPACTED: only unmasked keys, per batch.
#define QKV_ELEMS ((size_t)BB * HH * TT * DH)
__device__ __nv_bfloat16 g_q_h[QKV_ELEMS];
__device__ __nv_bfloat16 g_q_l[QKV_ELEMS];
__device__ __nv_bfloat16 g_k_h[QKV_ELEMS];
__device__ __nv_bfloat16 g_k_l[QKV_ELEMS];
__device__ __nv_bfloat16 g_v_h[QKV_ELEMS];
__device__ __nv_bfloat16 g_v_l[QKV_ELEMS];
// mask compaction: counts and compacted-index -> token map
__device__ int g_toklist[BB * TT];
__device__ int g_ncomp[BB];

// ---------------------------------------------------------------------------
// sm_80-portable PTX helpers
// ---------------------------------------------------------------------------
__device__ __forceinline__ uint32_t smem_u32(const void* p) {
    uint32_t a;
    asm("{ .reg .u64 t; cvta.to.shared.u64 t, %1; cvt.u32.u64 %0, t; }"
        : "=r"(a) : "l"(p));
    return a;
}
__device__ __forceinline__ void cpa16(uint32_t dst, const void* src) {
    asm volatile("cp.async.cg.shared.global [%0], [%1], 16;"
                 :: "r"(dst), "l"(src));
}
#define CP_COMMIT() asm volatile("cp.async.commit_group;" ::: "memory")
#define CP_WAIT(n)  asm volatile("cp.async.wait_group %0;" :: "n"(n) : "memory")

__device__ __forceinline__ void ldsm4(uint32_t* r, uint32_t addr) {
    asm volatile("ldmatrix.sync.aligned.m8n8.x4.shared.b16 {%0,%1,%2,%3}, [%4];"
                 : "=r"(r[0]), "=r"(r[1]), "=r"(r[2]), "=r"(r[3]) : "r"(addr));
}
__device__ __forceinline__ void ldsm4t(uint32_t* r, uint32_t addr) {
    asm volatile("ldmatrix.sync.aligned.m8n8.x4.trans.shared.b16 {%0,%1,%2,%3}, [%4];"
                 : "=r"(r[0]), "=r"(r[1]), "=r"(r[2]), "=r"(r[3]) : "r"(addr));
}
__device__ __forceinline__ void mma_bf16(float* d, const uint32_t* a,
                                         const uint32_t* b) {
    asm volatile("mma.sync.aligned.m16n8k16.row.col.f32.bf16.bf16.f32 "
                 "{%0,%1,%2,%3}, {%4,%5,%6,%7}, {%8,%9}, {%0,%1,%2,%3};"
                 : "+f"(d[0]), "+f"(d[1]), "+f"(d[2]), "+f"(d[3])
                 : "r"(a[0]), "r"(a[1]), "r"(a[2]), "r"(a[3]),
                   "r"(b[0]), "r"(b[1]));
}
// split pair of fp32 -> bf16x2 hi + bf16x2 lo
__device__ __forceinline__ void split2(float x, float y, uint32_t& hi, uint32_t& lo) {
    __nv_bfloat162 h, l;
    h.x = __float2bfloat16(x);
    h.y = __float2bfloat16(y);
    l.x = __float2bfloat16(x - __bfloat162float(h.x));
    l.y = __float2bfloat16(y - __bfloat162float(h.y));
    hi = *(uint32_t*)&h;
    lo = *(uint32_t*)&l;
}

// ---------------------------------------------------------------------------
// Fused conversion kernel: pre-split weights + activations + mask scan
// (blocks 8192..8195 build toklist/ncomp).
// ---------------------------------------------------------------------------
__device__ __forceinline__ void conv_w_body(
    const float* __restrict__ W, __nv_bfloat16* __restrict__ Wh,
    __nv_bfloat16* __restrict__ Wl, int K, int N, int bx, int by, int tid)
{
    __shared__ float t[32][33];
    const int n0 = bx * 32, k0 = by * 32;
    const int tx = tid & 31, ty = tid >> 5;
    #pragma unroll
    for (int i = 0; i < 32; i += 8)
        t[ty + i][tx] = W[(size_t)(k0 + ty + i) * N + n0 + tx];
    __syncthreads();
    #pragma unroll
    for (int i = 0; i < 32; i += 8) {
        int n = ty + i;
        float v = t[tx][n];
        __nv_bfloat16 h = __float2bfloat16(v);
        __nv_bfloat16 l = __float2bfloat16(v - __bfloat162float(h));
        size_t o = (size_t)(n0 + n) * K + k0 + tx;
        Wh[o] = h;
        Wl[o] = l;
    }
}

__global__ __launch_bounds__(256)
void conv_all_kernel(const float* __restrict__ W_qkv,
                     const float* __restrict__ W_out,
                     const float* __restrict__ x,
                     const int* __restrict__ mask,
                     __nv_bfloat16* __restrict__ wqh, __nv_bfloat16* __restrict__ wql,
                     __nv_bfloat16* __restrict__ woh, __nv_bfloat16* __restrict__ wol,
                     __nv_bfloat16* __restrict__ xh,  __nv_bfloat16* __restrict__ xl,
                     int* __restrict__ toklist, int* __restrict__ ncomp)
{
    const int bid = blockIdx.x, tid = threadIdx.x;
    if (bid < 3072) {
        conv_w_body(W_qkv, wqh, wql, DD, N_QKV, bid % 96, bid / 96, tid);
    } else if (bid < 4096) {
        const int id = bid - 3072;
        conv_w_body(W_out, woh, wol, DD, DD, id % 32, id / 32, tid);
    } else if (bid < 8192) {
        const int base = (bid - 4096) * 512 + tid;
        #pragma unroll
        for (int u = 0; u < 2; u++) {
            int idx = base + u * 256;
            float4 v = ((const float4*)x)[idx];
            uint32_t h0, h1, l0, l1;
            split2(v.x, v.y, h0, l0);
            split2(v.z, v.w, h1, l1);
            ((uint32_t*)xh)[idx * 2 + 0] = h0;
            ((uint32_t*)xh)[idx * 2 + 1] = h1;
            ((uint32_t*)xl)[idx * 2 + 0] = l0;
            ((uint32_t*)xl)[idx * 2 + 1] = l1;
        }
    } else {
        // mask prefix-scan for batch bb: build toklist (compact idx -> token)
        const int bb = bid - 8192;
        const int* mrow = mask + bb * TT;
        __shared__ int part[256];
        int loc[8];
        int s = 0;
        const int base = tid * 8;
        #pragma unroll
        for (int i = 0; i < 8; i++) {
            loc[i] = s;
            s += (mrow[base + i] != 0) ? 1 : 0;
        }
        part[tid] = s;
        __syncthreads();
        for (int off = 1; off < 256; off <<= 1) {
            int v = (tid >= off) ? part[tid - off] : 0;
            __syncthreads();
            part[tid] += v;
            __syncthreads();
        }
        const int excl = (tid == 0) ? 0 : part[tid - 1];
        #pragma unroll
        for (int i = 0; i < 8; i++)
            if (mrow[base + i] != 0)
                toklist[bb * TT + excl + loc[i]] = base + i;
        if (tid == 255) ncomp[bb] = part[255];
    }
}

// ---------------------------------------------------------------------------
// Shared GEMM machinery: BK=32, 2-stage cp.async, 80B smem rows, 2 CTAs/SM.
// ---------------------------------------------------------------------------
#define GBK 32
#define AROW 40
#define MAT_BYTES (128 * AROW * 2)
#define ST_A_H 0
#define ST_A_L (1 * MAT_BYTES)
#define ST_B_H (2 * MAT_BYTES)
#define ST_B_L (3 * MAT_BYTES)
#define STAGE_B (4 * MAT_BYTES)
#define GEMM_SMEM (2 * STAGE_B)

// compute body for one chunk (shared by all GEMM kernels)
__device__ __forceinline__ void gemm_compute_chunk(
    uint32_t st, int wm, int wn,
    int a_r, int a_k, int b_r, int b_k,
    float acc[4][4][4])
{
    #pragma unroll
    for (int ks = 0; ks < 2; ks++) {
        const int k0 = ks * 16;
        uint32_t bh2[4][2], bl2[4][2];
        #pragma unroll
        for (int half = 0; half < 2; half++) {
            uint32_t baddr = (uint32_t)((wn * 32 + half * 16 + b_r) * 80
                                        + (k0 + b_k) * 2);
            uint32_t r[4];
            ldsm4(r, st + ST_B_H + baddr);
            bh2[half * 2 + 0][0] = r[0]; bh2[half * 2 + 0][1] = r[1];
            bh2[half * 2 + 1][0] = r[2]; bh2[half * 2 + 1][1] = r[3];
            ldsm4(r, st + ST_B_L + baddr);
            bl2[half * 2 + 0][0] = r[0]; bl2[half * 2 + 0][1] = r[1];
            bl2[half * 2 + 1][0] = r[2]; bl2[half * 2 + 1][1] = r[3];
        }
        #pragma unroll
        for (int mi = 0; mi < 4; mi++) {
            uint32_t aaddr = (uint32_t)((wm * 64 + mi * 16 + a_r) * 80
                                        + (k0 + a_k) * 2);
            uint32_t ah[4], al[4];
            ldsm4(ah, st + ST_A_H + aaddr);
            ldsm4(al, st + ST_A_L + aaddr);
            #pragma unroll
            for (int nf = 0; nf < 4; nf++) mma_bf16(acc[mi][nf], ah, bh2[nf]);
            #pragma unroll
            for (int nf = 0; nf < 4; nf++) mma_bf16(acc[mi][nf], ah, bl2[nf]);
            #pragma unroll
            for (int nf = 0; nf < 4; nf++) mma_bf16(acc[mi][nf], al, bh2[nf]);
        }
    }
}

__device__ __forceinline__ void gemm_load_chunk_rows(
    uint32_t stBase,
    const __nv_bfloat16* __restrict__ Ah, const __nv_bfloat16* __restrict__ Al,
    const __nv_bfloat16* __restrict__ Bh, const __nv_bfloat16* __restrict__ Bl,
    size_t a_row_off, size_t b_row_off, int k0, int tid)
{
    // a_row_off/b_row_off: element offset of this thread's row start (+kc)
    const int kc = (tid & 1) * 16;
    const int row = tid >> 1;
    const uint32_t so = (uint32_t)(row * 80 + kc * 2);
    cpa16(stBase + ST_A_H + so,      Ah + a_row_off + k0);
    cpa16(stBase + ST_A_H + so + 16, Ah + a_row_off + k0 + 8);
    cpa16(stBase + ST_A_L + so,      Al + a_row_off + k0);
    cpa16(stBase + ST_A_L + so + 16, Al + a_row_off + k0 + 8);
    cpa16(stBase + ST_B_H + so,      Bh + b_row_off + k0);
    cpa16(stBase + ST_B_H + so + 16, Bh + b_row_off + k0 + 8);
    cpa16(stBase + ST_B_L + so,      Bl + b_row_off + k0);
    cpa16(stBase + ST_B_L + so + 16, Bl + b_row_off + k0 + 8);
}

// ---------------------------------------------------------------------------
// GEMM A: dense. Epilogue: plain C+bias (qh==nullptr) or Q-scatter.
// ---------------------------------------------------------------------------
__global__ __launch_bounds__(256, 2)
void gemm_tc_kernel(const __nv_bfloat16* __restrict__ Ah,
                    const __nv_bfloat16* __restrict__ Al,
                    const __nv_bfloat16* __restrict__ Bh,
                    const __nv_bfloat16* __restrict__ Bl,
                    const float* __restrict__ bias, float* __restrict__ C,
                    int M, int N, int K,
                    __nv_bfloat16* qh, __nv_bfloat16* ql)
{
    extern __shared__ char smraw[];
    const uint32_t sb = smem_u32(smraw);
    const int tid = threadIdx.x, wid = tid >> 5, lane = tid & 31;
    const int bm0 = blockIdx.y * 128, bn0 = blockIdx.x * 128;
    const int wm = wid >> 2, wn = wid & 3;

    const int a_r = (lane & 7) + ((lane >> 3) & 1) * 8;
    const int a_k = (lane >> 4) * 8;
    const int b_r = (lane & 7) + (lane >> 4) * 8;
    const int b_k = ((lane >> 3) & 1) * 8;

    const int row = tid >> 1, kc = (tid & 1) * 16;
    const size_t a_off = (size_t)(bm0 + row) * K + kc;
    const size_t b_off = (size_t)(bn0 + row) * K + kc;

    float acc[4][4][4];
    #pragma unroll
    for (int i = 0; i < 4; i++)
        #pragma unroll
        for (int j = 0; j < 4; j++)
            #pragma unroll
            for (int v = 0; v < 4; v++) acc[i][j][v] = 0.0f;

    const int NCH = K / GBK;
    gemm_load_chunk_rows(sb, Ah, Al, Bh, Bl, a_off, b_off, 0, tid);
    CP_COMMIT();

    for (int c = 0; c < NCH; c++) {
        const uint32_t st = sb + (uint32_t)(c & 1) * STAGE_B;
        if (c + 1 < NCH) {
            gemm_load_chunk_rows(sb + (uint32_t)((c + 1) & 1) * STAGE_B,
                                 Ah, Al, Bh, Bl, a_off, b_off,
                                 (c + 1) * GBK, tid);
            CP_COMMIT();
            CP_WAIT(1);
        } else {
            CP_WAIT(0);
        }
        __syncthreads();
        gemm_compute_chunk(st, wm, wn, a_r, a_k, b_r, b_k, acc);
        __syncthreads();
    }

    #pragma unroll
    for (int mi = 0; mi < 4; mi++) {
        const int orow = bm0 + wm * 64 + mi * 16 + (lane >> 2);
        #pragma unroll
        for (int nf = 0; nf < 4; nf++) {
            const int col = bn0 + wn * 32 + nf * 8 + (lane & 3) * 2;
            const float b0 = bias[col], b1 = bias[col + 1];
            float v0 = acc[mi][nf][0] + b0, v1 = acc[mi][nf][1] + b1;
            float v2 = acc[mi][nf][2] + b0, v3 = acc[mi][nf][3] + b1;
            if (qh == nullptr) {
                float2 p0, p1;
                p0.x = v0; p0.y = v1; p1.x = v2; p1.y = v3;
                *(float2*)&C[(size_t)orow * N + col]       = p0;
                *(float2*)&C[(size_t)(orow + 8) * N + col] = p1;
            } else {
                // Q scatter: head-major, pre-scaled by 1/8
                const int hh  = (col >> 6) & 15;
                const int d   = col & 63;
                const int bb  = orow >> 11;
                const int trow = orow & 2047;
                size_t dst = (((size_t)(bb * 16 + hh)) * TT + trow) * 64 + d;
                uint32_t hi, lo;
                split2(v0 * 0.125f, v1 * 0.125f, hi, lo);
                *(uint32_t*)(qh + dst) = hi;
                *(uint32_t*)(ql + dst) = lo;
                split2(v2 * 0.125f, v3 * 0.125f, hi, lo);
                *(uint32_t*)(qh + dst + 8 * 64) = hi;
                *(uint32_t*)(ql + dst + 8 * 64) = lo;
            }
        }
    }
}

// ---------------------------------------------------------------------------
// GEMM KV: A gathered over compacted tokens; only ~ncomp rows computed.
// grid x = N_KV/128 = 16; grid y = b*16 + tile (tile covers compacted rows).
// B = W_qkv^T rows [1024, 3072) (passed pre-offset), bias pre-offset.
// ---------------------------------------------------------------------------
__global__ __launch_bounds__(256, 2)
void gemm_kv_kernel(const __nv_bfloat16* __restrict__ Ah,
                    const __nv_bfloat16* __restrict__ Al,
                    const __nv_bfloat16* __restrict__ Bh,
                    const __nv_bfloat16* __restrict__ Bl,
                    const float* __restrict__ bias,
                    __nv_bfloat16* kh, __nv_bfloat16* kl,
                    __nv_bfloat16* vh, __nv_bfloat16* vl,
                    const int* __restrict__ toklist,
                    const int* __restrict__ ncomp)
{
    const int bb = blockIdx.y >> 4;
    const int tile = blockIdx.y & 15;
    const int nc = ncomp[bb];
    if (tile * 128 >= nc) return;   // uniform early exit

    extern __shared__ char smraw[];
    const uint32_t sb = smem_u32(smraw);
    const int tid = threadIdx.x, wid = tid >> 5, lane = tid & 31;
    const int bn0 = blockIdx.x * 128;
    const int wm = wid >> 2, wn = wid & 3;

    const int a_r = (lane & 7) + ((lane >> 3) & 1) * 8;
    const int a_k = (lane >> 4) * 8;
    const int b_r = (lane & 7) + (lane >> 4) * 8;
    const int b_k = ((lane >> 3) & 1) * 8;

    // gathered A row (hoisted: row fixed per thread across all chunks)
    const int row = tid >> 1, kc = (tid & 1) * 16;
    int ci = tile * 128 + row;
    if (ci >= nc) ci = nc - 1;                     // clamp (stores guarded)
    const int token = toklist[bb * TT + ci];
    const size_t a_off = (size_t)(bb * TT + token) * DD + kc;
    const size_t b_off = (size_t)(bn0 + row) * DD + kc;

    float acc[4][4][4];
    #pragma unroll
    for (int i = 0; i < 4; i++)
        #pragma unroll
        for (int j = 0; j < 4; j++)
            #pragma unroll
            for (int v = 0; v < 4; v++) acc[i][j][v] = 0.0f;

    const int NCH = DD / GBK;
    gemm_load_chunk_rows(sb, Ah, Al, Bh, Bl, a_off, b_off, 0, tid);
    CP_COMMIT();

    for (int c = 0; c < NCH; c++) {
        const uint32_t st = sb + (uint32_t)(c & 1) * STAGE_B;
        if (c + 1 < NCH) {
            gemm_load_chunk_rows(sb + (uint32_t)((c + 1) & 1) * STAGE_B,
                                 Ah, Al, Bh, Bl, a_off, b_off,
                                 (c + 1) * GBK, tid);
            CP_COMMIT();
            CP_WAIT(1);
        } else {
            CP_WAIT(0);
        }
        __syncthreads();
        gemm_compute_chunk(st, wm, wn, a_r, a_k, b_r, b_k, acc);
        __syncthreads();
    }

    // Epilogue: store K/V at compacted rows (guarded)
    #pragma unroll
    for (int mi = 0; mi < 4; mi++) {
        const int rin = wm * 64 + mi * 16 + (lane >> 2);
        const int crow0 = tile * 128 + rin;
        const int crow1 = crow0 + 8;
        #pragma unroll
        for (int nf = 0; nf < 4; nf++) {
            const int col = bn0 + wn * 32 + nf * 8 + (lane & 3) * 2;  // 0..2047
            const float b0 = bias[col], b1 = bias[col + 1];
            float v0 = acc[mi][nf][0] + b0, v1 = acc[mi][nf][1] + b1;
            float v2 = acc[mi][nf][2] + b0, v3 = acc[mi][nf][3] + b1;
            __nv_bfloat16* H = (col < DD) ? kh : vh;
            __nv_bfloat16* L = (col < DD) ? kl : vl;
            const int hh = (col >> 6) & 15;
            const int d  = col & 63;
            const size_t hb = ((size_t)(bb * 16 + hh)) * TT;
            uint32_t hi, lo;
            if (crow0 < nc) {
                size_t dst = (hb + crow0) * 64 + d;
                split2(v0, v1, hi, lo);
                *(uint32_t*)(H + dst) = hi;
                *(uint32_t*)(L + dst) = lo;
            }
            if (crow1 < nc) {
                size_t dst = (hb + crow1) * 64 + d;
                split2(v2, v3, hi, lo);
                *(uint32_t*)(H + dst) = hi;
                *(uint32_t*)(L + dst) = lo;
            }
        }
    }
}

// ---------------------------------------------------------------------------
// Tensor-core flash attention over COMPACTED K/V — unchanged from R10.
// ---------------------------------------------------------------------------
#define AVROW 72                       // bf16 row stride (144 B)
#define KQH 0
#define KQL 18432
#define KKH 0
#define KKL 9216
#define KVH 18432
#define KVL 27648
#define ASTAGE 36864
#define ATTN_SMEM (2 * ASTAGE + 256)   // 73984

__device__ __forceinline__ void attn_kvload(
    uint32_t sb, int region, int bh, int n0,
    const __nv_bfloat16* __restrict__ Kh_g, const __nv_bfloat16* __restrict__ Kl_g,
    const __nv_bfloat16* __restrict__ Vh_g, const __nv_bfloat16* __restrict__ Vl_g,
    int tid)
{
    const uint32_t st = sb + (uint32_t)region * ASTAGE;
    const size_t gb = ((size_t)bh * TT + n0) * 64;
    #pragma unroll
    for (int u = 0; u < 2; u++) {
        int idx = tid * 2 + u;
        int row = idx >> 3, ch = idx & 7;
        uint32_t so = (uint32_t)(row * 144 + ch * 16);
        size_t go = gb + row * 64 + ch * 8;
        cpa16(st + KKH + so, Kh_g + go);
        cpa16(st + KKL + so, Kl_g + go);
        cpa16(st + KVH + so, Vh_g + go);
        cpa16(st + KVL + so, Vl_g + go);
    }
}

__global__ __launch_bounds__(256, 2)
void attn_tc_kernel(const __nv_bfloat16* __restrict__ Qh_g,
                    const __nv_bfloat16* __restrict__ Ql_g,
                    const __nv_bfloat16* __restrict__ Kh_g,
                    const __nv_bfloat16* __restrict__ Kl_g,
                    const __nv_bfloat16* __restrict__ Vh_g,
                    const __nv_bfloat16* __restrict__ Vl_g,
                    const int* __restrict__ ncomp,
                    __nv_bfloat16* __restrict__ Oh_g,
                    __nv_bfloat16* __restrict__ Ol_g)
{
    extern __shared__ char smraw[];
    const uint32_t sb = smem_u32(smraw);
    const int tid = threadIdx.x, wid = tid >> 5, lane = tid & 31;
    const int bh = blockIdx.y;
    const int b = bh >> 4, h = bh & 15;
    const int t0 = blockIdx.x * 128;
    const int wm = wid;

    const int a_r = (lane & 7) + ((lane >> 3) & 1) * 8;
    const int a_k = (lane >> 4) * 8;
    const int b_r = (lane & 7) + (lane >> 4) * 8;
    const int b_k = ((lane >> 3) & 1) * 8;
    const int c0base = (lane & 3) * 2;

    const int nc = ncomp[b];
    const int ntiles = (nc + 63) >> 6;

    const size_t qbase = ((size_t)bh * TT + t0) * 64;
    #pragma unroll
    for (int i = 0; i < 4; i++) {
        int f = tid + i * 256;
        int row = f >> 3, ch = f & 7;
        uint32_t so = (uint32_t)(row * 144 + ch * 16);
        size_t go = qbase + row * 64 + ch * 8;
        cpa16(sb + KQH + so, Qh_g + go);
        cpa16(sb + KQL + so, Ql_g + go);
    }
    attn_kvload(sb, 1, bh, 0, Kh_g, Kl_g, Vh_g, Vl_g, tid);
    CP_COMMIT();
    CP_WAIT(0);
    __syncthreads();

    uint32_t qfh[4][4], qfl[4][4];
    #pragma unroll
    for (int kk = 0; kk < 4; kk++) {
        uint32_t addr = (uint32_t)(((wm * 16 + a_r) * AVROW + kk * 16 + a_k) * 2);
        ldsm4(qfh[kk], sb + KQH + addr);
        ldsm4(qfl[kk], sb + KQL + addr);
    }
    __syncthreads();

    float O[8][4];
    #pragma unroll
    for (int j = 0; j < 8; j++)
        #pragma unroll
        for (int v = 0; v < 4; v++) O[j][v] = 0.0f;
    float m0 = -3.0e38f, m1 = -3.0e38f, l0 = 0.0f, l1 = 0.0f;

    for (int t = 0; t < ntiles; t++) {
        const int rt = (t + 1) & 1;
        if (t + 1 < ntiles) {
            attn_kvload(sb, t & 1, bh, (t + 1) * 64,
                        Kh_g, Kl_g, Vh_g, Vl_g, tid);
            CP_COMMIT();
        }
        const uint32_t st = sb + (uint32_t)rt * ASTAGE;
        const int kbase = t * 64;

        float acc[8][4];
        #pragma unroll
        for (int j = 0; j < 8; j++)
            #pragma unroll
            for (int v = 0; v < 4; v++) acc[j][v] = 0.0f;

        #pragma unroll
        for (int kk = 0; kk < 4; kk++) {
            #pragma unroll
            for (int nb = 0; nb < 4; nb++) {
                uint32_t addr = (uint32_t)(((nb * 16 + b_r) * AVROW
                                            + kk * 16 + b_k) * 2);
                uint32_t rh[4], rl[4];
                ldsm4(rh, st + KKH + addr);
                ldsm4(rl, st + KKL + addr);
                mma_bf16(acc[2 * nb],     qfh[kk], &rh[0]);
                mma_bf16(acc[2 * nb + 1], qfh[kk], &rh[2]);
                mma_bf16(acc[2 * nb],     qfh[kk], &rl[0]);
                mma_bf16(acc[2 * nb + 1], qfh[kk], &rl[2]);
                mma_bf16(acc[2 * nb],     qfl[kk], &rh[0]);
                mma_bf16(acc[2 * nb + 1], qfl[kk], &rh[2]);
            }
        }

        float rmax0 = -3.0e38f, rmax1 = -3.0e38f;
        #pragma unroll
        for (int j = 0; j < 8; j++) {
            int c = kbase + j * 8 + c0base;
            bool v0 = (c < nc), v1 = (c + 1 < nc);
            acc[j][0] = v0 ? acc[j][0] : -1000.0f;
            acc[j][1] = v1 ? acc[j][1] : -1000.0f;
            acc[j][2] = v0 ? acc[j][2] : -1000.0f;
            acc[j][3] = v1 ? acc[j][3] : -1000.0f;
            rmax0 = fmaxf(rmax0, fmaxf(acc[j][0], acc[j][1]));
            rmax1 = fmaxf(rmax1, fmaxf(acc[j][2], acc[j][3]));
        }
        rmax0 = fmaxf(rmax0, __shfl_xor_sync(0xffffffffu, rmax0, 1));
        rmax0 = fmaxf(rmax0, __shfl_xor_sync(0xffffffffu, rmax0, 2));
        rmax1 = fmaxf(rmax1, __shfl_xor_sync(0xffffffffu, rmax1, 1));
        rmax1 = fmaxf(rmax1, __shfl_xor_sync(0xffffffffu, rmax1, 2));

        float mn0 = fmaxf(m0, rmax0), mn1 = fmaxf(m1, rmax1);
        float al0 = __expf(m0 - mn0), al1 = __expf(m1 - mn1);
        m0 = mn0; m1 = mn1;

        float rs0 = 0.0f, rs1 = 0.0f;
        #pragma unroll
        for (int j = 0; j < 8; j++) {
            acc[j][0] = __expf(acc[j][0] - mn0); rs0 += acc[j][0];
            acc[j][1] = __expf(acc[j][1] - mn0); rs0 += acc[j][1];
            acc[j][2] = __expf(acc[j][2] - mn1); rs1 += acc[j][2];
            acc[j][3] = __expf(acc[j][3] - mn1); rs1 += acc[j][3];
        }
        rs0 += __shfl_xor_sync(0xffffffffu, rs0, 1);
        rs0 += __shfl_xor_sync(0xffffffffu, rs0, 2);
        rs1 += __shfl_xor_sync(0xffffffffu, rs1, 1);
        rs1 += __shfl_xor_sync(0xffffffffu, rs1, 2);
        l0 = l0 * al0 + rs0;
        l1 = l1 * al1 + rs1;
        #pragma unroll
        for (int j = 0; j < 8; j++) {
            O[j][0] *= al0; O[j][1] *= al0;
            O[j][2] *= al1; O[j][3] *= al1;
        }

        #pragma unroll
        for (int kk = 0; kk < 4; kk++) {
            uint32_t pah[4], pal[4];
            split2(acc[2 * kk][0],     acc[2 * kk][1],     pah[0], pal[0]);
            split2(acc[2 * kk][2],     acc[2 * kk][3],     pah[1], pal[1]);
            split2(acc[2 * kk + 1][0], acc[2 * kk + 1][1], pah[2], pal[2]);
            split2(acc[2 * kk + 1][2], acc[2 * kk + 1][3], pah[3], pal[3]);
            #pragma unroll
            for (int nb = 0; nb < 4; nb++) {
                uint32_t addr = (uint32_t)(((kk * 16 + ((lane >> 3) & 1) * 8
                                             + (lane & 7)) * AVROW
                                            + nb * 16 + (lane >> 4) * 8) * 2);
                uint32_t vh4[4], vl4[4];
                ldsm4t(vh4, st + KVH + addr);
                ldsm4t(vl4, st + KVL + addr);
                mma_bf16(O[2 * nb],     pah, &vh4[0]);
                mma_bf16(O[2 * nb + 1], pah, &vh4[2]);
                mma_bf16(O[2 * nb],     pah, &vl4[0]);
                mma_bf16(O[2 * nb + 1], pah, &vl4[2]);
                mma_bf16(O[2 * nb],     pal, &vh4[0]);
                mma_bf16(O[2 * nb + 1], pal, &vh4[2]);
            }
        }

        if (t + 1 < ntiles) CP_WAIT(0);
        __syncthreads();
    }

    const float inv0 = 1.0f / l0, inv1 = 1.0f / l1;
    const int trow = t0 + wm * 16 + (lane >> 2);
    const size_t ob0 = ((size_t)(b * TT + trow)) * DD + h * 64;
    const size_t ob1 = ob0 + (size_t)8 * DD;
    #pragma unroll
    for (int jn = 0; jn < 8; jn++) {
        int c = jn * 8 + c0base;
        uint32_t hi, lo;
        split2(O[jn][0] * inv0, O[jn][1] * inv0, hi, lo);
        *(uint32_t*)(Oh_g + ob0 + c) = hi;
        *(uint32_t*)(Ol_g + ob0 + c) = lo;
        split2(O[jn][2] * inv1, O[jn][3] * inv1, hi, lo);
        *(uint32_t*)(Oh_g + ob1 + c) = hi;
        *(uint32_t*)(Ol_g + ob1 + c) = lo;
    }
}

// ---------------------------------------------------------------------------
extern "C" void kernel_launch(void* const* d_in, const int* in_sizes, int n_in,
                              void* d_out, int out_size)
{
    const float* x     = (const float*)d_in[0];
    const int*   mask  = (const int*)  d_in[1];
    const float* W_qkv = (const float*)d_in[2];
    const float* b_qkv = (const float*)d_in[3];
    const float* W_out = (const float*)d_in[4];
    const float* b_out = (const float*)d_in[5];
    float* out = (float*)d_out;

    __nv_bfloat16 *wqh, *wql, *woh, *wol, *xh, *xl;
    __nv_bfloat16 *qh, *ql, *kh, *kl, *vh, *vl;
    int *toklist, *ncomp;
    cudaGetSymbolAddress((void**)&wqh, g_wqkv_h);
    cudaGetSymbolAddress((void**)&wql, g_wqkv_l);
    cudaGetSymbolAddress((void**)&woh, g_wout_h);
    cudaGetSymbolAddress((void**)&wol, g_wout_l);
    cudaGetSymbolAddress((void**)&xh,  g_act_h);
    cudaGetSymbolAddress((void**)&xl,  g_act_l);
    cudaGetSymbolAddress((void**)&qh,  g_q_h);
    cudaGetSymbolAddress((void**)&ql,  g_q_l);
    cudaGetSymbolAddress((void**)&kh,  g_k_h);
    cudaGetSymbolAddress((void**)&kl,  g_k_l);
    cudaGetSymbolAddress((void**)&vh,  g_v_h);
    cudaGetSymbolAddress((void**)&vl,  g_v_l);
    cudaGetSymbolAddress((void**)&toklist, g_toklist);
    cudaGetSymbolAddress((void**)&ncomp,   g_ncomp);

    cudaFuncSetAttribute(gemm_tc_kernel,
                         cudaFuncAttributeMaxDynamicSharedMemorySize, GEMM_SMEM);
    cudaFuncSetAttribute(gemm_kv_kernel,
                         cudaFuncAttributeMaxDynamicSharedMemorySize, GEMM_SMEM);
    cudaFuncSetAttribute(attn_tc_kernel,
                         cudaFuncAttributeMaxDynamicSharedMemorySize, ATTN_SMEM);

    // 0) Fused pre-split + mask scan (toklist/ncomp)
    conv_all_kernel<<<8196, 256>>>(W_qkv, W_out, x, mask,
                                   wqh, wql, woh, wol, xh, xl, toklist, ncomp);

    // 1a) Q projection (dense, N=1024): scatter head-major, pre-scaled
    gemm_tc_kernel<<<dim3(DD / 128, MTOT / 128), 256, GEMM_SMEM>>>(
        xh, xl, wqh, wql, b_qkv, nullptr, MTOT, DD, DD, qh, ql);

    // 1b) K/V projection over compacted tokens only (N=2048)
    gemm_kv_kernel<<<dim3(N_KV / 128, BB * 16), 256, GEMM_SMEM>>>(
        xh, xl, wqh + (size_t)DD * DD, wql + (size_t)DD * DD,
        b_qkv + DD, kh, kl, vh, vl, toklist, ncomp);

    // 2) Flash attention over compacted K/V
    attn_tc_kernel<<<dim3(TT / 128, BB * HH), 256, ATTN_SMEM>>>(
        qh, ql, kh, kl, vh, vl, ncomp, xh, xl);

    // 3) Output projection
    gemm_tc_kernel<<<dim3(DD / 128, MTOT / 128), 256, GEMM_SMEM>>>(
        xh, xl, woh, wol, b_out, out, MTOT, DD, DD, nullptr, nullptr);
}

// round 13
// speedup vs baseline: 1.4945x; 1.0251x over previous
#include <cuda_runtime.h>
#include <cuda_bf16.h>
#include <cstdint>
#include <math.h>

// Problem constants
#define BB 4
#define TT 2048
#define DD 1024
#define HH 16
#define DH 64
#define MTOT (BB*TT)        // 8192
#define N_QKV (3*DD)        // 3072
#define N_KV  (2*DD)        // 2048

// Scratch (device globals: allocation-guard safe)
__device__ __nv_bfloat16 g_wqkv_h[(size_t)N_QKV * DD];  // W_qkv^T hi  [3072,1024]
__device__ __nv_bfloat16 g_wqkv_l[(size_t)N_QKV * DD];
__device__ __nv_bfloat16 g_wout_h[(size_t)DD * DD];     // W_out^T hi  [1024,1024]
__device__ __nv_bfloat16 g_wout_l[(size_t)DD * DD];
__device__ __nv_bfloat16 g_act_h[(size_t)MTOT * DD];    // activation hi [M,K]
__device__ __nv_bfloat16 g_act_l[(size_t)MTOT * DD];
// Q/K/V head-major [B*H][T][DH], hi/lo split (Q pre-scaled by 0.125)
// K/V are COMPACTED: only unmasked keys, per batch.
#define QKV_ELEMS ((size_t)BB * HH * TT * DH)
__device__ __nv_bfloat16 g_q_h[QKV_ELEMS];
__device__ __nv_bfloat16 g_q_l[QKV_ELEMS];
__device__ __nv_bfloat16 g_k_h[QKV_ELEMS];
__device__ __nv_bfloat16 g_k_l[QKV_ELEMS];
__device__ __nv_bfloat16 g_v_h[QKV_ELEMS];
__device__ __nv_bfloat16 g_v_l[QKV_ELEMS];
// mask compaction: counts and compacted-index -> token map
__device__ int g_toklist[BB * TT];
__device__ int g_ncomp[BB];

// ---------------------------------------------------------------------------
// sm_80-portable PTX helpers
// ---------------------------------------------------------------------------
__device__ __forceinline__ uint32_t smem_u32(const void* p) {
    uint32_t a;
    asm("{ .reg .u64 t; cvta.to.shared.u64 t, %1; cvt.u32.u64 %0, t; }"
        : "=r"(a) : "l"(p));
    return a;
}
__device__ __forceinline__ void cpa16(uint32_t dst, const void* src) {
    asm volatile("cp.async.cg.shared.global [%0], [%1], 16;"
                 :: "r"(dst), "l"(src));
}
#define CP_COMMIT() asm volatile("cp.async.commit_group;" ::: "memory")
#define CP_WAIT(n)  asm volatile("cp.async.wait_group %0;" :: "n"(n) : "memory")

__device__ __forceinline__ void ldsm4(uint32_t* r, uint32_t addr) {
    asm volatile("ldmatrix.sync.aligned.m8n8.x4.shared.b16 {%0,%1,%2,%3}, [%4];"
                 : "=r"(r[0]), "=r"(r[1]), "=r"(r[2]), "=r"(r[3]) : "r"(addr));
}
__device__ __forceinline__ void ldsm4t(uint32_t* r, uint32_t addr) {
    asm volatile("ldmatrix.sync.aligned.m8n8.x4.trans.shared.b16 {%0,%1,%2,%3}, [%4];"
                 : "=r"(r[0]), "=r"(r[1]), "=r"(r[2]), "=r"(r[3]) : "r"(addr));
}
__device__ __forceinline__ void mma_bf16(float* d, const uint32_t* a,
                                         const uint32_t* b) {
    asm volatile("mma.sync.aligned.m16n8k16.row.col.f32.bf16.bf16.f32 "
                 "{%0,%1,%2,%3}, {%4,%5,%6,%7}, {%8,%9}, {%0,%1,%2,%3};"
                 : "+f"(d[0]), "+f"(d[1]), "+f"(d[2]), "+f"(d[3])
                 : "r"(a[0]), "r"(a[1]), "r"(a[2]), "r"(a[3]),
                   "r"(b[0]), "r"(b[1]));
}
// split pair of fp32 -> bf16x2 hi + bf16x2 lo
__device__ __forceinline__ void split2(float x, float y, uint32_t& hi, uint32_t& lo) {
    __nv_bfloat162 h, l;
    h.x = __float2bfloat16(x);
    h.y = __float2bfloat16(y);
    l.x = __float2bfloat16(x - __bfloat162float(h.x));
    l.y = __float2bfloat16(y - __bfloat162float(h.y));
    hi = *(uint32_t*)&h;
    lo = *(uint32_t*)&l;
}

// ---------------------------------------------------------------------------
// Fused conversion kernel: pre-split weights + activations + mask scan
// (blocks 8192..8195 build toklist/ncomp).
// ---------------------------------------------------------------------------
__device__ __forceinline__ void conv_w_body(
    const float* __restrict__ W, __nv_bfloat16* __restrict__ Wh,
    __nv_bfloat16* __restrict__ Wl, int K, int N, int bx, int by, int tid)
{
    __shared__ float t[32][33];
    const int n0 = bx * 32, k0 = by * 32;
    const int tx = tid & 31, ty = tid >> 5;
    #pragma unroll
    for (int i = 0; i < 32; i += 8)
        t[ty + i][tx] = W[(size_t)(k0 + ty + i) * N + n0 + tx];
    __syncthreads();
    #pragma unroll
    for (int i = 0; i < 32; i += 8) {
        int n = ty + i;
        float v = t[tx][n];
        __nv_bfloat16 h = __float2bfloat16(v);
        __nv_bfloat16 l = __float2bfloat16(v - __bfloat162float(h));
        size_t o = (size_t)(n0 + n) * K + k0 + tx;
        Wh[o] = h;
        Wl[o] = l;
    }
}

__global__ __launch_bounds__(256)
void conv_all_kernel(const float* __restrict__ W_qkv,
                     const float* __restrict__ W_out,
                     const float* __restrict__ x,
                     const int* __restrict__ mask,
                     __nv_bfloat16* __restrict__ wqh, __nv_bfloat16* __restrict__ wql,
                     __nv_bfloat16* __restrict__ woh, __nv_bfloat16* __restrict__ wol,
                     __nv_bfloat16* __restrict__ xh,  __nv_bfloat16* __restrict__ xl,
                     int* __restrict__ toklist, int* __restrict__ ncomp)
{
    const int bid = blockIdx.x, tid = threadIdx.x;
    if (bid < 3072) {
        conv_w_body(W_qkv, wqh, wql, DD, N_QKV, bid % 96, bid / 96, tid);
    } else if (bid < 4096) {
        const int id = bid - 3072;
        conv_w_body(W_out, woh, wol, DD, DD, id % 32, id / 32, tid);
    } else if (bid < 8192) {
        const int base = (bid - 4096) * 512 + tid;
        #pragma unroll
        for (int u = 0; u < 2; u++) {
            int idx = base + u * 256;
            float4 v = ((const float4*)x)[idx];
            uint32_t h0, h1, l0, l1;
            split2(v.x, v.y, h0, l0);
            split2(v.z, v.w, h1, l1);
            ((uint32_t*)xh)[idx * 2 + 0] = h0;
            ((uint32_t*)xh)[idx * 2 + 1] = h1;
            ((uint32_t*)xl)[idx * 2 + 0] = l0;
            ((uint32_t*)xl)[idx * 2 + 1] = l1;
        }
    } else {
        // mask prefix-scan for batch bb: build toklist (compact idx -> token)
        const int bb = bid - 8192;
        const int* mrow = mask + bb * TT;
        __shared__ int part[256];
        int loc[8];
        int s = 0;
        const int base = tid * 8;
        #pragma unroll
        for (int i = 0; i < 8; i++) {
            loc[i] = s;
            s += (mrow[base + i] != 0) ? 1 : 0;
        }
        part[tid] = s;
        __syncthreads();
        for (int off = 1; off < 256; off <<= 1) {
            int v = (tid >= off) ? part[tid - off] : 0;
            __syncthreads();
            part[tid] += v;
            __syncthreads();
        }
        const int excl = (tid == 0) ? 0 : part[tid - 1];
        #pragma unroll
        for (int i = 0; i < 8; i++)
            if (mrow[base + i] != 0)
                toklist[bb * TT + excl + loc[i]] = base + i;
        if (tid == 255) ncomp[bb] = part[255];
    }
}

// ---------------------------------------------------------------------------
// Shared GEMM machinery: BK=32, 2-stage cp.async, 80B smem rows, 2 CTAs/SM.
// ---------------------------------------------------------------------------
#define GBK 32
#define AROW 40
#define MAT_BYTES (128 * AROW * 2)
#define ST_A_H 0
#define ST_A_L (1 * MAT_BYTES)
#define ST_B_H (2 * MAT_BYTES)
#define ST_B_L (3 * MAT_BYTES)
#define STAGE_B (4 * MAT_BYTES)
#define GEMM_SMEM (2 * STAGE_B)

__device__ __forceinline__ void gemm_compute_chunk(
    uint32_t st, int wm, int wn,
    int a_r, int a_k, int b_r, int b_k,
    float acc[4][4][4])
{
    #pragma unroll
    for (int ks = 0; ks < 2; ks++) {
        const int k0 = ks * 16;
        uint32_t bh2[4][2], bl2[4][2];
        #pragma unroll
        for (int half = 0; half < 2; half++) {
            uint32_t baddr = (uint32_t)((wn * 32 + half * 16 + b_r) * 80
                                        + (k0 + b_k) * 2);
            uint32_t r[4];
            ldsm4(r, st + ST_B_H + baddr);
            bh2[half * 2 + 0][0] = r[0]; bh2[half * 2 + 0][1] = r[1];
            bh2[half * 2 + 1][0] = r[2]; bh2[half * 2 + 1][1] = r[3];
            ldsm4(r, st + ST_B_L + baddr);
            bl2[half * 2 + 0][0] = r[0]; bl2[half * 2 + 0][1] = r[1];
            bl2[half * 2 + 1][0] = r[2]; bl2[half * 2 + 1][1] = r[3];
        }
        #pragma unroll
        for (int mi = 0; mi < 4; mi++) {
            uint32_t aaddr = (uint32_t)((wm * 64 + mi * 16 + a_r) * 80
                                        + (k0 + a_k) * 2);
            uint32_t ah[4], al[4];
            ldsm4(ah, st + ST_A_H + aaddr);
            ldsm4(al, st + ST_A_L + aaddr);
            #pragma unroll
            for (int nf = 0; nf < 4; nf++) mma_bf16(acc[mi][nf], ah, bh2[nf]);
            #pragma unroll
            for (int nf = 0; nf < 4; nf++) mma_bf16(acc[mi][nf], ah, bl2[nf]);
            #pragma unroll
            for (int nf = 0; nf < 4; nf++) mma_bf16(acc[mi][nf], al, bh2[nf]);
        }
    }
}

__device__ __forceinline__ void gemm_load_chunk_rows(
    uint32_t stBase,
    const __nv_bfloat16* __restrict__ Ah, const __nv_bfloat16* __restrict__ Al,
    const __nv_bfloat16* __restrict__ Bh, const __nv_bfloat16* __restrict__ Bl,
    size_t a_row_off, size_t b_row_off, int k0, int tid)
{
    const int kc = (tid & 1) * 16;
    const int row = tid >> 1;
    const uint32_t so = (uint32_t)(row * 80 + kc * 2);
    cpa16(stBase + ST_A_H + so,      Ah + a_row_off + k0);
    cpa16(stBase + ST_A_H + so + 16, Ah + a_row_off + k0 + 8);
    cpa16(stBase + ST_A_L + so,      Al + a_row_off + k0);
    cpa16(stBase + ST_A_L + so + 16, Al + a_row_off + k0 + 8);
    cpa16(stBase + ST_B_H + so,      Bh + b_row_off + k0);
    cpa16(stBase + ST_B_H + so + 16, Bh + b_row_off + k0 + 8);
    cpa16(stBase + ST_B_L + so,      Bl + b_row_off + k0);
    cpa16(stBase + ST_B_L + so + 16, Bl + b_row_off + k0 + 8);
}

// full pipelined mainloop (K = DD), accumulators in-place
__device__ __forceinline__ void gemm_core(
    uint32_t sb,
    const __nv_bfloat16* __restrict__ Ah, const __nv_bfloat16* __restrict__ Al,
    const __nv_bfloat16* __restrict__ Bh, const __nv_bfloat16* __restrict__ Bl,
    size_t a_off, size_t b_off, int tid, int wm, int wn,
    int a_r, int a_k, int b_r, int b_k, float acc[4][4][4])
{
    const int NCH = DD / GBK;
    gemm_load_chunk_rows(sb, Ah, Al, Bh, Bl, a_off, b_off, 0, tid);
    CP_COMMIT();
    for (int c = 0; c < NCH; c++) {
        const uint32_t st = sb + (uint32_t)(c & 1) * STAGE_B;
        if (c + 1 < NCH) {
            gemm_load_chunk_rows(sb + (uint32_t)((c + 1) & 1) * STAGE_B,
                                 Ah, Al, Bh, Bl, a_off, b_off,
                                 (c + 1) * GBK, tid);
            CP_COMMIT();
            CP_WAIT(1);
        } else {
            CP_WAIT(0);
        }
        __syncthreads();
        gemm_compute_chunk(st, wm, wn, a_r, a_k, b_r, b_k, acc);
        __syncthreads();
    }
}

// ---------------------------------------------------------------------------
// Fused projection kernel: blocks [0,512) = Q (dense, scatter pre-scaled);
// blocks [512,1536) = K/V over compacted tokens only.
// ---------------------------------------------------------------------------
__global__ __launch_bounds__(256, 2)
void gemm_proj_kernel(const __nv_bfloat16* __restrict__ Ah,
                      const __nv_bfloat16* __restrict__ Al,
                      const __nv_bfloat16* __restrict__ Wh,
                      const __nv_bfloat16* __restrict__ Wl,
                      const float* __restrict__ bias,
                      __nv_bfloat16* qh, __nv_bfloat16* ql,
                      __nv_bfloat16* kh, __nv_bfloat16* kl,
                      __nv_bfloat16* vh, __nv_bfloat16* vl,
                      const int* __restrict__ toklist,
                      const int* __restrict__ ncomp)
{
    extern __shared__ char smraw[];
    const uint32_t sb = smem_u32(smraw);
    const int tid = threadIdx.x, wid = tid >> 5, lane = tid & 31;
    const int wm = wid >> 2, wn = wid & 3;
    const int a_r = (lane & 7) + ((lane >> 3) & 1) * 8;
    const int a_k = (lane >> 4) * 8;
    const int b_r = (lane & 7) + (lane >> 4) * 8;
    const int b_k = ((lane >> 3) & 1) * 8;
    const int row = tid >> 1, kc = (tid & 1) * 16;

    float acc[4][4][4];
    #pragma unroll
    for (int i = 0; i < 4; i++)
        #pragma unroll
        for (int j = 0; j < 4; j++)
            #pragma unroll
            for (int v = 0; v < 4; v++) acc[i][j][v] = 0.0f;

    if (blockIdx.x < 512) {
        // ---- Q path ----
        const int qid = blockIdx.x;
        const int bn0 = (qid & 7) * 128;
        const int bm0 = (qid >> 3) * 128;
        const size_t a_off = (size_t)(bm0 + row) * DD + kc;
        const size_t b_off = (size_t)(bn0 + row) * DD + kc;
        gemm_core(sb, Ah, Al, Wh, Wl, a_off, b_off,
                  tid, wm, wn, a_r, a_k, b_r, b_k, acc);

        #pragma unroll
        for (int mi = 0; mi < 4; mi++) {
            const int orow = bm0 + wm * 64 + mi * 16 + (lane >> 2);
            #pragma unroll
            for (int nf = 0; nf < 4; nf++) {
                const int col = bn0 + wn * 32 + nf * 8 + (lane & 3) * 2;
                const float b0 = bias[col], b1 = bias[col + 1];
                float v0 = acc[mi][nf][0] + b0, v1 = acc[mi][nf][1] + b1;
                float v2 = acc[mi][nf][2] + b0, v3 = acc[mi][nf][3] + b1;
                const int hh  = (col >> 6) & 15;
                const int d   = col & 63;
                const int bb  = orow >> 11;
                const int trow = orow & 2047;
                size_t dst = (((size_t)(bb * 16 + hh)) * TT + trow) * 64 + d;
                uint32_t hi, lo;
                split2(v0 * 0.125f, v1 * 0.125f, hi, lo);
                *(uint32_t*)(qh + dst) = hi;
                *(uint32_t*)(ql + dst) = lo;
                split2(v2 * 0.125f, v3 * 0.125f, hi, lo);
                *(uint32_t*)(qh + dst + 8 * 64) = hi;
                *(uint32_t*)(ql + dst + 8 * 64) = lo;
            }
        }
    } else {
        // ---- KV path (compacted tokens) ----
        const int kvid = blockIdx.x - 512;
        const int bn0 = (kvid & 15) * 128;       // 0..1920 over N_KV
        const int yy  = kvid >> 4;               // 0..63
        const int bb  = yy >> 4;
        const int tile = yy & 15;
        const int nc = ncomp[bb];
        if (tile * 128 >= nc) return;

        int ci = tile * 128 + row;
        if (ci >= nc) ci = nc - 1;
        const int token = toklist[bb * TT + ci];
        const size_t a_off = (size_t)(bb * TT + token) * DD + kc;
        const size_t b_off = (size_t)(DD + bn0 + row) * DD + kc;  // W rows 1024+
        gemm_core(sb, Ah, Al, Wh, Wl, a_off, b_off,
                  tid, wm, wn, a_r, a_k, b_r, b_k, acc);

        #pragma unroll
        for (int mi = 0; mi < 4; mi++) {
            const int rin = wm * 64 + mi * 16 + (lane >> 2);
            const int crow0 = tile * 128 + rin;
            const int crow1 = crow0 + 8;
            #pragma unroll
            for (int nf = 0; nf < 4; nf++) {
                const int col = bn0 + wn * 32 + nf * 8 + (lane & 3) * 2;
                const float b0 = bias[DD + col], b1 = bias[DD + col + 1];
                float v0 = acc[mi][nf][0] + b0, v1 = acc[mi][nf][1] + b1;
                float v2 = acc[mi][nf][2] + b0, v3 = acc[mi][nf][3] + b1;
                __nv_bfloat16* H = (col < DD) ? kh : vh;
                __nv_bfloat16* L = (col < DD) ? kl : vl;
                const int hh = (col >> 6) & 15;
                const int d  = col & 63;
                const size_t hb = ((size_t)(bb * 16 + hh)) * TT;
                uint32_t hi, lo;
                if (crow0 < nc) {
                    size_t dst = (hb + crow0) * 64 + d;
                    split2(v0, v1, hi, lo);
                    *(uint32_t*)(H + dst) = hi;
                    *(uint32_t*)(L + dst) = lo;
                }
                if (crow1 < nc) {
                    size_t dst = (hb + crow1) * 64 + d;
                    split2(v2, v3, hi, lo);
                    *(uint32_t*)(H + dst) = hi;
                    *(uint32_t*)(L + dst) = lo;
                }
            }
        }
    }
}

// ---------------------------------------------------------------------------
// Out-projection GEMM (dense, plain epilogue)
// ---------------------------------------------------------------------------
__global__ __launch_bounds__(256, 2)
void gemm_tc_kernel(const __nv_bfloat16* __restrict__ Ah,
                    const __nv_bfloat16* __restrict__ Al,
                    const __nv_bfloat16* __restrict__ Bh,
                    const __nv_bfloat16* __restrict__ Bl,
                    const float* __restrict__ bias, float* __restrict__ C)
{
    extern __shared__ char smraw[];
    const uint32_t sb = smem_u32(smraw);
    const int tid = threadIdx.x, wid = tid >> 5, lane = tid & 31;
    const int bm0 = blockIdx.y * 128, bn0 = blockIdx.x * 128;
    const int wm = wid >> 2, wn = wid & 3;
    const int a_r = (lane & 7) + ((lane >> 3) & 1) * 8;
    const int a_k = (lane >> 4) * 8;
    const int b_r = (lane & 7) + (lane >> 4) * 8;
    const int b_k = ((lane >> 3) & 1) * 8;
    const int row = tid >> 1, kc = (tid & 1) * 16;
    const size_t a_off = (size_t)(bm0 + row) * DD + kc;
    const size_t b_off = (size_t)(bn0 + row) * DD + kc;

    float acc[4][4][4];
    #pragma unroll
    for (int i = 0; i < 4; i++)
        #pragma unroll
        for (int j = 0; j < 4; j++)
            #pragma unroll
            for (int v = 0; v < 4; v++) acc[i][j][v] = 0.0f;

    gemm_core(sb, Ah, Al, Bh, Bl, a_off, b_off,
              tid, wm, wn, a_r, a_k, b_r, b_k, acc);

    #pragma unroll
    for (int mi = 0; mi < 4; mi++) {
        const int orow = bm0 + wm * 64 + mi * 16 + (lane >> 2);
        #pragma unroll
        for (int nf = 0; nf < 4; nf++) {
            const int col = bn0 + wn * 32 + nf * 8 + (lane & 3) * 2;
            const float b0 = bias[col], b1 = bias[col + 1];
            float2 p0, p1;
            p0.x = acc[mi][nf][0] + b0; p0.y = acc[mi][nf][1] + b1;
            p1.x = acc[mi][nf][2] + b0; p1.y = acc[mi][nf][3] + b1;
            *(float2*)&C[(size_t)orow * DD + col]       = p0;
            *(float2*)&C[(size_t)(orow + 8) * DD + col] = p1;
        }
    }
}

// ---------------------------------------------------------------------------
// Tensor-core flash attention over COMPACTED K/V.
// Full tiles skip validity selects (fast path); only the tail tile masks.
// ---------------------------------------------------------------------------
#define AVROW 72                       // bf16 row stride (144 B)
#define KQH 0
#define KQL 18432
#define KKH 0
#define KKL 9216
#define KVH 18432
#define KVL 27648
#define ASTAGE 36864
#define ATTN_SMEM (2 * ASTAGE + 256)   // 73984

__device__ __forceinline__ void attn_kvload(
    uint32_t sb, int region, int bh, int n0,
    const __nv_bfloat16* __restrict__ Kh_g, const __nv_bfloat16* __restrict__ Kl_g,
    const __nv_bfloat16* __restrict__ Vh_g, const __nv_bfloat16* __restrict__ Vl_g,
    int tid)
{
    const uint32_t st = sb + (uint32_t)region * ASTAGE;
    const size_t gb = ((size_t)bh * TT + n0) * 64;
    #pragma unroll
    for (int u = 0; u < 2; u++) {
        int idx = tid * 2 + u;
        int row = idx >> 3, ch = idx & 7;
        uint32_t so = (uint32_t)(row * 144 + ch * 16);
        size_t go = gb + row * 64 + ch * 8;
        cpa16(st + KKH + so, Kh_g + go);
        cpa16(st + KKL + so, Kl_g + go);
        cpa16(st + KVH + so, Vh_g + go);
        cpa16(st + KVL + so, Vl_g + go);
    }
}

__global__ __launch_bounds__(256, 2)
void attn_tc_kernel(const __nv_bfloat16* __restrict__ Qh_g,
                    const __nv_bfloat16* __restrict__ Ql_g,
                    const __nv_bfloat16* __restrict__ Kh_g,
                    const __nv_bfloat16* __restrict__ Kl_g,
                    const __nv_bfloat16* __restrict__ Vh_g,
                    const __nv_bfloat16* __restrict__ Vl_g,
                    const int* __restrict__ ncomp,
                    __nv_bfloat16* __restrict__ Oh_g,
                    __nv_bfloat16* __restrict__ Ol_g)
{
    extern __shared__ char smraw[];
    const uint32_t sb = smem_u32(smraw);
    const int tid = threadIdx.x, wid = tid >> 5, lane = tid & 31;
    const int bh = blockIdx.y;
    const int b = bh >> 4, h = bh & 15;
    const int t0 = blockIdx.x * 128;
    const int wm = wid;

    const int a_r = (lane & 7) + ((lane >> 3) & 1) * 8;
    const int a_k = (lane >> 4) * 8;
    const int b_r = (lane & 7) + (lane >> 4) * 8;
    const int b_k = ((lane >> 3) & 1) * 8;
    const int c0base = (lane & 3) * 2;

    const int nc = ncomp[b];
    const int ntiles = (nc + 63) >> 6;

    const size_t qbase = ((size_t)bh * TT + t0) * 64;
    #pragma unroll
    for (int i = 0; i < 4; i++) {
        int f = tid + i * 256;
        int row = f >> 3, ch = f & 7;
        uint32_t so = (uint32_t)(row * 144 + ch * 16);
        size_t go = qbase + row * 64 + ch * 8;
        cpa16(sb + KQH + so, Qh_g + go);
        cpa16(sb + KQL + so, Ql_g + go);
    }
    attn_kvload(sb, 1, bh, 0, Kh_g, Kl_g, Vh_g, Vl_g, tid);
    CP_COMMIT();
    CP_WAIT(0);
    __syncthreads();

    uint32_t qfh[4][4], qfl[4][4];
    #pragma unroll
    for (int kk = 0; kk < 4; kk++) {
        uint32_t addr = (uint32_t)(((wm * 16 + a_r) * AVROW + kk * 16 + a_k) * 2);
        ldsm4(qfh[kk], sb + KQH + addr);
        ldsm4(qfl[kk], sb + KQL + addr);
    }
    __syncthreads();

    float O[8][4];
    #pragma unroll
    for (int j = 0; j < 8; j++)
        #pragma unroll
        for (int v = 0; v < 4; v++) O[j][v] = 0.0f;
    float m0 = -3.0e38f, m1 = -3.0e38f, l0 = 0.0f, l1 = 0.0f;

    for (int t = 0; t < ntiles; t++) {
        const int rt = (t + 1) & 1;
        if (t + 1 < ntiles) {
            attn_kvload(sb, t & 1, bh, (t + 1) * 64,
                        Kh_g, Kl_g, Vh_g, Vl_g, tid);
            CP_COMMIT();
        }
        const uint32_t st = sb + (uint32_t)rt * ASTAGE;
        const int kbase = t * 64;

        float acc[8][4];
        #pragma unroll
        for (int j = 0; j < 8; j++)
            #pragma unroll
            for (int v = 0; v < 4; v++) acc[j][v] = 0.0f;

        #pragma unroll
        for (int kk = 0; kk < 4; kk++) {
            #pragma unroll
            for (int nb = 0; nb < 4; nb++) {
                uint32_t addr = (uint32_t)(((nb * 16 + b_r) * AVROW
                                            + kk * 16 + b_k) * 2);
                uint32_t rh[4], rl[4];
                ldsm4(rh, st + KKH + addr);
                ldsm4(rl, st + KKL + addr);
                mma_bf16(acc[2 * nb],     qfh[kk], &rh[0]);
                mma_bf16(acc[2 * nb + 1], qfh[kk], &rh[2]);
                mma_bf16(acc[2 * nb],     qfh[kk], &rl[0]);
                mma_bf16(acc[2 * nb + 1], qfh[kk], &rl[2]);
                mma_bf16(acc[2 * nb],     qfl[kk], &rh[0]);
                mma_bf16(acc[2 * nb + 1], qfl[kk], &rh[2]);
            }
        }

        float rmax0 = -3.0e38f, rmax1 = -3.0e38f;
        if (kbase + 64 <= nc) {
            // fast path: all keys valid
            #pragma unroll
            for (int j = 0; j < 8; j++) {
                rmax0 = fmaxf(rmax0, fmaxf(acc[j][0], acc[j][1]));
                rmax1 = fmaxf(rmax1, fmaxf(acc[j][2], acc[j][3]));
            }
        } else {
            #pragma unroll
            for (int j = 0; j < 8; j++) {
                int c = kbase + j * 8 + c0base;
                bool v0 = (c < nc), v1 = (c + 1 < nc);
                acc[j][0] = v0 ? acc[j][0] : -1000.0f;
                acc[j][1] = v1 ? acc[j][1] : -1000.0f;
                acc[j][2] = v0 ? acc[j][2] : -1000.0f;
                acc[j][3] = v1 ? acc[j][3] : -1000.0f;
                rmax0 = fmaxf(rmax0, fmaxf(acc[j][0], acc[j][1]));
                rmax1 = fmaxf(rmax1, fmaxf(acc[j][2], acc[j][3]));
            }
        }
        rmax0 = fmaxf(rmax0, __shfl_xor_sync(0xffffffffu, rmax0, 1));
        rmax0 = fmaxf(rmax0, __shfl_xor_sync(0xffffffffu, rmax0, 2));
        rmax1 = fmaxf(rmax1, __shfl_xor_sync(0xffffffffu, rmax1, 1));
        rmax1 = fmaxf(rmax1, __shfl_xor_sync(0xffffffffu, rmax1, 2));

        float mn0 = fmaxf(m0, rmax0), mn1 = fmaxf(m1, rmax1);
        float al0 = __expf(m0 - mn0), al1 = __expf(m1 - mn1);
        m0 = mn0; m1 = mn1;

        float rs0 = 0.0f, rs1 = 0.0f;
        #pragma unroll
        for (int j = 0; j < 8; j++) {
            acc[j][0] = __expf(acc[j][0] - mn0); rs0 += acc[j][0];
            acc[j][1] = __expf(acc[j][1] - mn0); rs0 += acc[j][1];
            acc[j][2] = __expf(acc[j][2] - mn1); rs1 += acc[j][2];
            acc[j][3] = __expf(acc[j][3] - mn1); rs1 += acc[j][3];
        }
        rs0 += __shfl_xor_sync(0xffffffffu, rs0, 1);
        rs0 += __shfl_xor_sync(0xffffffffu, rs0, 2);
        rs1 += __shfl_xor_sync(0xffffffffu, rs1, 1);
        rs1 += __shfl_xor_sync(0xffffffffu, rs1, 2);
        l0 = l0 * al0 + rs0;
        l1 = l1 * al1 + rs1;
        #pragma unroll
        for (int j = 0; j < 8; j++) {
            O[j][0] *= al0; O[j][1] *= al0;
            O[j][2] *= al1; O[j][3] *= al1;
        }

        #pragma unroll
        for (int kk = 0; kk < 4; kk++) {
            uint32_t pah[4], pal[4];
            split2(acc[2 * kk][0],     acc[2 * kk][1],     pah[0], pal[0]);
            split2(acc[2 * kk][2],     acc[2 * kk][3],     pah[1], pal[1]);
            split2(acc[2 * kk + 1][0], acc[2 * kk + 1][1], pah[2], pal[2]);
            split2(acc[2 * kk + 1][2], acc[2 * kk + 1][3], pah[3], pal[3]);
            #pragma unroll
            for (int nb = 0; nb < 4; nb++) {
                uint32_t addr = (uint32_t)(((kk * 16 + ((lane >> 3) & 1) * 8
                                             + (lane & 7)) * AVROW
                                            + nb * 16 + (lane >> 4) * 8) * 2);
                uint32_t vh4[4], vl4[4];
                ldsm4t(vh4, st + KVH + addr);
                ldsm4t(vl4, st + KVL + addr);
                mma_bf16(O[2 * nb],     pah, &vh4[0]);
                mma_bf16(O[2 * nb + 1], pah, &vh4[2]);
                mma_bf16(O[2 * nb],     pah, &vl4[0]);
                mma_bf16(O[2 * nb + 1], pah, &vl4[2]);
                mma_bf16(O[2 * nb],     pal, &vh4[0]);
                mma_bf16(O[2 * nb + 1], pal, &vh4[2]);
            }
        }

        if (t + 1 < ntiles) CP_WAIT(0);
        __syncthreads();
    }

    const float inv0 = 1.0f / l0, inv1 = 1.0f / l1;
    const int trow = t0 + wm * 16 + (lane >> 2);
    const size_t ob0 = ((size_t)(b * TT + trow)) * DD + h * 64;
    const size_t ob1 = ob0 + (size_t)8 * DD;
    #pragma unroll
    for (int jn = 0; jn < 8; jn++) {
        int c = jn * 8 + c0base;
        uint32_t hi, lo;
        split2(O[jn][0] * inv0, O[jn][1] * inv0, hi, lo);
        *(uint32_t*)(Oh_g + ob0 + c) = hi;
        *(uint32_t*)(Ol_g + ob0 + c) = lo;
        split2(O[jn][2] * inv1, O[jn][3] * inv1, hi, lo);
        *(uint32_t*)(Oh_g + ob1 + c) = hi;
        *(uint32_t*)(Ol_g + ob1 + c) = lo;
    }
}

// ---------------------------------------------------------------------------
extern "C" void kernel_launch(void* const* d_in, const int* in_sizes, int n_in,
                              void* d_out, int out_size)
{
    const float* x     = (const float*)d_in[0];
    const int*   mask  = (const int*)  d_in[1];
    const float* W_qkv = (const float*)d_in[2];
    const float* b_qkv = (const float*)d_in[3];
    const float* W_out = (const float*)d_in[4];
    const float* b_out = (const float*)d_in[5];
    float* out = (float*)d_out;

    __nv_bfloat16 *wqh, *wql, *woh, *wol, *xh, *xl;
    __nv_bfloat16 *qh, *ql, *kh, *kl, *vh, *vl;
    int *toklist, *ncomp;
    cudaGetSymbolAddress((void**)&wqh, g_wqkv_h);
    cudaGetSymbolAddress((void**)&wql, g_wqkv_l);
    cudaGetSymbolAddress((void**)&woh, g_wout_h);
    cudaGetSymbolAddress((void**)&wol, g_wout_l);
    cudaGetSymbolAddress((void**)&xh,  g_act_h);
    cudaGetSymbolAddress((void**)&xl,  g_act_l);
    cudaGetSymbolAddress((void**)&qh,  g_q_h);
    cudaGetSymbolAddress((void**)&ql,  g_q_l);
    cudaGetSymbolAddress((void**)&kh,  g_k_h);
    cudaGetSymbolAddress((void**)&kl,  g_k_l);
    cudaGetSymbolAddress((void**)&vh,  g_v_h);
    cudaGetSymbolAddress((void**)&vl,  g_v_l);
    cudaGetSymbolAddress((void**)&toklist, g_toklist);
    cudaGetSymbolAddress((void**)&ncomp,   g_ncomp);

    cudaFuncSetAttribute(gemm_proj_kernel,
                         cudaFuncAttributeMaxDynamicSharedMemorySize, GEMM_SMEM);
    cudaFuncSetAttribute(gemm_tc_kernel,
                         cudaFuncAttributeMaxDynamicSharedMemorySize, GEMM_SMEM);
    cudaFuncSetAttribute(attn_tc_kernel,
                         cudaFuncAttributeMaxDynamicSharedMemorySize, ATTN_SMEM);

    // 0) Fused pre-split + mask scan (toklist/ncomp)
    conv_all_kernel<<<8196, 256>>>(W_qkv, W_out, x, mask,
                                   wqh, wql, woh, wol, xh, xl, toklist, ncomp);

    // 1) Fused Q + K/V projection (Q dense-scatter; K/V compacted)
    gemm_proj_kernel<<<1536, 256, GEMM_SMEM>>>(
        xh, xl, wqh, wql, b_qkv,
        qh, ql, kh, kl, vh, vl, toklist, ncomp);

    // 2) Flash attention over compacted K/V
    attn_tc_kernel<<<dim3(TT / 128, BB * HH), 256, ATTN_SMEM>>>(
        qh, ql, kh, kl, vh, vl, ncomp, xh, xl);

    // 3) Output projection
    gemm_tc_kernel<<<dim3(DD / 128, MTOT / 128), 256, GEMM_SMEM>>>(
        xh, xl, woh, wol, b_out, out);
}

// round 14
// speedup vs baseline: 2.1012x; 1.4060x over previous
#include <cuda_runtime.h>
#include <cuda_fp16.h>
#include <cstdint>
#include <math.h>

// Problem constants
#define BB 4
#define TT 2048
#define DD 1024
#define HH 16
#define DH 64
#define MTOT (BB*TT)        // 8192
#define N_QKV (3*DD)        // 3072
#define N_KV  (2*DD)        // 2048

// Scratch (device globals: allocation-guard safe). fp16, B-side split hi/lo.
__device__ __half g_wqkv_h[(size_t)N_QKV * DD];  // W_qkv^T hi  [3072,1024]
__device__ __half g_wqkv_l[(size_t)N_QKV * DD];
__device__ __half g_wout_h[(size_t)DD * DD];     // W_out^T hi
__device__ __half g_wout_l[(size_t)DD * DD];
__device__ __half g_act[(size_t)MTOT * DD];      // activation SINGLE fp16 [M,K]
#define QKV_ELEMS ((size_t)BB * HH * TT * DH)
__device__ __half g_q[QKV_ELEMS];                // Q single (pre-scaled 1/8)
__device__ __half g_k_h[QKV_ELEMS];              // K hi/lo (compacted)
__device__ __half g_k_l[QKV_ELEMS];
__device__ __half g_v_h[QKV_ELEMS];              // V hi/lo (compacted)
__device__ __half g_v_l[QKV_ELEMS];
// mask compaction: counts and compacted-index -> token map
__device__ int g_toklist[BB * TT];
__device__ int g_ncomp[BB];

// ---------------------------------------------------------------------------
// sm_80-portable PTX helpers
// ---------------------------------------------------------------------------
__device__ __forceinline__ uint32_t smem_u32(const void* p) {
    uint32_t a;
    asm("{ .reg .u64 t; cvta.to.shared.u64 t, %1; cvt.u32.u64 %0, t; }"
        : "=r"(a) : "l"(p));
    return a;
}
__device__ __forceinline__ void cpa16(uint32_t dst, const void* src) {
    asm volatile("cp.async.cg.shared.global [%0], [%1], 16;"
                 :: "r"(dst), "l"(src));
}
#define CP_COMMIT() asm volatile("cp.async.commit_group;" ::: "memory")
#define CP_WAIT(n)  asm volatile("cp.async.wait_group %0;" :: "n"(n) : "memory")

__device__ __forceinline__ void ldsm4(uint32_t* r, uint32_t addr) {
    asm volatile("ldmatrix.sync.aligned.m8n8.x4.shared.b16 {%0,%1,%2,%3}, [%4];"
                 : "=r"(r[0]), "=r"(r[1]), "=r"(r[2]), "=r"(r[3]) : "r"(addr));
}
__device__ __forceinline__ void ldsm4t(uint32_t* r, uint32_t addr) {
    asm volatile("ldmatrix.sync.aligned.m8n8.x4.trans.shared.b16 {%0,%1,%2,%3}, [%4];"
                 : "=r"(r[0]), "=r"(r[1]), "=r"(r[2]), "=r"(r[3]) : "r"(addr));
}
__device__ __forceinline__ void mma_f16(float* d, const uint32_t* a,
                                        const uint32_t* b) {
    asm volatile("mma.sync.aligned.m16n8k16.row.col.f32.f16.f16.f32 "
                 "{%0,%1,%2,%3}, {%4,%5,%6,%7}, {%8,%9}, {%0,%1,%2,%3};"
                 : "+f"(d[0]), "+f"(d[1]), "+f"(d[2]), "+f"(d[3])
                 : "r"(a[0]), "r"(a[1]), "r"(a[2]), "r"(a[3]),
                   "r"(b[0]), "r"(b[1]));
}
// split pair of fp32 -> f16x2 hi + f16x2 lo
__device__ __forceinline__ void split2h(float x, float y, uint32_t& hi, uint32_t& lo) {
    __half2 h, l;
    h.x = __float2half(x);
    h.y = __float2half(y);
    l.x = __float2half(x - __half2float(h.x));
    l.y = __float2half(y - __half2float(h.y));
    hi = *(uint32_t*)&h;
    lo = *(uint32_t*)&l;
}
__device__ __forceinline__ uint32_t pack2h(float x, float y) {
    __half2 h;
    h.x = __float2half(x);
    h.y = __float2half(y);
    return *(uint32_t*)&h;
}

// ---------------------------------------------------------------------------
// Fused conversion kernel: weights split h/l, activations single, mask scan.
// ---------------------------------------------------------------------------
__device__ __forceinline__ void conv_w_body(
    const float* __restrict__ W, __half* __restrict__ Wh,
    __half* __restrict__ Wl, int K, int N, int bx, int by, int tid)
{
    __shared__ float t[32][33];
    const int n0 = bx * 32, k0 = by * 32;
    const int tx = tid & 31, ty = tid >> 5;
    #pragma unroll
    for (int i = 0; i < 32; i += 8)
        t[ty + i][tx] = W[(size_t)(k0 + ty + i) * N + n0 + tx];
    __syncthreads();
    #pragma unroll
    for (int i = 0; i < 32; i += 8) {
        int n = ty + i;
        float v = t[tx][n];
        __half h = __float2half(v);
        __half l = __float2half(v - __half2float(h));
        size_t o = (size_t)(n0 + n) * K + k0 + tx;
        Wh[o] = h;
        Wl[o] = l;
    }
}

__global__ __launch_bounds__(256)
void conv_all_kernel(const float* __restrict__ W_qkv,
                     const float* __restrict__ W_out,
                     const float* __restrict__ x,
                     const int* __restrict__ mask,
                     __half* __restrict__ wqh, __half* __restrict__ wql,
                     __half* __restrict__ woh, __half* __restrict__ wol,
                     __half* __restrict__ xs,
                     int* __restrict__ toklist, int* __restrict__ ncomp)
{
    const int bid = blockIdx.x, tid = threadIdx.x;
    if (bid < 3072) {
        conv_w_body(W_qkv, wqh, wql, DD, N_QKV, bid % 96, bid / 96, tid);
    } else if (bid < 4096) {
        const int id = bid - 3072;
        conv_w_body(W_out, woh, wol, DD, DD, id % 32, id / 32, tid);
    } else if (bid < 8192) {
        const int base = (bid - 4096) * 512 + tid;
        #pragma unroll
        for (int u = 0; u < 2; u++) {
            int idx = base + u * 256;
            float4 v = ((const float4*)x)[idx];
            ((uint32_t*)xs)[idx * 2 + 0] = pack2h(v.x, v.y);
            ((uint32_t*)xs)[idx * 2 + 1] = pack2h(v.z, v.w);
        }
    } else {
        const int bb = bid - 8192;
        const int* mrow = mask + bb * TT;
        __shared__ int part[256];
        int loc[8];
        int s = 0;
        const int base = tid * 8;
        #pragma unroll
        for (int i = 0; i < 8; i++) {
            loc[i] = s;
            s += (mrow[base + i] != 0) ? 1 : 0;
        }
        part[tid] = s;
        __syncthreads();
        for (int off = 1; off < 256; off <<= 1) {
            int v = (tid >= off) ? part[tid - off] : 0;
            __syncthreads();
            part[tid] += v;
            __syncthreads();
        }
        const int excl = (tid == 0) ? 0 : part[tid - 1];
        #pragma unroll
        for (int i = 0; i < 8; i++)
            if (mrow[base + i] != 0)
                toklist[bb * TT + excl + loc[i]] = base + i;
        if (tid == 255) ncomp[bb] = part[255];
    }
}

// ---------------------------------------------------------------------------
// GEMM machinery: A single fp16, B split h/l. BK=32, 2-stage, 80B rows.
// ---------------------------------------------------------------------------
#define GBK 32
#define MATB (128 * 80)                // 10240 bytes per matrix tile
#define ST_A   0
#define ST_B_H (1 * MATB)
#define ST_B_L (2 * MATB)
#define STAGE_B (3 * MATB)             // 30720
#define GEMM_SMEM (2 * STAGE_B)        // 61440

__device__ __forceinline__ void gemm_compute_chunk(
    uint32_t st, int wm, int wn,
    int a_r, int a_k, int b_r, int b_k,
    float acc[4][4][4])
{
    #pragma unroll
    for (int ks = 0; ks < 2; ks++) {
        const int k0 = ks * 16;
        uint32_t bh2[4][2], bl2[4][2];
        #pragma unroll
        for (int half = 0; half < 2; half++) {
            uint32_t baddr = (uint32_t)((wn * 32 + half * 16 + b_r) * 80
                                        + (k0 + b_k) * 2);
            uint32_t r[4];
            ldsm4(r, st + ST_B_H + baddr);
            bh2[half * 2 + 0][0] = r[0]; bh2[half * 2 + 0][1] = r[1];
            bh2[half * 2 + 1][0] = r[2]; bh2[half * 2 + 1][1] = r[3];
            ldsm4(r, st + ST_B_L + baddr);
            bl2[half * 2 + 0][0] = r[0]; bl2[half * 2 + 0][1] = r[1];
            bl2[half * 2 + 1][0] = r[2]; bl2[half * 2 + 1][1] = r[3];
        }
        #pragma unroll
        for (int mi = 0; mi < 4; mi++) {
            uint32_t aaddr = (uint32_t)((wm * 64 + mi * 16 + a_r) * 80
                                        + (k0 + a_k) * 2);
            uint32_t a4[4];
            ldsm4(a4, st + ST_A + aaddr);
            #pragma unroll
            for (int nf = 0; nf < 4; nf++) mma_f16(acc[mi][nf], a4, bh2[nf]);
            #pragma unroll
            for (int nf = 0; nf < 4; nf++) mma_f16(acc[mi][nf], a4, bl2[nf]);
        }
    }
}

__device__ __forceinline__ void gemm_load_chunk_rows(
    uint32_t stBase,
    const __half* __restrict__ A,
    const __half* __restrict__ Bh, const __half* __restrict__ Bl,
    size_t a_row_off, size_t b_row_off, int k0, int tid)
{
    const int kc = (tid & 1) * 16;
    const int row = tid >> 1;
    const uint32_t so = (uint32_t)(row * 80 + kc * 2);
    cpa16(stBase + ST_A + so,        A + a_row_off + k0);
    cpa16(stBase + ST_A + so + 16,   A + a_row_off + k0 + 8);
    cpa16(stBase + ST_B_H + so,      Bh + b_row_off + k0);
    cpa16(stBase + ST_B_H + so + 16, Bh + b_row_off + k0 + 8);
    cpa16(stBase + ST_B_L + so,      Bl + b_row_off + k0);
    cpa16(stBase + ST_B_L + so + 16, Bl + b_row_off + k0 + 8);
}

__device__ __forceinline__ void gemm_core(
    uint32_t sb,
    const __half* __restrict__ A,
    const __half* __restrict__ Bh, const __half* __restrict__ Bl,
    size_t a_off, size_t b_off, int tid, int wm, int wn,
    int a_r, int a_k, int b_r, int b_k, float acc[4][4][4])
{
    const int NCH = DD / GBK;
    gemm_load_chunk_rows(sb, A, Bh, Bl, a_off, b_off, 0, tid);
    CP_COMMIT();
    for (int c = 0; c < NCH; c++) {
        const uint32_t st = sb + (uint32_t)(c & 1) * STAGE_B;
        if (c + 1 < NCH) {
            gemm_load_chunk_rows(sb + (uint32_t)((c + 1) & 1) * STAGE_B,
                                 A, Bh, Bl, a_off, b_off, (c + 1) * GBK, tid);
            CP_COMMIT();
            CP_WAIT(1);
        } else {
            CP_WAIT(0);
        }
        __syncthreads();
        gemm_compute_chunk(st, wm, wn, a_r, a_k, b_r, b_k, acc);
        __syncthreads();
    }
}

// ---------------------------------------------------------------------------
// Fused projection kernel: blocks [0,512) = Q (dense, scatter pre-scaled);
// blocks [512,1536) = K/V over compacted tokens only (split h/l epilogue).
// ---------------------------------------------------------------------------
__global__ __launch_bounds__(256, 2)
void gemm_proj_kernel(const __half* __restrict__ A,
                      const __half* __restrict__ Wh,
                      const __half* __restrict__ Wl,
                      const float* __restrict__ bias,
                      __half* q_g,
                      __half* kh, __half* kl,
                      __half* vh, __half* vl,
                      const int* __restrict__ toklist,
                      const int* __restrict__ ncomp)
{
    extern __shared__ char smraw[];
    const uint32_t sb = smem_u32(smraw);
    const int tid = threadIdx.x, wid = tid >> 5, lane = tid & 31;
    const int wm = wid >> 2, wn = wid & 3;
    const int a_r = (lane & 7) + ((lane >> 3) & 1) * 8;
    const int a_k = (lane >> 4) * 8;
    const int b_r = (lane & 7) + (lane >> 4) * 8;
    const int b_k = ((lane >> 3) & 1) * 8;
    const int row = tid >> 1, kc = (tid & 1) * 16;

    float acc[4][4][4];
    #pragma unroll
    for (int i = 0; i < 4; i++)
        #pragma unroll
        for (int j = 0; j < 4; j++)
            #pragma unroll
            for (int v = 0; v < 4; v++) acc[i][j][v] = 0.0f;

    if (blockIdx.x < 512) {
        // ---- Q path ----
        const int qid = blockIdx.x;
        const int bn0 = (qid & 7) * 128;
        const int bm0 = (qid >> 3) * 128;
        const size_t a_off = (size_t)(bm0 + row) * DD + kc;
        const size_t b_off = (size_t)(bn0 + row) * DD + kc;
        gemm_core(sb, A, Wh, Wl, a_off, b_off,
                  tid, wm, wn, a_r, a_k, b_r, b_k, acc);

        #pragma unroll
        for (int mi = 0; mi < 4; mi++) {
            const int orow = bm0 + wm * 64 + mi * 16 + (lane >> 2);
            #pragma unroll
            for (int nf = 0; nf < 4; nf++) {
                const int col = bn0 + wn * 32 + nf * 8 + (lane & 3) * 2;
                const float b0 = bias[col], b1 = bias[col + 1];
                float v0 = acc[mi][nf][0] + b0, v1 = acc[mi][nf][1] + b1;
                float v2 = acc[mi][nf][2] + b0, v3 = acc[mi][nf][3] + b1;
                const int hh  = (col >> 6) & 15;
                const int d   = col & 63;
                const int bb  = orow >> 11;
                const int trow = orow & 2047;
                size_t dst = (((size_t)(bb * 16 + hh)) * TT + trow) * 64 + d;
                *(uint32_t*)(q_g + dst) = pack2h(v0 * 0.125f, v1 * 0.125f);
                *(uint32_t*)(q_g + dst + 8 * 64) = pack2h(v2 * 0.125f, v3 * 0.125f);
            }
        }
    } else {
        // ---- KV path (compacted tokens) ----
        const int kvid = blockIdx.x - 512;
        const int bn0 = (kvid & 15) * 128;       // over N_KV
        const int yy  = kvid >> 4;
        const int bb  = yy >> 4;
        const int tile = yy & 15;
        const int nc = ncomp[bb];
        if (tile * 128 >= nc) return;

        int ci = tile * 128 + row;
        if (ci >= nc) ci = nc - 1;
        const int token = toklist[bb * TT + ci];
        const size_t a_off = (size_t)(bb * TT + token) * DD + kc;
        const size_t b_off = (size_t)(DD + bn0 + row) * DD + kc;  // W rows 1024+
        gemm_core(sb, A, Wh, Wl, a_off, b_off,
                  tid, wm, wn, a_r, a_k, b_r, b_k, acc);

        #pragma unroll
        for (int mi = 0; mi < 4; mi++) {
            const int rin = wm * 64 + mi * 16 + (lane >> 2);
            const int crow0 = tile * 128 + rin;
            const int crow1 = crow0 + 8;
            #pragma unroll
            for (int nf = 0; nf < 4; nf++) {
                const int col = bn0 + wn * 32 + nf * 8 + (lane & 3) * 2;
                const float b0 = bias[DD + col], b1 = bias[DD + col + 1];
                float v0 = acc[mi][nf][0] + b0, v1 = acc[mi][nf][1] + b1;
                float v2 = acc[mi][nf][2] + b0, v3 = acc[mi][nf][3] + b1;
                __half* H = (col < DD) ? kh : vh;
                __half* L = (col < DD) ? kl : vl;
                const int hh = (col >> 6) & 15;
                const int d  = col & 63;
                const size_t hb = ((size_t)(bb * 16 + hh)) * TT;
                uint32_t hi, lo;
                if (crow0 < nc) {
                    size_t dst = (hb + crow0) * 64 + d;
                    split2h(v0, v1, hi, lo);
                    *(uint32_t*)(H + dst) = hi;
                    *(uint32_t*)(L + dst) = lo;
                }
                if (crow1 < nc) {
                    size_t dst = (hb + crow1) * 64 + d;
                    split2h(v2, v3, hi, lo);
                    *(uint32_t*)(H + dst) = hi;
                    *(uint32_t*)(L + dst) = lo;
                }
            }
        }
    }
}

// ---------------------------------------------------------------------------
// Out-projection GEMM (dense, plain epilogue). A single fp16.
// ---------------------------------------------------------------------------
__global__ __launch_bounds__(256, 2)
void gemm_tc_kernel(const __half* __restrict__ A,
                    const __half* __restrict__ Bh,
                    const __half* __restrict__ Bl,
                    const float* __restrict__ bias, float* __restrict__ C)
{
    extern __shared__ char smraw[];
    const uint32_t sb = smem_u32(smraw);
    const int tid = threadIdx.x, wid = tid >> 5, lane = tid & 31;
    const int bm0 = blockIdx.y * 128, bn0 = blockIdx.x * 128;
    const int wm = wid >> 2, wn = wid & 3;
    const int a_r = (lane & 7) + ((lane >> 3) & 1) * 8;
    const int a_k = (lane >> 4) * 8;
    const int b_r = (lane & 7) + (lane >> 4) * 8;
    const int b_k = ((lane >> 3) & 1) * 8;
    const int row = tid >> 1, kc = (tid & 1) * 16;
    const size_t a_off = (size_t)(bm0 + row) * DD + kc;
    const size_t b_off = (size_t)(bn0 + row) * DD + kc;

    float acc[4][4][4];
    #pragma unroll
    for (int i = 0; i < 4; i++)
        #pragma unroll
        for (int j = 0; j < 4; j++)
            #pragma unroll
            for (int v = 0; v < 4; v++) acc[i][j][v] = 0.0f;

    gemm_core(sb, A, Bh, Bl, a_off, b_off,
              tid, wm, wn, a_r, a_k, b_r, b_k, acc);

    #pragma unroll
    for (int mi = 0; mi < 4; mi++) {
        const int orow = bm0 + wm * 64 + mi * 16 + (lane >> 2);
        #pragma unroll
        for (int nf = 0; nf < 4; nf++) {
            const int col = bn0 + wn * 32 + nf * 8 + (lane & 3) * 2;
            const float b0 = bias[col], b1 = bias[col + 1];
            float2 p0, p1;
            p0.x = acc[mi][nf][0] + b0; p0.y = acc[mi][nf][1] + b1;
            p1.x = acc[mi][nf][2] + b0; p1.y = acc[mi][nf][3] + b1;
            *(float2*)&C[(size_t)orow * DD + col]       = p0;
            *(float2*)&C[(size_t)(orow + 8) * DD + col] = p1;
        }
    }
}

// ---------------------------------------------------------------------------
// Tensor-core flash attention over COMPACTED K/V.
// Q single fp16 (pre-scaled), K/V split h/l, P single fp16.
// Full tiles skip validity selects; only the tail tile masks.
// ---------------------------------------------------------------------------
#define AVROW 72                       // half row stride (144 B)
#define KQ  0                          // Q single: 128*144 = 18432 (region 0)
#define KKH 0
#define KKL 9216
#define KVH 18432
#define KVL 27648
#define ASTAGE 36864
#define ATTN_SMEM (2 * ASTAGE + 256)   // 73984

__device__ __forceinline__ void attn_kvload(
    uint32_t sb, int region, int bh, int n0,
    const __half* __restrict__ Kh_g, const __half* __restrict__ Kl_g,
    const __half* __restrict__ Vh_g, const __half* __restrict__ Vl_g,
    int tid)
{
    const uint32_t st = sb + (uint32_t)region * ASTAGE;
    const size_t gb = ((size_t)bh * TT + n0) * 64;
    #pragma unroll
    for (int u = 0; u < 2; u++) {
        int idx = tid * 2 + u;
        int row = idx >> 3, ch = idx & 7;
        uint32_t so = (uint32_t)(row * 144 + ch * 16);
        size_t go = gb + row * 64 + ch * 8;
        cpa16(st + KKH + so, Kh_g + go);
        cpa16(st + KKL + so, Kl_g + go);
        cpa16(st + KVH + so, Vh_g + go);
        cpa16(st + KVL + so, Vl_g + go);
    }
}

__global__ __launch_bounds__(256, 2)
void attn_tc_kernel(const __half* __restrict__ Q_g,
                    const __half* __restrict__ Kh_g,
                    const __half* __restrict__ Kl_g,
                    const __half* __restrict__ Vh_g,
                    const __half* __restrict__ Vl_g,
                    const int* __restrict__ ncomp,
                    __half* __restrict__ O_g)
{
    extern __shared__ char smraw[];
    const uint32_t sb = smem_u32(smraw);
    const int tid = threadIdx.x, wid = tid >> 5, lane = tid & 31;
    const int bh = blockIdx.y;
    const int b = bh >> 4, h = bh & 15;
    const int t0 = blockIdx.x * 128;
    const int wm = wid;

    const int a_r = (lane & 7) + ((lane >> 3) & 1) * 8;
    const int a_k = (lane >> 4) * 8;
    const int b_r = (lane & 7) + (lane >> 4) * 8;
    const int b_k = ((lane >> 3) & 1) * 8;
    const int c0base = (lane & 3) * 2;

    const int nc = ncomp[b];
    const int ntiles = (nc + 63) >> 6;

    // Q single -> region 0 start; KV tile 0 -> region 1
    const size_t qbase = ((size_t)bh * TT + t0) * 64;
    #pragma unroll
    for (int i = 0; i < 4; i++) {
        int f = tid + i * 256;
        int row = f >> 3, ch = f & 7;
        uint32_t so = (uint32_t)(row * 144 + ch * 16);
        cpa16(sb + KQ + so, Q_g + qbase + row * 64 + ch * 8);
    }
    attn_kvload(sb, 1, bh, 0, Kh_g, Kl_g, Vh_g, Vl_g, tid);
    CP_COMMIT();
    CP_WAIT(0);
    __syncthreads();

    uint32_t qf[4][4];
    #pragma unroll
    for (int kk = 0; kk < 4; kk++) {
        uint32_t addr = (uint32_t)(((wm * 16 + a_r) * AVROW + kk * 16 + a_k) * 2);
        ldsm4(qf[kk], sb + KQ + addr);
    }
    __syncthreads();

    float O[8][4];
    #pragma unroll
    for (int j = 0; j < 8; j++)
        #pragma unroll
        for (int v = 0; v < 4; v++) O[j][v] = 0.0f;
    float m0 = -3.0e38f, m1 = -3.0e38f, l0 = 0.0f, l1 = 0.0f;

    for (int t = 0; t < ntiles; t++) {
        const int rt = (t + 1) & 1;
        if (t + 1 < ntiles) {
            attn_kvload(sb, t & 1, bh, (t + 1) * 64,
                        Kh_g, Kl_g, Vh_g, Vl_g, tid);
            CP_COMMIT();
        }
        const uint32_t st = sb + (uint32_t)rt * ASTAGE;
        const int kbase = t * 64;

        float acc[8][4];
        #pragma unroll
        for (int j = 0; j < 8; j++)
            #pragma unroll
            for (int v = 0; v < 4; v++) acc[j][v] = 0.0f;

        #pragma unroll
        for (int kk = 0; kk < 4; kk++) {
            #pragma unroll
            for (int nb = 0; nb < 4; nb++) {
                uint32_t addr = (uint32_t)(((nb * 16 + b_r) * AVROW
                                            + kk * 16 + b_k) * 2);
                uint32_t rh[4], rl[4];
                ldsm4(rh, st + KKH + addr);
                ldsm4(rl, st + KKL + addr);
                mma_f16(acc[2 * nb],     qf[kk], &rh[0]);
                mma_f16(acc[2 * nb + 1], qf[kk], &rh[2]);
                mma_f16(acc[2 * nb],     qf[kk], &rl[0]);
                mma_f16(acc[2 * nb + 1], qf[kk], &rl[2]);
            }
        }

        float rmax0 = -3.0e38f, rmax1 = -3.0e38f;
        if (kbase + 64 <= nc) {
            #pragma unroll
            for (int j = 0; j < 8; j++) {
                rmax0 = fmaxf(rmax0, fmaxf(acc[j][0], acc[j][1]));
                rmax1 = fmaxf(rmax1, fmaxf(acc[j][2], acc[j][3]));
            }
        } else {
            #pragma unroll
            for (int j = 0; j < 8; j++) {
                int c = kbase + j * 8 + c0base;
                bool v0 = (c < nc), v1 = (c + 1 < nc);
                acc[j][0] = v0 ? acc[j][0] : -1000.0f;
                acc[j][1] = v1 ? acc[j][1] : -1000.0f;
                acc[j][2] = v0 ? acc[j][2] : -1000.0f;
                acc[j][3] = v1 ? acc[j][3] : -1000.0f;
                rmax0 = fmaxf(rmax0, fmaxf(acc[j][0], acc[j][1]));
                rmax1 = fmaxf(rmax1, fmaxf(acc[j][2], acc[j][3]));
            }
        }
        rmax0 = fmaxf(rmax0, __shfl_xor_sync(0xffffffffu, rmax0, 1));
        rmax0 = fmaxf(rmax0, __shfl_xor_sync(0xffffffffu, rmax0, 2));
        rmax1 = fmaxf(rmax1, __shfl_xor_sync(0xffffffffu, rmax1, 1));
        rmax1 = fmaxf(rmax1, __shfl_xor_sync(0xffffffffu, rmax1, 2));

        float mn0 = fmaxf(m0, rmax0), mn1 = fmaxf(m1, rmax1);
        float al0 = __expf(m0 - mn0), al1 = __expf(m1 - mn1);
        m0 = mn0; m1 = mn1;

        float rs0 = 0.0f, rs1 = 0.0f;
        #pragma unroll
        for (int j = 0; j < 8; j++) {
            acc[j][0] = __expf(acc[j][0] - mn0); rs0 += acc[j][0];
            acc[j][1] = __expf(acc[j][1] - mn0); rs0 += acc[j][1];
            acc[j][2] = __expf(acc[j][2] - mn1); rs1 += acc[j][2];
            acc[j][3] = __expf(acc[j][3] - mn1); rs1 += acc[j][3];
        }
        rs0 += __shfl_xor_sync(0xffffffffu, rs0, 1);
        rs0 += __shfl_xor_sync(0xffffffffu, rs0, 2);
        rs1 += __shfl_xor_sync(0xffffffffu, rs1, 1);
        rs1 += __shfl_xor_sync(0xffffffffu, rs1, 2);
        l0 = l0 * al0 + rs0;
        l1 = l1 * al1 + rs1;
        #pragma unroll
        for (int j = 0; j < 8; j++) {
            O[j][0] *= al0; O[j][1] *= al0;
            O[j][2] *= al1; O[j][3] *= al1;
        }

        #pragma unroll
        for (int kk = 0; kk < 4; kk++) {
            uint32_t pa[4];
            pa[0] = pack2h(acc[2 * kk][0],     acc[2 * kk][1]);
            pa[1] = pack2h(acc[2 * kk][2],     acc[2 * kk][3]);
            pa[2] = pack2h(acc[2 * kk + 1][0], acc[2 * kk + 1][1]);
            pa[3] = pack2h(acc[2 * kk + 1][2], acc[2 * kk + 1][3]);
            #pragma unroll
            for (int nb = 0; nb < 4; nb++) {
                uint32_t addr = (uint32_t)(((kk * 16 + ((lane >> 3) & 1) * 8
                                             + (lane & 7)) * AVROW
                                            + nb * 16 + (lane >> 4) * 8) * 2);
                uint32_t vh4[4], vl4[4];
                ldsm4t(vh4, st + KVH + addr);
                ldsm4t(vl4, st + KVL + addr);
                mma_f16(O[2 * nb],     pa, &vh4[0]);
                mma_f16(O[2 * nb + 1], pa, &vh4[2]);
                mma_f16(O[2 * nb],     pa, &vl4[0]);
                mma_f16(O[2 * nb + 1], pa, &vl4[2]);
            }
        }

        if (t + 1 < ntiles) CP_WAIT(0);
        __syncthreads();
    }

    const float inv0 = 1.0f / l0, inv1 = 1.0f / l1;
    const int trow = t0 + wm * 16 + (lane >> 2);
    const size_t ob0 = ((size_t)(b * TT + trow)) * DD + h * 64;
    const size_t ob1 = ob0 + (size_t)8 * DD;
    #pragma unroll
    for (int jn = 0; jn < 8; jn++) {
        int c = jn * 8 + c0base;
        *(uint32_t*)(O_g + ob0 + c) = pack2h(O[jn][0] * inv0, O[jn][1] * inv0);
        *(uint32_t*)(O_g + ob1 + c) = pack2h(O[jn][2] * inv1, O[jn][3] * inv1);
    }
}

// ---------------------------------------------------------------------------
extern "C" void kernel_launch(void* const* d_in, const int* in_sizes, int n_in,
                              void* d_out, int out_size)
{
    const float* x     = (const float*)d_in[0];
    const int*   mask  = (const int*)  d_in[1];
    const float* W_qkv = (const float*)d_in[2];
    const float* b_qkv = (const float*)d_in[3];
    const float* W_out = (const float*)d_in[4];
    const float* b_out = (const float*)d_in[5];
    float* out = (float*)d_out;

    __half *wqh, *wql, *woh, *wol, *xs;
    __half *qg, *kh, *kl, *vh, *vl;
    int *toklist, *ncomp;
    cudaGetSymbolAddress((void**)&wqh, g_wqkv_h);
    cudaGetSymbolAddress((void**)&wql, g_wqkv_l);
    cudaGetSymbolAddress((void**)&woh, g_wout_h);
    cudaGetSymbolAddress((void**)&wol, g_wout_l);
    cudaGetSymbolAddress((void**)&xs,  g_act);
    cudaGetSymbolAddress((void**)&qg,  g_q);
    cudaGetSymbolAddress((void**)&kh,  g_k_h);
    cudaGetSymbolAddress((void**)&kl,  g_k_l);
    cudaGetSymbolAddress((void**)&vh,  g_v_h);
    cudaGetSymbolAddress((void**)&vl,  g_v_l);
    cudaGetSymbolAddress((void**)&toklist, g_toklist);
    cudaGetSymbolAddress((void**)&ncomp,   g_ncomp);

    cudaFuncSetAttribute(gemm_proj_kernel,
                         cudaFuncAttributeMaxDynamicSharedMemorySize, GEMM_SMEM);
    cudaFuncSetAttribute(gemm_tc_kernel,
                         cudaFuncAttributeMaxDynamicSharedMemorySize, GEMM_SMEM);
    cudaFuncSetAttribute(attn_tc_kernel,
                         cudaFuncAttributeMaxDynamicSharedMemorySize, ATTN_SMEM);

    // 0) Fused pre-split (fp16) + mask scan
    conv_all_kernel<<<8196, 256>>>(W_qkv, W_out, x, mask,
                                   wqh, wql, woh, wol, xs, toklist, ncomp);

    // 1) Fused Q + K/V projection
    gemm_proj_kernel<<<1536, 256, GEMM_SMEM>>>(
        xs, wqh, wql, b_qkv, qg, kh, kl, vh, vl, toklist, ncomp);

    // 2) Flash attention over compacted K/V (writes O single fp16 -> xs)
    attn_tc_kernel<<<dim3(TT / 128, BB * HH), 256, ATTN_SMEM>>>(
        qg, kh, kl, vh, vl, ncomp, xs);

    // 3) Output projection
    gemm_tc_kernel<<<dim3(DD / 128, MTOT / 128), 256, GEMM_SMEM>>>(
        xs, woh, wol, b_out, out);
}

// round 15
// speedup vs baseline: 3.1665x; 1.5070x over previous
#include <cuda_runtime.h>
#include <cuda_fp16.h>
#include <cstdint>
#include <math.h>

// Problem constants
#define BB 4
#define TT 2048
#define DD 1024
#define HH 16
#define DH 64
#define MTOT (BB*TT)        // 8192
#define N_QKV (3*DD)        // 3072
#define N_KV  (2*DD)        // 2048

// Scratch (device globals: allocation-guard safe). ALL single fp16.
__device__ __half g_wqkv[(size_t)N_QKV * DD];    // W_qkv^T [3072,1024]
__device__ __half g_wout[(size_t)DD * DD];       // W_out^T
__device__ __half g_act[(size_t)MTOT * DD];      // activations [M,K]
#define QKV_ELEMS ((size_t)BB * HH * TT * DH)
__device__ __half g_q[QKV_ELEMS];                // Q (pre-scaled 1/8)
__device__ __half g_k[QKV_ELEMS];                // K (compacted)
__device__ __half g_v[QKV_ELEMS];                // V (compacted)
// mask compaction: counts and compacted-index -> token map
__device__ int g_toklist[BB * TT];
__device__ int g_ncomp[BB];

// ---------------------------------------------------------------------------
// sm_80-portable PTX helpers
// ---------------------------------------------------------------------------
__device__ __forceinline__ uint32_t smem_u32(const void* p) {
    uint32_t a;
    asm("{ .reg .u64 t; cvta.to.shared.u64 t, %1; cvt.u32.u64 %0, t; }"
        : "=r"(a) : "l"(p));
    return a;
}
__device__ __forceinline__ void cpa16(uint32_t dst, const void* src) {
    asm volatile("cp.async.cg.shared.global [%0], [%1], 16;"
                 :: "r"(dst), "l"(src));
}
#define CP_COMMIT() asm volatile("cp.async.commit_group;" ::: "memory")
#define CP_WAIT(n)  asm volatile("cp.async.wait_group %0;" :: "n"(n) : "memory")

__device__ __forceinline__ void ldsm4(uint32_t* r, uint32_t addr) {
    asm volatile("ldmatrix.sync.aligned.m8n8.x4.shared.b16 {%0,%1,%2,%3}, [%4];"
                 : "=r"(r[0]), "=r"(r[1]), "=r"(r[2]), "=r"(r[3]) : "r"(addr));
}
__device__ __forceinline__ void ldsm4t(uint32_t* r, uint32_t addr) {
    asm volatile("ldmatrix.sync.aligned.m8n8.x4.trans.shared.b16 {%0,%1,%2,%3}, [%4];"
                 : "=r"(r[0]), "=r"(r[1]), "=r"(r[2]), "=r"(r[3]) : "r"(addr));
}
__device__ __forceinline__ void mma_f16(float* d, const uint32_t* a,
                                        const uint32_t* b) {
    asm volatile("mma.sync.aligned.m16n8k16.row.col.f32.f16.f16.f32 "
                 "{%0,%1,%2,%3}, {%4,%5,%6,%7}, {%8,%9}, {%0,%1,%2,%3};"
                 : "+f"(d[0]), "+f"(d[1]), "+f"(d[2]), "+f"(d[3])
                 : "r"(a[0]), "r"(a[1]), "r"(a[2]), "r"(a[3]),
                   "r"(b[0]), "r"(b[1]));
}
__device__ __forceinline__ uint32_t pack2h(float x, float y) {
    __half2 h;
    h.x = __float2half(x);
    h.y = __float2half(y);
    return *(uint32_t*)&h;
}

// ---------------------------------------------------------------------------
// Fused conversion kernel: weights + activations to fp16, mask scan.
// ---------------------------------------------------------------------------
__device__ __forceinline__ void conv_w_body(
    const float* __restrict__ W, __half* __restrict__ Wt,
    int K, int N, int bx, int by, int tid)
{
    __shared__ float t[32][33];
    const int n0 = bx * 32, k0 = by * 32;
    const int tx = tid & 31, ty = tid >> 5;
    #pragma unroll
    for (int i = 0; i < 32; i += 8)
        t[ty + i][tx] = W[(size_t)(k0 + ty + i) * N + n0 + tx];
    __syncthreads();
    #pragma unroll
    for (int i = 0; i < 32; i += 8) {
        int n = ty + i;
        Wt[(size_t)(n0 + n) * K + k0 + tx] = __float2half(t[tx][n]);
    }
}

__global__ __launch_bounds__(256)
void conv_all_kernel(const float* __restrict__ W_qkv,
                     const float* __restrict__ W_out,
                     const float* __restrict__ x,
                     const int* __restrict__ mask,
                     __half* __restrict__ wq, __half* __restrict__ wo,
                     __half* __restrict__ xs,
                     int* __restrict__ toklist, int* __restrict__ ncomp)
{
    const int bid = blockIdx.x, tid = threadIdx.x;
    if (bid < 3072) {
        conv_w_body(W_qkv, wq, DD, N_QKV, bid % 96, bid / 96, tid);
    } else if (bid < 4096) {
        const int id = bid - 3072;
        conv_w_body(W_out, wo, DD, DD, id % 32, id / 32, tid);
    } else if (bid < 8192) {
        const int base = (bid - 4096) * 512 + tid;
        #pragma unroll
        for (int u = 0; u < 2; u++) {
            int idx = base + u * 256;
            float4 v = ((const float4*)x)[idx];
            ((uint32_t*)xs)[idx * 2 + 0] = pack2h(v.x, v.y);
            ((uint32_t*)xs)[idx * 2 + 1] = pack2h(v.z, v.w);
        }
    } else {
        const int bb = bid - 8192;
        const int* mrow = mask + bb * TT;
        __shared__ int part[256];
        int loc[8];
        int s = 0;
        const int base = tid * 8;
        #pragma unroll
        for (int i = 0; i < 8; i++) {
            loc[i] = s;
            s += (mrow[base + i] != 0) ? 1 : 0;
        }
        part[tid] = s;
        __syncthreads();
        for (int off = 1; off < 256; off <<= 1) {
            int v = (tid >= off) ? part[tid - off] : 0;
            __syncthreads();
            part[tid] += v;
            __syncthreads();
        }
        const int excl = (tid == 0) ? 0 : part[tid - 1];
        #pragma unroll
        for (int i = 0; i < 8; i++)
            if (mrow[base + i] != 0)
                toklist[bb * TT + excl + loc[i]] = base + i;
        if (tid == 255) ncomp[bb] = part[255];
    }
}

// ---------------------------------------------------------------------------
// GEMM machinery: single fp16 A and B. BK=32, 2-stage, 80B rows.
// ---------------------------------------------------------------------------
#define GBK 32
#define MATB (128 * 80)                // 10240 bytes per matrix tile
#define ST_A  0
#define ST_B  MATB
#define STAGE_B (2 * MATB)             // 20480
#define GEMM_SMEM (2 * STAGE_B)        // 40960

__device__ __forceinline__ void gemm_compute_chunk(
    uint32_t st, int wm, int wn,
    int a_r, int a_k, int b_r, int b_k,
    float acc[4][4][4])
{
    #pragma unroll
    for (int ks = 0; ks < 2; ks++) {
        const int k0 = ks * 16;
        uint32_t bf[4][2];
        #pragma unroll
        for (int half = 0; half < 2; half++) {
            uint32_t baddr = (uint32_t)((wn * 32 + half * 16 + b_r) * 80
                                        + (k0 + b_k) * 2);
            uint32_t r[4];
            ldsm4(r, st + ST_B + baddr);
            bf[half * 2 + 0][0] = r[0]; bf[half * 2 + 0][1] = r[1];
            bf[half * 2 + 1][0] = r[2]; bf[half * 2 + 1][1] = r[3];
        }
        #pragma unroll
        for (int mi = 0; mi < 4; mi++) {
            uint32_t aaddr = (uint32_t)((wm * 64 + mi * 16 + a_r) * 80
                                        + (k0 + a_k) * 2);
            uint32_t a4[4];
            ldsm4(a4, st + ST_A + aaddr);
            #pragma unroll
            for (int nf = 0; nf < 4; nf++) mma_f16(acc[mi][nf], a4, bf[nf]);
        }
    }
}

__device__ __forceinline__ void gemm_load_chunk_rows(
    uint32_t stBase,
    const __half* __restrict__ A, const __half* __restrict__ B,
    size_t a_row_off, size_t b_row_off, int k0, int tid)
{
    const int kc = (tid & 1) * 16;
    const int row = tid >> 1;
    const uint32_t so = (uint32_t)(row * 80 + kc * 2);
    cpa16(stBase + ST_A + so,      A + a_row_off + k0);
    cpa16(stBase + ST_A + so + 16, A + a_row_off + k0 + 8);
    cpa16(stBase + ST_B + so,      B + b_row_off + k0);
    cpa16(stBase + ST_B + so + 16, B + b_row_off + k0 + 8);
}

__device__ __forceinline__ void gemm_core(
    uint32_t sb,
    const __half* __restrict__ A, const __half* __restrict__ B,
    size_t a_off, size_t b_off, int tid, int wm, int wn,
    int a_r, int a_k, int b_r, int b_k, float acc[4][4][4])
{
    const int NCH = DD / GBK;
    gemm_load_chunk_rows(sb, A, B, a_off, b_off, 0, tid);
    CP_COMMIT();
    for (int c = 0; c < NCH; c++) {
        const uint32_t st = sb + (uint32_t)(c & 1) * STAGE_B;
        if (c + 1 < NCH) {
            gemm_load_chunk_rows(sb + (uint32_t)((c + 1) & 1) * STAGE_B,
                                 A, B, a_off, b_off, (c + 1) * GBK, tid);
            CP_COMMIT();
            CP_WAIT(1);
        } else {
            CP_WAIT(0);
        }
        __syncthreads();
        gemm_compute_chunk(st, wm, wn, a_r, a_k, b_r, b_k, acc);
        __syncthreads();
    }
}

// ---------------------------------------------------------------------------
// Fused projection kernel: blocks [0,512) = Q (dense, scatter pre-scaled);
// blocks [512,1536) = K/V over compacted tokens only.
// ---------------------------------------------------------------------------
__global__ __launch_bounds__(256, 2)
void gemm_proj_kernel(const __half* __restrict__ A,
                      const __half* __restrict__ W,
                      const float* __restrict__ bias,
                      __half* q_g, __half* k_g, __half* v_g,
                      const int* __restrict__ toklist,
                      const int* __restrict__ ncomp)
{
    extern __shared__ char smraw[];
    const uint32_t sb = smem_u32(smraw);
    const int tid = threadIdx.x, wid = tid >> 5, lane = tid & 31;
    const int wm = wid >> 2, wn = wid & 3;
    const int a_r = (lane & 7) + ((lane >> 3) & 1) * 8;
    const int a_k = (lane >> 4) * 8;
    const int b_r = (lane & 7) + (lane >> 4) * 8;
    const int b_k = ((lane >> 3) & 1) * 8;
    const int row = tid >> 1, kc = (tid & 1) * 16;

    float acc[4][4][4];
    #pragma unroll
    for (int i = 0; i < 4; i++)
        #pragma unroll
        for (int j = 0; j < 4; j++)
            #pragma unroll
            for (int v = 0; v < 4; v++) acc[i][j][v] = 0.0f;

    if (blockIdx.x < 512) {
        // ---- Q path ----
        const int qid = blockIdx.x;
        const int bn0 = (qid & 7) * 128;
        const int bm0 = (qid >> 3) * 128;
        const size_t a_off = (size_t)(bm0 + row) * DD + kc;
        const size_t b_off = (size_t)(bn0 + row) * DD + kc;
        gemm_core(sb, A, W, a_off, b_off,
                  tid, wm, wn, a_r, a_k, b_r, b_k, acc);

        #pragma unroll
        for (int mi = 0; mi < 4; mi++) {
            const int orow = bm0 + wm * 64 + mi * 16 + (lane >> 2);
            #pragma unroll
            for (int nf = 0; nf < 4; nf++) {
                const int col = bn0 + wn * 32 + nf * 8 + (lane & 3) * 2;
                const float b0 = bias[col], b1 = bias[col + 1];
                float v0 = acc[mi][nf][0] + b0, v1 = acc[mi][nf][1] + b1;
                float v2 = acc[mi][nf][2] + b0, v3 = acc[mi][nf][3] + b1;
                const int hh  = (col >> 6) & 15;
                const int d   = col & 63;
                const int bb  = orow >> 11;
                const int trow = orow & 2047;
                size_t dst = (((size_t)(bb * 16 + hh)) * TT + trow) * 64 + d;
                *(uint32_t*)(q_g + dst) = pack2h(v0 * 0.125f, v1 * 0.125f);
                *(uint32_t*)(q_g + dst + 8 * 64) = pack2h(v2 * 0.125f, v3 * 0.125f);
            }
        }
    } else {
        // ---- KV path (compacted tokens) ----
        const int kvid = blockIdx.x - 512;
        const int bn0 = (kvid & 15) * 128;       // over N_KV
        const int yy  = kvid >> 4;
        const int bb  = yy >> 4;
        const int tile = yy & 15;
        const int nc = ncomp[bb];
        if (tile * 128 >= nc) return;

        int ci = tile * 128 + row;
        if (ci >= nc) ci = nc - 1;
        const int token = toklist[bb * TT + ci];
        const size_t a_off = (size_t)(bb * TT + token) * DD + kc;
        const size_t b_off = (size_t)(DD + bn0 + row) * DD + kc;  // W rows 1024+
        gemm_core(sb, A, W, a_off, b_off,
                  tid, wm, wn, a_r, a_k, b_r, b_k, acc);

        #pragma unroll
        for (int mi = 0; mi < 4; mi++) {
            const int rin = wm * 64 + mi * 16 + (lane >> 2);
            const int crow0 = tile * 128 + rin;
            const int crow1 = crow0 + 8;
            #pragma unroll
            for (int nf = 0; nf < 4; nf++) {
                const int col = bn0 + wn * 32 + nf * 8 + (lane & 3) * 2;
                const float b0 = bias[DD + col], b1 = bias[DD + col + 1];
                float v0 = acc[mi][nf][0] + b0, v1 = acc[mi][nf][1] + b1;
                float v2 = acc[mi][nf][2] + b0, v3 = acc[mi][nf][3] + b1;
                __half* G = (col < DD) ? k_g : v_g;
                const int hh = (col >> 6) & 15;
                const int d  = col & 63;
                const size_t hb = ((size_t)(bb * 16 + hh)) * TT;
                if (crow0 < nc)
                    *(uint32_t*)(G + (hb + crow0) * 64 + d) = pack2h(v0, v1);
                if (crow1 < nc)
                    *(uint32_t*)(G + (hb + crow1) * 64 + d) = pack2h(v2, v3);
            }
        }
    }
}

// ---------------------------------------------------------------------------
// Out-projection GEMM (dense, plain epilogue).
// ---------------------------------------------------------------------------
__global__ __launch_bounds__(256, 2)
void gemm_tc_kernel(const __half* __restrict__ A,
                    const __half* __restrict__ B,
                    const float* __restrict__ bias, float* __restrict__ C)
{
    extern __shared__ char smraw[];
    const uint32_t sb = smem_u32(smraw);
    const int tid = threadIdx.x, wid = tid >> 5, lane = tid & 31;
    const int bm0 = blockIdx.y * 128, bn0 = blockIdx.x * 128;
    const int wm = wid >> 2, wn = wid & 3;
    const int a_r = (lane & 7) + ((lane >> 3) & 1) * 8;
    const int a_k = (lane >> 4) * 8;
    const int b_r = (lane & 7) + (lane >> 4) * 8;
    const int b_k = ((lane >> 3) & 1) * 8;
    const int row = tid >> 1, kc = (tid & 1) * 16;
    const size_t a_off = (size_t)(bm0 + row) * DD + kc;
    const size_t b_off = (size_t)(bn0 + row) * DD + kc;

    float acc[4][4][4];
    #pragma unroll
    for (int i = 0; i < 4; i++)
        #pragma unroll
        for (int j = 0; j < 4; j++)
            #pragma unroll
            for (int v = 0; v < 4; v++) acc[i][j][v] = 0.0f;

    gemm_core(sb, A, B, a_off, b_off,
              tid, wm, wn, a_r, a_k, b_r, b_k, acc);

    #pragma unroll
    for (int mi = 0; mi < 4; mi++) {
        const int orow = bm0 + wm * 64 + mi * 16 + (lane >> 2);
        #pragma unroll
        for (int nf = 0; nf < 4; nf++) {
            const int col = bn0 + wn * 32 + nf * 8 + (lane & 3) * 2;
            const float b0 = bias[col], b1 = bias[col + 1];
            float2 p0, p1;
            p0.x = acc[mi][nf][0] + b0; p0.y = acc[mi][nf][1] + b1;
            p1.x = acc[mi][nf][2] + b0; p1.y = acc[mi][nf][3] + b1;
            *(float2*)&C[(size_t)orow * DD + col]       = p0;
            *(float2*)&C[(size_t)(orow + 8) * DD + col] = p1;
        }
    }
}

// ---------------------------------------------------------------------------
// Tensor-core flash attention over COMPACTED K/V. All operands single fp16.
// Full tiles skip validity selects; only the tail tile masks.
// ---------------------------------------------------------------------------
#define AVROW 72                       // half row stride (144 B)
#define KQ  0                          // Q: 128*144 = 18432 (region 0)
#define KK  0
#define KV  9216
#define ASTAGE 18432
#define ATTN_SMEM (2 * ASTAGE + 256)   // 37120

__device__ __forceinline__ void attn_kvload(
    uint32_t sb, int region, int bh, int n0,
    const __half* __restrict__ K_g, const __half* __restrict__ V_g, int tid)
{
    const uint32_t st = sb + (uint32_t)region * ASTAGE;
    const size_t gb = ((size_t)bh * TT + n0) * 64;
    #pragma unroll
    for (int u = 0; u < 2; u++) {
        int idx = tid * 2 + u;
        int row = idx >> 3, ch = idx & 7;
        uint32_t so = (uint32_t)(row * 144 + ch * 16);
        size_t go = gb + row * 64 + ch * 8;
        cpa16(st + KK + so, K_g + go);
        cpa16(st + KV + so, V_g + go);
    }
}

__global__ __launch_bounds__(256, 2)
void attn_tc_kernel(const __half* __restrict__ Q_g,
                    const __half* __restrict__ K_g,
                    const __half* __restrict__ V_g,
                    const int* __restrict__ ncomp,
                    __half* __restrict__ O_g)
{
    extern __shared__ char smraw[];
    const uint32_t sb = smem_u32(smraw);
    const int tid = threadIdx.x, wid = tid >> 5, lane = tid & 31;
    const int bh = blockIdx.y;
    const int b = bh >> 4, h = bh & 15;
    const int t0 = blockIdx.x * 128;
    const int wm = wid;

    const int a_r = (lane & 7) + ((lane >> 3) & 1) * 8;
    const int a_k = (lane >> 4) * 8;
    const int b_r = (lane & 7) + (lane >> 4) * 8;
    const int b_k = ((lane >> 3) & 1) * 8;
    const int c0base = (lane & 3) * 2;

    const int nc = ncomp[b];
    const int ntiles = (nc + 63) >> 6;

    // Q -> region 0; KV tile 0 -> region 1
    const size_t qbase = ((size_t)bh * TT + t0) * 64;
    #pragma unroll
    for (int i = 0; i < 4; i++) {
        int f = tid + i * 256;
        int row = f >> 3, ch = f & 7;
        uint32_t so = (uint32_t)(row * 144 + ch * 16);
        cpa16(sb + KQ + so, Q_g + qbase + row * 64 + ch * 8);
    }
    attn_kvload(sb, 1, bh, 0, K_g, V_g, tid);
    CP_COMMIT();
    CP_WAIT(0);
    __syncthreads();

    uint32_t qf[4][4];
    #pragma unroll
    for (int kk = 0; kk < 4; kk++) {
        uint32_t addr = (uint32_t)(((wm * 16 + a_r) * AVROW + kk * 16 + a_k) * 2);
        ldsm4(qf[kk], sb + KQ + addr);
    }
    __syncthreads();

    float O[8][4];
    #pragma unroll
    for (int j = 0; j < 8; j++)
        #pragma unroll
        for (int v = 0; v < 4; v++) O[j][v] = 0.0f;
    float m0 = -3.0e38f, m1 = -3.0e38f, l0 = 0.0f, l1 = 0.0f;

    for (int t = 0; t < ntiles; t++) {
        const int rt = (t + 1) & 1;
        if (t + 1 < ntiles) {
            attn_kvload(sb, t & 1, bh, (t + 1) * 64, K_g, V_g, tid);
            CP_COMMIT();
        }
        const uint32_t st = sb + (uint32_t)rt * ASTAGE;
        const int kbase = t * 64;

        float acc[8][4];
        #pragma unroll
        for (int j = 0; j < 8; j++)
            #pragma unroll
            for (int v = 0; v < 4; v++) acc[j][v] = 0.0f;

        #pragma unroll
        for (int kk = 0; kk < 4; kk++) {
            #pragma unroll
            for (int nb = 0; nb < 4; nb++) {
                uint32_t addr = (uint32_t)(((nb * 16 + b_r) * AVROW
                                            + kk * 16 + b_k) * 2);
                uint32_t rk[4];
                ldsm4(rk, st + KK + addr);
                mma_f16(acc[2 * nb],     qf[kk], &rk[0]);
                mma_f16(acc[2 * nb + 1], qf[kk], &rk[2]);
            }
        }

        float rmax0 = -3.0e38f, rmax1 = -3.0e38f;
        if (kbase + 64 <= nc) {
            #pragma unroll
            for (int j = 0; j < 8; j++) {
                rmax0 = fmaxf(rmax0, fmaxf(acc[j][0], acc[j][1]));
                rmax1 = fmaxf(rmax1, fmaxf(acc[j][2], acc[j][3]));
            }
        } else {
            #pragma unroll
            for (int j = 0; j < 8; j++) {
                int c = kbase + j * 8 + c0base;
                bool v0 = (c < nc), v1 = (c + 1 < nc);
                acc[j][0] = v0 ? acc[j][0] : -1000.0f;
                acc[j][1] = v1 ? acc[j][1] : -1000.0f;
                acc[j][2] = v0 ? acc[j][2] : -1000.0f;
                acc[j][3] = v1 ? acc[j][3] : -1000.0f;
                rmax0 = fmaxf(rmax0, fmaxf(acc[j][0], acc[j][1]));
                rmax1 = fmaxf(rmax1, fmaxf(acc[j][2], acc[j][3]));
            }
        }
        rmax0 = fmaxf(rmax0, __shfl_xor_sync(0xffffffffu, rmax0, 1));
        rmax0 = fmaxf(rmax0, __shfl_xor_sync(0xffffffffu, rmax0, 2));
        rmax1 = fmaxf(rmax1, __shfl_xor_sync(0xffffffffu, rmax1, 1));
        rmax1 = fmaxf(rmax1, __shfl_xor_sync(0xffffffffu, rmax1, 2));

        float mn0 = fmaxf(m0, rmax0), mn1 = fmaxf(m1, rmax1);
        float al0 = __expf(m0 - mn0), al1 = __expf(m1 - mn1);
        m0 = mn0; m1 = mn1;

        float rs0 = 0.0f, rs1 = 0.0f;
        #pragma unroll
        for (int j = 0; j < 8; j++) {
            acc[j][0] = __expf(acc[j][0] - mn0); rs0 += acc[j][0];
            acc[j][1] = __expf(acc[j][1] - mn0); rs0 += acc[j][1];
            acc[j][2] = __expf(acc[j][2] - mn1); rs1 += acc[j][2];
            acc[j][3] = __expf(acc[j][3] - mn1); rs1 += acc[j][3];
        }
        rs0 += __shfl_xor_sync(0xffffffffu, rs0, 1);
        rs0 += __shfl_xor_sync(0xffffffffu, rs0, 2);
        rs1 += __shfl_xor_sync(0xffffffffu, rs1, 1);
        rs1 += __shfl_xor_sync(0xffffffffu, rs1, 2);
        l0 = l0 * al0 + rs0;
        l1 = l1 * al1 + rs1;
        #pragma unroll
        for (int j = 0; j < 8; j++) {
            O[j][0] *= al0; O[j][1] *= al0;
            O[j][2] *= al1; O[j][3] *= al1;
        }

        #pragma unroll
        for (int kk = 0; kk < 4; kk++) {
            uint32_t pa[4];
            pa[0] = pack2h(acc[2 * kk][0],     acc[2 * kk][1]);
            pa[1] = pack2h(acc[2 * kk][2],     acc[2 * kk][3]);
            pa[2] = pack2h(acc[2 * kk + 1][0], acc[2 * kk + 1][1]);
            pa[3] = pack2h(acc[2 * kk + 1][2], acc[2 * kk + 1][3]);
            #pragma unroll
            for (int nb = 0; nb < 4; nb++) {
                uint32_t addr = (uint32_t)(((kk * 16 + ((lane >> 3) & 1) * 8
                                             + (lane & 7)) * AVROW
                                            + nb * 16 + (lane >> 4) * 8) * 2);
                uint32_t v4[4];
                ldsm4t(v4, st + KV + addr);
                mma_f16(O[2 * nb],     pa, &v4[0]);
                mma_f16(O[2 * nb + 1], pa, &v4[2]);
            }
        }

        if (t + 1 < ntiles) CP_WAIT(0);
        __syncthreads();
    }

    const float inv0 = 1.0f / l0, inv1 = 1.0f / l1;
    const int trow = t0 + wm * 16 + (lane >> 2);
    const size_t ob0 = ((size_t)(b * TT + trow)) * DD + h * 64;
    const size_t ob1 = ob0 + (size_t)8 * DD;
    #pragma unroll
    for (int jn = 0; jn < 8; jn++) {
        int c = jn * 8 + c0base;
        *(uint32_t*)(O_g + ob0 + c) = pack2h(O[jn][0] * inv0, O[jn][1] * inv0);
        *(uint32_t*)(O_g + ob1 + c) = pack2h(O[jn][2] * inv1, O[jn][3] * inv1);
    }
}

// ---------------------------------------------------------------------------
extern "C" void kernel_launch(void* const* d_in, const int* in_sizes, int n_in,
                              void* d_out, int out_size)
{
    const float* x     = (const float*)d_in[0];
    const int*   mask  = (const int*)  d_in[1];
    const float* W_qkv = (const float*)d_in[2];
    const float* b_qkv = (const float*)d_in[3];
    const float* W_out = (const float*)d_in[4];
    const float* b_out = (const float*)d_in[5];
    float* out = (float*)d_out;

    __half *wq, *wo, *xs, *qg, *kg, *vg;
    int *toklist, *ncomp;
    cudaGetSymbolAddress((void**)&wq, g_wqkv);
    cudaGetSymbolAddress((void**)&wo, g_wout);
    cudaGetSymbolAddress((void**)&xs, g_act);
    cudaGetSymbolAddress((void**)&qg, g_q);
    cudaGetSymbolAddress((void**)&kg, g_k);
    cudaGetSymbolAddress((void**)&vg, g_v);
    cudaGetSymbolAddress((void**)&toklist, g_toklist);
    cudaGetSymbolAddress((void**)&ncomp,   g_ncomp);

    cudaFuncSetAttribute(gemm_proj_kernel,
                         cudaFuncAttributeMaxDynamicSharedMemorySize, GEMM_SMEM);
    cudaFuncSetAttribute(gemm_tc_kernel,
                         cudaFuncAttributeMaxDynamicSharedMemorySize, GEMM_SMEM);
    cudaFuncSetAttribute(attn_tc_kernel,
                         cudaFuncAttributeMaxDynamicSharedMemorySize, ATTN_SMEM);

    // 0) Fused fp16 conversion + mask scan
    conv_all_kernel<<<8196, 256>>>(W_qkv, W_out, x, mask,
                                   wq, wo, xs, toklist, ncomp);

    // 1) Fused Q + K/V projection
    gemm_proj_kernel<<<1536, 256, GEMM_SMEM>>>(
        xs, wq, b_qkv, qg, kg, vg, toklist, ncomp);

    // 2) Flash attention over compacted K/V (writes O fp16 -> xs)
    attn_tc_kernel<<<dim3(TT / 128, BB * HH), 256, ATTN_SMEM>>>(
        qg, kg, vg, ncomp, xs);

    // 3) Output projection
    gemm_tc_kernel<<<dim3(DD / 128, MTOT / 128), 256, GEMM_SMEM>>>(
        xs, wo, b_out, out);
}